// round 1
// baseline (speedup 1.0000x reference)
#include <cuda_runtime.h>

#define SEQ  4096
#define DMODEL 1024
#define NH   16
#define HDIM 64

// Scratch (allocation-free): head-major q/k/v for coalesced attention access,
// plus the attention output in [L][D] layout for the proj GEMM.
__device__ float g_q[(long)NH * SEQ * HDIM];
__device__ float g_k[(long)NH * SEQ * HDIM];
__device__ float g_v[(long)NH * SEQ * HDIM];
__device__ float g_attn[(long)SEQ * DMODEL];

// ---------------------------------------------------------------------------
// SGEMM: C[M,N] = A[M,K] @ B[K,N] + bias[N]
// BM=BN=128, BK=16, 256 threads, 8x8 microtile (split 4+4 columns/rows so
// fragment LDS.128 loads are conflict-free).
// MODE 1: A = X param, epilogue splits columns into g_q/g_k/g_v (head-major).
// MODE 0: A = g_attn, epilogue writes C (d_out) with bias.
// ---------------------------------------------------------------------------
template <int MODE>
__global__ __launch_bounds__(256, 2) void sgemm_kernel(
    const float* __restrict__ A, const float* __restrict__ B,
    const float* __restrict__ bias, float* __restrict__ C,
    int N, int K)
{
    __shared__ float As[16][132];   // transposed A tile [k][m]
    __shared__ float Bs[16][132];   // B tile [k][n]

    const int tid = threadIdx.x;
    const int tx = tid & 15;
    const int ty = tid >> 4;
    const int m0 = blockIdx.y * 128;
    const int n0 = blockIdx.x * 128;

    const float* Ap = MODE ? A : g_attn;

    float acc[8][8];
#pragma unroll
    for (int i = 0; i < 8; i++)
#pragma unroll
        for (int j = 0; j < 8; j++) acc[i][j] = 0.f;

    for (int k0 = 0; k0 < K; k0 += 16) {
        // A tile: 128 rows x 16 k. 512 float4 loads, store transposed.
#pragma unroll
        for (int rep = 0; rep < 2; rep++) {
            int id  = tid + rep * 256;       // 0..511
            int row = id >> 2;               // 0..127
            int k4  = (id & 3) << 2;         // 0,4,8,12
            float4 v = *(const float4*)(Ap + (long)(m0 + row) * K + k0 + k4);
            As[k4 + 0][row] = v.x;
            As[k4 + 1][row] = v.y;
            As[k4 + 2][row] = v.z;
            As[k4 + 3][row] = v.w;
        }
        // B tile: 16 k x 128 n.
#pragma unroll
        for (int rep = 0; rep < 2; rep++) {
            int id   = tid + rep * 256;
            int krow = id >> 5;              // 0..15
            int n4   = (id & 31) << 2;       // 0..124
            *(float4*)&Bs[krow][n4] =
                *(const float4*)(B + (long)(k0 + krow) * N + n0 + n4);
        }
        __syncthreads();

#pragma unroll
        for (int k = 0; k < 16; k++) {
            float a[8], b[8];
            *(float4*)&a[0] = *(const float4*)&As[k][ty * 4];
            *(float4*)&a[4] = *(const float4*)&As[k][64 + ty * 4];
            *(float4*)&b[0] = *(const float4*)&Bs[k][tx * 4];
            *(float4*)&b[4] = *(const float4*)&Bs[k][64 + tx * 4];
#pragma unroll
            for (int i = 0; i < 8; i++)
#pragma unroll
                for (int j = 0; j < 8; j++) acc[i][j] += a[i] * b[j];
        }
        __syncthreads();
    }

    // Epilogue
#pragma unroll
    for (int i = 0; i < 8; i++) {
        int rloc = ty * 4 + (i & 3) + ((i >> 2) << 6);   // 0..127
        int row  = m0 + rloc;
#pragma unroll
        for (int j = 0; j < 8; j++) {
            int cloc = tx * 4 + (j & 3) + ((j >> 2) << 6);
            int n    = n0 + cloc;
            float v  = acc[i][j] + bias[n];
            if (MODE) {
                int sect = n >> 10;          // 0=q 1=k 2=v
                int w    = n & 1023;
                int hh   = w >> 6;
                int dd   = w & 63;
                float* dst = (sect == 0) ? g_q : (sect == 1) ? g_k : g_v;
                dst[((long)hh * SEQ + row) * HDIM + dd] = v;
            } else {
                C[(long)row * N + n] = v;
            }
        }
    }
}

// ---------------------------------------------------------------------------
// Fused causal attention (flash style), fp32.
// Block: one head x 128 query rows. 256 threads (16x16), 8x4 microtiles.
// Tiles of 64 keys; online softmax; O accumulated in registers.
// smem (floats): Qt[64][132] St[64][132] Kt[64][68] Vs[64][68] m/l/alpha[128]
// ---------------------------------------------------------------------------
__global__ __launch_bounds__(256, 2) void attn_kernel()
{
    extern __shared__ float sm[];
    float* Qt   = sm;                    // [d][r]  64 x 132
    float* Kt   = Qt + 64 * 132;         // [d][c]  64 x 68
    float* Vs   = Kt + 64 * 68;          // [c][d]  64 x 68
    float* St   = Vs + 64 * 68;          // [c][r]  64 x 132 (scores then P)
    float* mrow = St + 64 * 132;         // [128]
    float* lrow = mrow + 128;            // [128]
    float* arow = lrow + 128;            // [128]

    const int tid = threadIdx.x;
    const int tx  = tid & 15;
    const int ty  = tid >> 4;
    const int iq  = 31 - (int)blockIdx.x;   // heavy blocks first
    const int h   = blockIdx.y;

    const long qbase = ((long)h * SEQ + (long)iq * 128) * HDIM;

    // Load Q tile transposed: Qt[d][r]
#pragma unroll
    for (int rep = 0; rep < 32; rep++) {
        int id = rep * 256 + tid;
        int r  = id >> 6;
        int d  = id & 63;
        Qt[d * 132 + r] = g_q[qbase + (long)r * HDIM + d];
    }
    if (tid < 128) { mrow[tid] = -1e30f; lrow[tid] = 0.f; }

    float o[8][4];
#pragma unroll
    for (int i = 0; i < 8; i++)
#pragma unroll
        for (int j = 0; j < 4; j++) o[i][j] = 0.f;

    const int jmax = 2 * iq + 1;
    for (int j = 0; j <= jmax; j++) {
        __syncthreads();   // covers Q-load/init (iter 0) and prev-iter PV reads

        const long kb = ((long)h * SEQ + (long)j * 64) * HDIM;
        // K tile transposed: Kt[d][c]
#pragma unroll
        for (int rep = 0; rep < 16; rep++) {
            int id = rep * 256 + tid;
            int c  = id >> 6;
            int d  = id & 63;
            Kt[d * 68 + c] = g_k[kb + (long)c * HDIM + d];
        }
        // V tile as-is: Vs[c][d] (vectorized)
#pragma unroll
        for (int rep = 0; rep < 4; rep++) {
            int id = rep * 256 + tid;
            int c  = id >> 4;
            int dg = (id & 15) << 2;
            *(float4*)&Vs[c * 68 + dg] = *(const float4*)&g_v[kb + (long)c * HDIM + dg];
        }
        __syncthreads();

        // S = Q @ K^T  (128 x 64, inner dim 64)
        float s[8][4];
#pragma unroll
        for (int i = 0; i < 8; i++)
#pragma unroll
            for (int jj = 0; jj < 4; jj++) s[i][jj] = 0.f;

#pragma unroll 8
        for (int d = 0; d < 64; d++) {
            float a[8], b[4];
            *(float4*)&a[0] = *(const float4*)&Qt[d * 132 + ty * 8];
            *(float4*)&a[4] = *(const float4*)&Qt[d * 132 + ty * 8 + 4];
            *(float4*)&b[0] = *(const float4*)&Kt[d * 68 + tx * 4];
#pragma unroll
            for (int i = 0; i < 8; i++)
#pragma unroll
                for (int jj = 0; jj < 4; jj++) s[i][jj] += a[i] * b[jj];
        }

        // scale + causal mask, store transposed St[c][r]
        const bool need_mask = (j >= 2 * iq);
#pragma unroll
        for (int i = 0; i < 8; i++) {
            int r = ty * 8 + i;
#pragma unroll
            for (int jj = 0; jj < 4; jj++) {
                int c = tx * 4 + jj;
                float v = s[i][jj] * 0.125f;
                if (need_mask && (j * 64 + c > iq * 128 + r)) v = -1e30f;
                St[c * 132 + r] = v;
            }
        }
        __syncthreads();

        // Online softmax: one thread per query row (threads 0..127)
        if (tid < 128) {
            float mold = mrow[tid];
            float mn   = mold;
#pragma unroll 8
            for (int c = 0; c < 64; c++) mn = fmaxf(mn, St[c * 132 + tid]);
            float alpha = __expf(mold - mn);
            float sum = 0.f;
#pragma unroll 8
            for (int c = 0; c < 64; c++) {
                float p = __expf(St[c * 132 + tid] - mn);
                St[c * 132 + tid] = p;
                sum += p;
            }
            lrow[tid] = lrow[tid] * alpha + sum;
            mrow[tid] = mn;
            arow[tid] = alpha;
        }
        __syncthreads();

        // O = O*alpha + P @ V
#pragma unroll
        for (int i = 0; i < 8; i++) {
            float al = arow[ty * 8 + i];
#pragma unroll
            for (int jj = 0; jj < 4; jj++) o[i][jj] *= al;
        }
#pragma unroll 8
        for (int c = 0; c < 64; c++) {
            float a[8], b[4];
            *(float4*)&a[0] = *(const float4*)&St[c * 132 + ty * 8];
            *(float4*)&a[4] = *(const float4*)&St[c * 132 + ty * 8 + 4];
            *(float4*)&b[0] = *(const float4*)&Vs[c * 68 + tx * 4];
#pragma unroll
            for (int i = 0; i < 8; i++)
#pragma unroll
                for (int jj = 0; jj < 4; jj++) o[i][jj] += a[i] * b[jj];
        }
    }

    // Write normalized output: g_attn[L][D] layout (row, h*64 + d)
#pragma unroll
    for (int i = 0; i < 8; i++) {
        int r = ty * 8 + i;
        float inv = 1.0f / lrow[r];
        long base = ((long)(iq * 128 + r)) * DMODEL + h * HDIM + tx * 4;
#pragma unroll
        for (int jj = 0; jj < 4; jj++)
            g_attn[base + jj] = o[i][jj] * inv;
    }
}

// ---------------------------------------------------------------------------
extern "C" void kernel_launch(void* const* d_in, const int* in_sizes, int n_in,
                              void* d_out, int out_size)
{
    const float* X     = (const float*)d_in[0];
    const float* Wqkv  = (const float*)d_in[1];
    const float* bqkv  = (const float*)d_in[2];
    const float* Wproj = (const float*)d_in[3];
    const float* bproj = (const float*)d_in[4];
    float* out = (float*)d_out;

    const int ATTN_SMEM = (64 * 132 + 64 * 68 + 64 * 68 + 64 * 132 + 3 * 128) * 4; // 103936 B
    cudaFuncSetAttribute(attn_kernel, cudaFuncAttributeMaxDynamicSharedMemorySize, ATTN_SMEM);

    dim3 blk(256);

    // 1) QKV GEMM with split epilogue: [4096,1024] @ [1024,3072]
    sgemm_kernel<1><<<dim3(24, 32), blk>>>(X, Wqkv, bqkv, nullptr, 3 * DMODEL, DMODEL);

    // 2) Fused causal attention: grid (32 q-blocks, 16 heads)
    attn_kernel<<<dim3(32, NH), blk, ATTN_SMEM>>>();

    // 3) Proj GEMM: [4096,1024] @ [1024,1024] -> d_out
    sgemm_kernel<0><<<dim3(8, 32), blk>>>(nullptr, Wproj, bproj, out, DMODEL, DMODEL);
}

// round 4
// speedup vs baseline: 1.2860x; 1.2860x over previous
#include <cuda_runtime.h>
#include <cuda_bf16.h>
#include <cstdint>

#define SEQ  4096
#define DMODEL 1024
#define NH   16
#define HDIM 64

// fp32 scratch
__device__ float g_q[(long)NH * SEQ * HDIM];
__device__ float g_k[(long)NH * SEQ * HDIM];
__device__ float g_v[(long)NH * SEQ * HDIM];
__device__ float g_attn[(long)SEQ * DMODEL];

// bf16 split scratch (A reused for both GEMMs; B per weight, transposed to [N][K])
__device__ __align__(16) __nv_bfloat16 g_ahi[(long)SEQ * DMODEL];
__device__ __align__(16) __nv_bfloat16 g_alo[(long)SEQ * DMODEL];
__device__ __align__(16) __nv_bfloat16 g_bhi1[(long)3 * DMODEL * DMODEL];
__device__ __align__(16) __nv_bfloat16 g_blo1[(long)3 * DMODEL * DMODEL];
__device__ __align__(16) __nv_bfloat16 g_bhi2[(long)DMODEL * DMODEL];
__device__ __align__(16) __nv_bfloat16 g_blo2[(long)DMODEL * DMODEL];

// ---------------------------------------------------------------------------
// Base-PTX helpers (NO tcgen05 — harness compiles for compute_103 family-common)
// ---------------------------------------------------------------------------
__device__ __forceinline__ uint32_t smem_u32(const void* p) {
    uint32_t a;
    asm("{ .reg .u64 t; cvta.to.shared.u64 t, %1; cvt.u32.u64 %0, t; }" : "=r"(a) : "l"(p));
    return a;
}
#define CP16(dst, src) \
    asm volatile("cp.async.cg.shared.global [%0], [%1], 16;" :: "r"(dst), "l"(src))
#define CP_COMMIT() asm volatile("cp.async.commit_group;" ::: "memory")
#define CP_WAIT1()  asm volatile("cp.async.wait_group 1;" ::: "memory")
#define CP_WAIT0()  asm volatile("cp.async.wait_group 0;" ::: "memory")

#define LDSM4(r0, r1, r2, r3, addr) \
    asm volatile("ldmatrix.sync.aligned.m8n8.x4.shared.b16 {%0,%1,%2,%3}, [%4];" \
                 : "=r"(r0), "=r"(r1), "=r"(r2), "=r"(r3) : "r"(addr))

#define MMA16816(c, a, b0, b1) \
    asm volatile("mma.sync.aligned.m16n8k16.row.col.f32.bf16.bf16.f32 " \
                 "{%0,%1,%2,%3}, {%4,%5,%6,%7}, {%8,%9}, {%0,%1,%2,%3};" \
                 : "+f"((c)[0]), "+f"((c)[1]), "+f"((c)[2]), "+f"((c)[3]) \
                 : "r"((a)[0]), "r"((a)[1]), "r"((a)[2]), "r"((a)[3]), \
                   "r"(b0), "r"(b1))

// ---------------------------------------------------------------------------
// Conversion kernels.  SRC=0: read A arg (harness ptr). SRC=1: read g_attn.
// Outputs are always the device-global g_ahi/g_alo (referenced in device code).
// ---------------------------------------------------------------------------
template <int SRC>
__global__ void convA_kernel(const float* __restrict__ A) {
    const float* src = (SRC == 0) ? A : g_attn;
    int i = blockIdx.x * 256 + threadIdx.x;        // float4 index
    float4 v = ((const float4*)src)[i];
    __nv_bfloat16 h0 = __float2bfloat16(v.x), h1 = __float2bfloat16(v.y);
    __nv_bfloat16 h2 = __float2bfloat16(v.z), h3 = __float2bfloat16(v.w);
    __nv_bfloat16 l0 = __float2bfloat16(v.x - __bfloat162float(h0));
    __nv_bfloat16 l1 = __float2bfloat16(v.y - __bfloat162float(h1));
    __nv_bfloat16 l2 = __float2bfloat16(v.z - __bfloat162float(h2));
    __nv_bfloat16 l3 = __float2bfloat16(v.w - __bfloat162float(h3));
    __nv_bfloat162* H = (__nv_bfloat162*)g_ahi;
    __nv_bfloat162* L = (__nv_bfloat162*)g_alo;
    __nv_bfloat162 a; a.x = h0; a.y = h1; H[2*i]   = a;
    __nv_bfloat162 b; b.x = h2; b.y = h3; H[2*i+1] = b;
    __nv_bfloat162 c; c.x = l0; c.y = l1; L[2*i]   = c;
    __nv_bfloat162 d; d.x = l2; d.y = l3; L[2*i+1] = d;
}

// W[K][N] fp32 -> g_bhi/g_blo[N][K] bf16 (transposed split). WSEL: 1=qkv 2=proj
template <int WSEL>
__global__ void transW_kernel(const float* __restrict__ W, int K, int N) {
    __nv_bfloat16* Th = (WSEL == 1) ? g_bhi1 : g_bhi2;
    __nv_bfloat16* Tl = (WSEL == 1) ? g_blo1 : g_blo2;
    __shared__ float t[32][33];
    int n0 = blockIdx.x * 32, k0 = blockIdx.y * 32;
    int tx = threadIdx.x, ty = threadIdx.y;   // 32 x 8
#pragma unroll
    for (int r = 0; r < 4; r++)
        t[ty + 8*r][tx] = W[(size_t)(k0 + ty + 8*r) * N + n0 + tx];
    __syncthreads();
#pragma unroll
    for (int r = 0; r < 4; r++) {
        int nl = ty + 8*r, kl = tx;
        float v = t[kl][nl];
        __nv_bfloat16 h = __float2bfloat16(v);
        Th[(size_t)(n0 + nl) * K + k0 + kl] = h;
        Tl[(size_t)(n0 + nl) * K + k0 + kl] = __float2bfloat16(v - __bfloat162float(h));
    }
}

// ---------------------------------------------------------------------------
// mma.sync bf16x3 GEMM: C[M,N] = A[M,K] @ B[K,N] + bias.
// CTA tile 128x128, K-chunk 64; 8 warps = 2(M) x 4(N), warp tile 64x32.
// A = g_ahi/g_alo [M][K]; B = g_bhi*/g_blo* [N][K] (transposed), all referenced
// as device globals (NEVER passed from host). SW128-swizzled smem, cp.async
// 2-stage pipeline. MODE 1: scatter into g_q/g_k/g_v. MODE 0: C + bias.
// ---------------------------------------------------------------------------
template <int MODE>
__global__ __launch_bounds__(256, 1) void tc_gemm(
    const float* __restrict__ bias, float* __restrict__ C, int N, int K)
{
    const __nv_bfloat16* __restrict__ Ahi = g_ahi;
    const __nv_bfloat16* __restrict__ Alo = g_alo;
    const __nv_bfloat16* __restrict__ Bhi = (MODE == 1) ? g_bhi1 : g_bhi2;
    const __nv_bfloat16* __restrict__ Blo = (MODE == 1) ? g_blo1 : g_blo2;

    extern __shared__ char smem[];                  // 2 stages x 4 arrays x 16KB
    const uint32_t sb = smem_u32(smem);
    const int tid  = threadIdx.x;
    const int lane = tid & 31;
    const int wid  = tid >> 5;
    const int wm   = wid >> 2;            // 0..1
    const int wn   = wid & 3;             // 0..3
    const int n0 = blockIdx.x * 128, m0 = blockIdx.y * 128;

    float acc[4][4][4];
#pragma unroll
    for (int mt = 0; mt < 4; mt++)
#pragma unroll
        for (int nt = 0; nt < 4; nt++)
#pragma unroll
            for (int r = 0; r < 4; r++) acc[mt][nt][r] = 0.f;

    // ---- loader ----
    auto load_stage = [&](int stg, int ck) {
        const uint32_t st = sb + stg * 65536;
        const int k0 = ck * 64;
#pragma unroll
        for (int arr = 0; arr < 4; arr++) {
            const __nv_bfloat16* src = (arr == 0) ? Ahi : (arr == 1) ? Alo
                                     : (arr == 2) ? Bhi : Blo;
            const int base0 = (arr < 2) ? m0 : n0;
#pragma unroll
            for (int it = 0; it < 4; it++) {
                int id  = it * 256 + tid;
                int row = id >> 3, kc = id & 7;
                const void* g = src + (size_t)(base0 + row) * K + k0 + kc * 8;
                uint32_t soff = (uint32_t)(row * 128 + ((kc * 16) ^ ((row & 7) << 4)));
                CP16(st + arr * 16384 + soff, g);
            }
        }
    };

    const int NC = K / 64;                 // 16
    load_stage(0, 0);
    CP_COMMIT();

    // ldmatrix per-thread address components
    const int r_lane = lane & 15;
    const int c_lane = (lane >> 4) << 4;   // 0 or 16 bytes
    const uint32_t xorterm = (uint32_t)((r_lane & 7) << 4);

    for (int c = 0; c < NC; c++) {
        if (c + 1 < NC) { load_stage((c + 1) & 1, c + 1); CP_COMMIT(); CP_WAIT1(); }
        else            { CP_WAIT0(); }
        __syncthreads();

        const uint32_t st  = sb + (c & 1) * 65536;
        const uint32_t aAh = st +      0 + (uint32_t)((wm * 64 + r_lane) * 128);
        const uint32_t aAl = aAh + 16384;
        const uint32_t aBh = st + 32768 + (uint32_t)((wn * 32 + r_lane) * 128);
        const uint32_t aBl = aBh + 16384;

#pragma unroll
        for (int ks = 0; ks < 4; ks++) {
            const uint32_t cv = ((uint32_t)(ks * 32 + c_lane)) ^ xorterm;
            uint32_t ah[4][4], al[4][4], bh[2][4], bl[2][4];
#pragma unroll
            for (int mt = 0; mt < 4; mt++) {
                LDSM4(ah[mt][0], ah[mt][1], ah[mt][2], ah[mt][3], aAh + mt * 2048 + cv);
                LDSM4(al[mt][0], al[mt][1], al[mt][2], al[mt][3], aAl + mt * 2048 + cv);
            }
#pragma unroll
            for (int bn = 0; bn < 2; bn++) {
                LDSM4(bh[bn][0], bh[bn][1], bh[bn][2], bh[bn][3], aBh + bn * 2048 + cv);
                LDSM4(bl[bn][0], bl[bn][1], bl[bn][2], bl[bn][3], aBl + bn * 2048 + cv);
            }
            // pass 1: Ah*Bh, pass 2: Al*Bh, pass 3: Ah*Bl
#pragma unroll
            for (int mt = 0; mt < 4; mt++)
#pragma unroll
                for (int nt = 0; nt < 4; nt++) {
                    int bn = nt >> 1, sub = nt & 1;
                    MMA16816(acc[mt][nt], ah[mt], bh[bn][sub], bh[bn][sub + 2]);
                }
#pragma unroll
            for (int mt = 0; mt < 4; mt++)
#pragma unroll
                for (int nt = 0; nt < 4; nt++) {
                    int bn = nt >> 1, sub = nt & 1;
                    MMA16816(acc[mt][nt], al[mt], bh[bn][sub], bh[bn][sub + 2]);
                }
#pragma unroll
            for (int mt = 0; mt < 4; mt++)
#pragma unroll
                for (int nt = 0; nt < 4; nt++) {
                    int bn = nt >> 1, sub = nt & 1;
                    MMA16816(acc[mt][nt], ah[mt], bl[bn][sub], bl[bn][sub + 2]);
                }
        }
        __syncthreads();
    }

    // ---- epilogue: registers -> global ----
    const int rq = lane >> 2;              // 0..7 row in 8-row group
    const int cq = (lane & 3) * 2;         // col pair base
#pragma unroll
    for (int mt = 0; mt < 4; mt++) {
#pragma unroll
        for (int nt = 0; nt < 4; nt++) {
            int gcol = n0 + wn * 32 + nt * 8 + cq;
            float b0 = bias[gcol], b1 = bias[gcol + 1];
#pragma unroll
            for (int half = 0; half < 2; half++) {
                int grow = m0 + wm * 64 + mt * 16 + rq + half * 8;
                float2 v;
                v.x = acc[mt][nt][half * 2 + 0] + b0;
                v.y = acc[mt][nt][half * 2 + 1] + b1;
                if (MODE == 1) {
                    int sect = gcol >> 10, w = gcol & 1023;
                    int hh = w >> 6, dd = w & 63;
                    float* dst = (sect == 0) ? g_q : (sect == 1) ? g_k : g_v;
                    *(float2*)&dst[((size_t)hh * SEQ + grow) * HDIM + dd] = v;
                } else {
                    *(float2*)&C[(size_t)grow * N + gcol] = v;
                }
            }
        }
    }
}

// ---------------------------------------------------------------------------
// Fused causal attention (flash style), fp32 — unchanged (passes at ~1.1ms).
// ---------------------------------------------------------------------------
__global__ __launch_bounds__(256, 2) void attn_kernel()
{
    extern __shared__ float sm[];
    float* Qt   = sm;
    float* Kt   = Qt + 64 * 132;
    float* Vs   = Kt + 64 * 68;
    float* St   = Vs + 64 * 68;
    float* mrow = St + 64 * 132;
    float* lrow = mrow + 128;
    float* arow = lrow + 128;

    const int tid = threadIdx.x;
    const int tx  = tid & 15;
    const int ty  = tid >> 4;
    const int iq  = 31 - (int)blockIdx.x;
    const int h   = blockIdx.y;

    const long qbase = ((long)h * SEQ + (long)iq * 128) * HDIM;

#pragma unroll
    for (int rep = 0; rep < 32; rep++) {
        int id = rep * 256 + tid;
        int r  = id >> 6;
        int d  = id & 63;
        Qt[d * 132 + r] = g_q[qbase + (long)r * HDIM + d];
    }
    if (tid < 128) { mrow[tid] = -1e30f; lrow[tid] = 0.f; }

    float o[8][4];
#pragma unroll
    for (int i = 0; i < 8; i++)
#pragma unroll
        for (int j = 0; j < 4; j++) o[i][j] = 0.f;

    const int jmax = 2 * iq + 1;
    for (int j = 0; j <= jmax; j++) {
        __syncthreads();

        const long kb = ((long)h * SEQ + (long)j * 64) * HDIM;
#pragma unroll
        for (int rep = 0; rep < 16; rep++) {
            int id = rep * 256 + tid;
            int c  = id >> 6;
            int d  = id & 63;
            Kt[d * 68 + c] = g_k[kb + (long)c * HDIM + d];
        }
#pragma unroll
        for (int rep = 0; rep < 4; rep++) {
            int id = rep * 256 + tid;
            int c  = id >> 4;
            int dg = (id & 15) << 2;
            *(float4*)&Vs[c * 68 + dg] = *(const float4*)&g_v[kb + (long)c * HDIM + dg];
        }
        __syncthreads();

        float s[8][4];
#pragma unroll
        for (int i = 0; i < 8; i++)
#pragma unroll
            for (int jj = 0; jj < 4; jj++) s[i][jj] = 0.f;

#pragma unroll 8
        for (int d = 0; d < 64; d++) {
            float a[8], b[4];
            *(float4*)&a[0] = *(const float4*)&Qt[d * 132 + ty * 8];
            *(float4*)&a[4] = *(const float4*)&Qt[d * 132 + ty * 8 + 4];
            *(float4*)&b[0] = *(const float4*)&Kt[d * 68 + tx * 4];
#pragma unroll
            for (int i = 0; i < 8; i++)
#pragma unroll
                for (int jj = 0; jj < 4; jj++) s[i][jj] += a[i] * b[jj];
        }

        const bool need_mask = (j >= 2 * iq);
#pragma unroll
        for (int i = 0; i < 8; i++) {
            int r = ty * 8 + i;
#pragma unroll
            for (int jj = 0; jj < 4; jj++) {
                int c = tx * 4 + jj;
                float v = s[i][jj] * 0.125f;
                if (need_mask && (j * 64 + c > iq * 128 + r)) v = -1e30f;
                St[c * 132 + r] = v;
            }
        }
        __syncthreads();

        if (tid < 128) {
            float mold = mrow[tid];
            float mn   = mold;
#pragma unroll 8
            for (int c = 0; c < 64; c++) mn = fmaxf(mn, St[c * 132 + tid]);
            float alpha = __expf(mold - mn);
            float sum = 0.f;
#pragma unroll 8
            for (int c = 0; c < 64; c++) {
                float p = __expf(St[c * 132 + tid] - mn);
                St[c * 132 + tid] = p;
                sum += p;
            }
            lrow[tid] = lrow[tid] * alpha + sum;
            mrow[tid] = mn;
            arow[tid] = alpha;
        }
        __syncthreads();

#pragma unroll
        for (int i = 0; i < 8; i++) {
            float al = arow[ty * 8 + i];
#pragma unroll
            for (int jj = 0; jj < 4; jj++) o[i][jj] *= al;
        }
#pragma unroll 8
        for (int c = 0; c < 64; c++) {
            float a[8], b[4];
            *(float4*)&a[0] = *(const float4*)&St[c * 132 + ty * 8];
            *(float4*)&a[4] = *(const float4*)&St[c * 132 + ty * 8 + 4];
            *(float4*)&b[0] = *(const float4*)&Vs[c * 68 + tx * 4];
#pragma unroll
            for (int i = 0; i < 8; i++)
#pragma unroll
                for (int jj = 0; jj < 4; jj++) o[i][jj] += a[i] * b[jj];
        }
    }

#pragma unroll
    for (int i = 0; i < 8; i++) {
        int r = ty * 8 + i;
        float inv = 1.0f / lrow[r];
        long base = ((long)(iq * 128 + r)) * DMODEL + h * HDIM + tx * 4;
#pragma unroll
        for (int jj = 0; jj < 4; jj++)
            g_attn[base + jj] = o[i][jj] * inv;
    }
}

// ---------------------------------------------------------------------------
extern "C" void kernel_launch(void* const* d_in, const int* in_sizes, int n_in,
                              void* d_out, int out_size)
{
    const float* X     = (const float*)d_in[0];
    const float* Wqkv  = (const float*)d_in[1];
    const float* bqkv  = (const float*)d_in[2];
    const float* Wproj = (const float*)d_in[3];
    const float* bproj = (const float*)d_in[4];
    float* out = (float*)d_out;

    const int GEMM_SMEM = 2 * 4 * 16384;   // 131072 B
    const int ATTN_SMEM = (64 * 132 + 64 * 68 + 64 * 68 + 64 * 132 + 3 * 128) * 4;
    cudaFuncSetAttribute(tc_gemm<1>, cudaFuncAttributeMaxDynamicSharedMemorySize, GEMM_SMEM);
    cudaFuncSetAttribute(tc_gemm<0>, cudaFuncAttributeMaxDynamicSharedMemorySize, GEMM_SMEM);
    cudaFuncSetAttribute(attn_kernel, cudaFuncAttributeMaxDynamicSharedMemorySize, ATTN_SMEM);

    // 1) split-convert X, transpose-split Wqkv / Wproj (outputs are device
    //    globals referenced INSIDE the kernels — never passed from host)
    convA_kernel<0><<<SEQ * DMODEL / 4 / 256, 256>>>(X);
    transW_kernel<1><<<dim3(3 * DMODEL / 32, DMODEL / 32), dim3(32, 8)>>>(Wqkv, DMODEL, 3 * DMODEL);
    transW_kernel<2><<<dim3(DMODEL / 32, DMODEL / 32), dim3(32, 8)>>>(Wproj, DMODEL, DMODEL);

    // 2) QKV GEMM (mma.sync bf16x3) -> g_q/g_k/g_v
    tc_gemm<1><<<dim3(24, 32), 256, GEMM_SMEM>>>(bqkv, nullptr, 3 * DMODEL, DMODEL);

    // 3) attention -> g_attn
    attn_kernel<<<dim3(32, NH), 256, ATTN_SMEM>>>();

    // 4) split-convert attention output (reads g_attn internally), proj GEMM -> out
    convA_kernel<1><<<SEQ * DMODEL / 4 / 256, 256>>>(nullptr);
    tc_gemm<0><<<dim3(8, 32), 256, GEMM_SMEM>>>(bproj, out, DMODEL, DMODEL);
}

// round 5
// speedup vs baseline: 2.6865x; 2.0890x over previous
#include <cuda_runtime.h>
#include <cuda_bf16.h>
#include <cstdint>

#define SEQ  4096
#define DMODEL 1024
#define NH   16
#define HDIM 64

// bf16 split scratch. A (g_ahi/g_alo) is reused: X for QKV GEMM, then attention
// output for proj GEMM. q/k/v are bf16 hi/lo, head-major [h][seq][hd].
__device__ __align__(16) __nv_bfloat16 g_ahi[(long)SEQ * DMODEL];
__device__ __align__(16) __nv_bfloat16 g_alo[(long)SEQ * DMODEL];
__device__ __align__(16) __nv_bfloat16 g_bhi1[(long)3 * DMODEL * DMODEL];
__device__ __align__(16) __nv_bfloat16 g_blo1[(long)3 * DMODEL * DMODEL];
__device__ __align__(16) __nv_bfloat16 g_bhi2[(long)DMODEL * DMODEL];
__device__ __align__(16) __nv_bfloat16 g_blo2[(long)DMODEL * DMODEL];
__device__ __align__(16) __nv_bfloat16 g_qh[(long)NH * SEQ * HDIM];
__device__ __align__(16) __nv_bfloat16 g_ql[(long)NH * SEQ * HDIM];
__device__ __align__(16) __nv_bfloat16 g_kh[(long)NH * SEQ * HDIM];
__device__ __align__(16) __nv_bfloat16 g_kl[(long)NH * SEQ * HDIM];
__device__ __align__(16) __nv_bfloat16 g_vh[(long)NH * SEQ * HDIM];
__device__ __align__(16) __nv_bfloat16 g_vl[(long)NH * SEQ * HDIM];

// ---------------------------------------------------------------------------
// Base-PTX helpers (family-common; no tcgen05)
// ---------------------------------------------------------------------------
__device__ __forceinline__ uint32_t smem_u32(const void* p) {
    uint32_t a;
    asm("{ .reg .u64 t; cvta.to.shared.u64 t, %1; cvt.u32.u64 %0, t; }" : "=r"(a) : "l"(p));
    return a;
}
#define CP16(dst, src) \
    asm volatile("cp.async.cg.shared.global [%0], [%1], 16;" :: "r"(dst), "l"(src))
#define CP_COMMIT() asm volatile("cp.async.commit_group;" ::: "memory")
#define CP_WAIT1()  asm volatile("cp.async.wait_group 1;" ::: "memory")
#define CP_WAIT0()  asm volatile("cp.async.wait_group 0;" ::: "memory")

#define LDSM4(r0, r1, r2, r3, addr) \
    asm volatile("ldmatrix.sync.aligned.m8n8.x4.shared.b16 {%0,%1,%2,%3}, [%4];" \
                 : "=r"(r0), "=r"(r1), "=r"(r2), "=r"(r3) : "r"(addr))
#define LDSM4T(r0, r1, r2, r3, addr) \
    asm volatile("ldmatrix.sync.aligned.m8n8.x4.trans.shared.b16 {%0,%1,%2,%3}, [%4];" \
                 : "=r"(r0), "=r"(r1), "=r"(r2), "=r"(r3) : "r"(addr))

#define MMA16816(c, a, b0, b1) \
    asm volatile("mma.sync.aligned.m16n8k16.row.col.f32.bf16.bf16.f32 " \
                 "{%0,%1,%2,%3}, {%4,%5,%6,%7}, {%8,%9}, {%0,%1,%2,%3};" \
                 : "+f"((c)[0]), "+f"((c)[1]), "+f"((c)[2]), "+f"((c)[3]) \
                 : "r"((a)[0]), "r"((a)[1]), "r"((a)[2]), "r"((a)[3]), \
                   "r"(b0), "r"(b1))

__device__ __forceinline__ uint32_t bf2u(__nv_bfloat162 h) { return *(uint32_t*)&h; }

// ---------------------------------------------------------------------------
// Conversion kernels
// ---------------------------------------------------------------------------
__global__ void convA_kernel(const float* __restrict__ A) {
    int i = blockIdx.x * 256 + threadIdx.x;        // float4 index
    float4 v = ((const float4*)A)[i];
    __nv_bfloat162 h01 = __floats2bfloat162_rn(v.x, v.y);
    __nv_bfloat162 h23 = __floats2bfloat162_rn(v.z, v.w);
    __nv_bfloat162 l01 = __floats2bfloat162_rn(v.x - __bfloat162float(h01.x),
                                               v.y - __bfloat162float(h01.y));
    __nv_bfloat162 l23 = __floats2bfloat162_rn(v.z - __bfloat162float(h23.x),
                                               v.w - __bfloat162float(h23.y));
    __nv_bfloat162* H = (__nv_bfloat162*)g_ahi;
    __nv_bfloat162* L = (__nv_bfloat162*)g_alo;
    H[2*i] = h01; H[2*i+1] = h23;
    L[2*i] = l01; L[2*i+1] = l23;
}

// W[K][N] fp32 -> g_bhi/g_blo[N][K] bf16 (transposed split). WSEL: 1=qkv 2=proj
template <int WSEL>
__global__ void transW_kernel(const float* __restrict__ W, int K, int N) {
    __nv_bfloat16* Th = (WSEL == 1) ? g_bhi1 : g_bhi2;
    __nv_bfloat16* Tl = (WSEL == 1) ? g_blo1 : g_blo2;
    __shared__ float t[32][33];
    int n0 = blockIdx.x * 32, k0 = blockIdx.y * 32;
    int tx = threadIdx.x, ty = threadIdx.y;   // 32 x 8
#pragma unroll
    for (int r = 0; r < 4; r++)
        t[ty + 8*r][tx] = W[(size_t)(k0 + ty + 8*r) * N + n0 + tx];
    __syncthreads();
#pragma unroll
    for (int r = 0; r < 4; r++) {
        int nl = ty + 8*r, kl = tx;
        float v = t[kl][nl];
        __nv_bfloat16 h = __float2bfloat16(v);
        Th[(size_t)(n0 + nl) * K + k0 + kl] = h;
        Tl[(size_t)(n0 + nl) * K + k0 + kl] = __float2bfloat16(v - __bfloat162float(h));
    }
}

// ---------------------------------------------------------------------------
// mma.sync bf16x3 GEMM (as round 4, passing). MODE 1: epilogue writes bf16
// hi/lo q/k/v (q scaled by 0.125). MODE 0: fp32 C + bias.
// ---------------------------------------------------------------------------
template <int MODE>
__global__ __launch_bounds__(256, 1) void tc_gemm(
    const float* __restrict__ bias, float* __restrict__ C, int N, int K)
{
    const __nv_bfloat16* __restrict__ Ahi = g_ahi;
    const __nv_bfloat16* __restrict__ Alo = g_alo;
    const __nv_bfloat16* __restrict__ Bhi = (MODE == 1) ? g_bhi1 : g_bhi2;
    const __nv_bfloat16* __restrict__ Blo = (MODE == 1) ? g_blo1 : g_blo2;

    extern __shared__ char smem[];                  // 2 stages x 4 arrays x 16KB
    const uint32_t sb = smem_u32(smem);
    const int tid  = threadIdx.x;
    const int lane = tid & 31;
    const int wid  = tid >> 5;
    const int wm   = wid >> 2;
    const int wn   = wid & 3;
    const int n0 = blockIdx.x * 128, m0 = blockIdx.y * 128;

    float acc[4][4][4];
#pragma unroll
    for (int mt = 0; mt < 4; mt++)
#pragma unroll
        for (int nt = 0; nt < 4; nt++)
#pragma unroll
            for (int r = 0; r < 4; r++) acc[mt][nt][r] = 0.f;

    auto load_stage = [&](int stg, int ck) {
        const uint32_t st = sb + stg * 65536;
        const int k0 = ck * 64;
#pragma unroll
        for (int arr = 0; arr < 4; arr++) {
            const __nv_bfloat16* src = (arr == 0) ? Ahi : (arr == 1) ? Alo
                                     : (arr == 2) ? Bhi : Blo;
            const int base0 = (arr < 2) ? m0 : n0;
#pragma unroll
            for (int it = 0; it < 4; it++) {
                int id  = it * 256 + tid;
                int row = id >> 3, kc = id & 7;
                const void* g = src + (size_t)(base0 + row) * K + k0 + kc * 8;
                uint32_t soff = (uint32_t)(row * 128 + ((kc * 16) ^ ((row & 7) << 4)));
                CP16(st + arr * 16384 + soff, g);
            }
        }
    };

    const int NC = K / 64;
    load_stage(0, 0);
    CP_COMMIT();

    const int r_lane = lane & 15;
    const int c_lane = (lane >> 4) << 4;
    const uint32_t xorterm = (uint32_t)((r_lane & 7) << 4);

    for (int c = 0; c < NC; c++) {
        if (c + 1 < NC) { load_stage((c + 1) & 1, c + 1); CP_COMMIT(); CP_WAIT1(); }
        else            { CP_WAIT0(); }
        __syncthreads();

        const uint32_t st  = sb + (c & 1) * 65536;
        const uint32_t aAh = st +      0 + (uint32_t)((wm * 64 + r_lane) * 128);
        const uint32_t aAl = aAh + 16384;
        const uint32_t aBh = st + 32768 + (uint32_t)((wn * 32 + r_lane) * 128);
        const uint32_t aBl = aBh + 16384;

#pragma unroll
        for (int ks = 0; ks < 4; ks++) {
            const uint32_t cv = ((uint32_t)(ks * 32 + c_lane)) ^ xorterm;
            uint32_t ah[4][4], al[4][4], bh[2][4], bl[2][4];
#pragma unroll
            for (int mt = 0; mt < 4; mt++) {
                LDSM4(ah[mt][0], ah[mt][1], ah[mt][2], ah[mt][3], aAh + mt * 2048 + cv);
                LDSM4(al[mt][0], al[mt][1], al[mt][2], al[mt][3], aAl + mt * 2048 + cv);
            }
#pragma unroll
            for (int bn = 0; bn < 2; bn++) {
                LDSM4(bh[bn][0], bh[bn][1], bh[bn][2], bh[bn][3], aBh + bn * 2048 + cv);
                LDSM4(bl[bn][0], bl[bn][1], bl[bn][2], bl[bn][3], aBl + bn * 2048 + cv);
            }
#pragma unroll
            for (int mt = 0; mt < 4; mt++)
#pragma unroll
                for (int nt = 0; nt < 4; nt++) {
                    int bn = nt >> 1, sub = nt & 1;
                    MMA16816(acc[mt][nt], ah[mt], bh[bn][sub], bh[bn][sub + 2]);
                }
#pragma unroll
            for (int mt = 0; mt < 4; mt++)
#pragma unroll
                for (int nt = 0; nt < 4; nt++) {
                    int bn = nt >> 1, sub = nt & 1;
                    MMA16816(acc[mt][nt], al[mt], bh[bn][sub], bh[bn][sub + 2]);
                }
#pragma unroll
            for (int mt = 0; mt < 4; mt++)
#pragma unroll
                for (int nt = 0; nt < 4; nt++) {
                    int bn = nt >> 1, sub = nt & 1;
                    MMA16816(acc[mt][nt], ah[mt], bl[bn][sub], bl[bn][sub + 2]);
                }
        }
        __syncthreads();
    }

    const int rq = lane >> 2;
    const int cq = (lane & 3) * 2;
#pragma unroll
    for (int mt = 0; mt < 4; mt++) {
#pragma unroll
        for (int nt = 0; nt < 4; nt++) {
            int gcol = n0 + wn * 32 + nt * 8 + cq;
            float b0 = bias[gcol], b1 = bias[gcol + 1];
#pragma unroll
            for (int half = 0; half < 2; half++) {
                int grow = m0 + wm * 64 + mt * 16 + rq + half * 8;
                float vx = acc[mt][nt][half * 2 + 0] + b0;
                float vy = acc[mt][nt][half * 2 + 1] + b1;
                if (MODE == 1) {
                    int sect = gcol >> 10, w = gcol & 1023;
                    int hh = w >> 6, dd = w & 63;
                    if (sect == 0) { vx *= 0.125f; vy *= 0.125f; }  // fold softmax scale into q
                    __nv_bfloat162 H = __floats2bfloat162_rn(vx, vy);
                    __nv_bfloat162 L = __floats2bfloat162_rn(vx - __bfloat162float(H.x),
                                                             vy - __bfloat162float(H.y));
                    __nv_bfloat16* dh = (sect == 0) ? g_qh : (sect == 1) ? g_kh : g_vh;
                    __nv_bfloat16* dl = (sect == 0) ? g_ql : (sect == 1) ? g_kl : g_vl;
                    size_t idx = ((size_t)hh * SEQ + grow) * HDIM + dd;
                    *(__nv_bfloat162*)&dh[idx] = H;
                    *(__nv_bfloat162*)&dl[idx] = L;
                } else {
                    float2 v; v.x = vx; v.y = vy;
                    *(float2*)&C[(size_t)grow * N + gcol] = v;
                }
            }
        }
    }
}

// ---------------------------------------------------------------------------
// FlashAttention-2 style causal attention on mma.sync, bf16x3 precision.
// 1 CTA = 1 head x 128 queries. 8 warps x 16 rows (M-only partition).
// Key tiles of 64; K/V double-buffered via cp.async; Q fragments in registers;
// P reinterpreted from S accumulators (no smem round-trip). Writes bf16 hi/lo
// output directly into g_ahi/g_alo (proj GEMM input).
// smem: Q 32KB + 2 stages x (Kh,Kl,Vh,Vl = 32KB) = 96KB.
// ---------------------------------------------------------------------------
__global__ __launch_bounds__(256, 1) void attn_mma_kernel()
{
    extern __shared__ char smem[];
    const uint32_t sb = smem_u32(smem);
    const int tid = threadIdx.x, lane = tid & 31, wid = tid >> 5;
    const int iq = 31 - (int)blockIdx.x;     // heavy blocks first
    const int h  = blockIdx.y;
    const int jmax = 2 * iq + 1;

    const uint32_t Qs = sb;                  // Qh @0, Ql @16K

    auto load_kv = [&](int stg, int j) {
        const uint32_t st = sb + 32768 + (uint32_t)stg * 32768;
#pragma unroll
        for (int a = 0; a < 4; a++) {
            const __nv_bfloat16* src = (a == 0) ? g_kh : (a == 1) ? g_kl
                                     : (a == 2) ? g_vh : g_vl;
#pragma unroll
            for (int it = 0; it < 2; it++) {
                int id = it * 256 + tid;
                int row = id >> 3, kc = id & 7;
                uint32_t soff = (uint32_t)(row * 128 + ((kc * 16) ^ ((row & 7) << 4)));
                CP16(st + a * 8192 + soff,
                     src + ((size_t)h * SEQ + j * 64 + row) * HDIM + kc * 8);
            }
        }
    };

    // prologue: Q (hi+lo) + first KV stage in one group
    {
#pragma unroll
        for (int a = 0; a < 2; a++) {
            const __nv_bfloat16* src = a ? g_ql : g_qh;
#pragma unroll
            for (int it = 0; it < 4; it++) {
                int id = it * 256 + tid;
                int row = id >> 3, kc = id & 7;
                uint32_t soff = (uint32_t)(row * 128 + ((kc * 16) ^ ((row & 7) << 4)));
                CP16(Qs + a * 16384 + soff,
                     src + ((size_t)h * SEQ + iq * 128 + row) * HDIM + kc * 8);
            }
        }
        load_kv(0, 0);
        CP_COMMIT();
    }

    float o[8][4];
#pragma unroll
    for (int nt = 0; nt < 8; nt++)
#pragma unroll
        for (int r = 0; r < 4; r++) o[nt][r] = 0.f;
    float m0 = -1e30f, m1 = -1e30f, l0 = 0.f, l1 = 0.f;
    uint32_t qhf[4][4], qlf[4][4];

    const uint32_t xorterm = (uint32_t)((lane & 7) << 4);
    const uint32_t c_lane  = (uint32_t)((lane >> 4) << 4);
    const int r0g_base = iq * 128 + wid * 16 + (lane >> 2);

    for (int j = 0; j <= jmax; j++) {
        if (j < jmax) { load_kv((j + 1) & 1, j + 1); CP_COMMIT(); CP_WAIT1(); }
        else          { CP_WAIT0(); }
        __syncthreads();

        if (j == 0) {
            // Q fragments (loop-invariant)
            const uint32_t qrow = Qs + (uint32_t)((wid * 16 + (lane & 15)) * 128);
#pragma unroll
            for (int ks = 0; ks < 4; ks++) {
                uint32_t cv = ((uint32_t)(ks * 32) + c_lane) ^ xorterm;
                LDSM4(qhf[ks][0], qhf[ks][1], qhf[ks][2], qhf[ks][3], qrow + cv);
                LDSM4(qlf[ks][0], qlf[ks][1], qlf[ks][2], qlf[ks][3], qrow + 16384 + cv);
            }
        }

        const uint32_t st  = sb + 32768 + (uint32_t)(j & 1) * 32768;
        const uint32_t Ksh = st, Ksl = st + 8192, Vsh = st + 16384, Vsl = st + 24576;

        // ---- S = Q @ K^T (scale pre-folded into q), bf16x3 ----
        float s[8][4];
#pragma unroll
        for (int nt = 0; nt < 8; nt++)
#pragma unroll
            for (int r = 0; r < 4; r++) s[nt][r] = 0.f;

#pragma unroll
        for (int ks = 0; ks < 4; ks++) {
            uint32_t cv = ((uint32_t)(ks * 32) + c_lane) ^ xorterm;
#pragma unroll
            for (int bn = 0; bn < 4; bn++) {
                uint32_t rowoff = (uint32_t)((bn * 16 + (lane & 15)) * 128);
                uint32_t kh[4], kl[4];
                LDSM4(kh[0], kh[1], kh[2], kh[3], Ksh + rowoff + cv);
                LDSM4(kl[0], kl[1], kl[2], kl[3], Ksl + rowoff + cv);
#pragma unroll
                for (int sub = 0; sub < 2; sub++) {
                    int nt = bn * 2 + sub;
                    MMA16816(s[nt], qhf[ks], kh[sub], kh[sub + 2]);
                    MMA16816(s[nt], qlf[ks], kh[sub], kh[sub + 2]);
                    MMA16816(s[nt], qhf[ks], kl[sub], kl[sub + 2]);
                }
            }
        }

        // ---- causal mask (only last two tiles can clip) ----
        if (j >= 2 * iq) {
            int cbase = j * 64 + (lane & 3) * 2;
#pragma unroll
            for (int nt = 0; nt < 8; nt++) {
                int c0 = cbase + nt * 8, c1 = c0 + 1;
                if (c0 > r0g_base)     s[nt][0] = -1e30f;
                if (c1 > r0g_base)     s[nt][1] = -1e30f;
                if (c0 > r0g_base + 8) s[nt][2] = -1e30f;
                if (c1 > r0g_base + 8) s[nt][3] = -1e30f;
            }
        }

        // ---- online softmax (per-warp rows; quad shfl reductions) ----
        float mx0 = -1e30f, mx1 = -1e30f;
#pragma unroll
        for (int nt = 0; nt < 8; nt++) {
            mx0 = fmaxf(mx0, fmaxf(s[nt][0], s[nt][1]));
            mx1 = fmaxf(mx1, fmaxf(s[nt][2], s[nt][3]));
        }
        mx0 = fmaxf(mx0, __shfl_xor_sync(0xFFFFFFFFu, mx0, 1));
        mx0 = fmaxf(mx0, __shfl_xor_sync(0xFFFFFFFFu, mx0, 2));
        mx1 = fmaxf(mx1, __shfl_xor_sync(0xFFFFFFFFu, mx1, 1));
        mx1 = fmaxf(mx1, __shfl_xor_sync(0xFFFFFFFFu, mx1, 2));
        float mn0 = fmaxf(m0, mx0), mn1 = fmaxf(m1, mx1);
        float al0 = __expf(m0 - mn0), al1 = __expf(m1 - mn1);
        m0 = mn0; m1 = mn1;

        float sum0 = 0.f, sum1 = 0.f;
#pragma unroll
        for (int nt = 0; nt < 8; nt++) {
            s[nt][0] = __expf(s[nt][0] - mn0);
            s[nt][1] = __expf(s[nt][1] - mn0);
            s[nt][2] = __expf(s[nt][2] - mn1);
            s[nt][3] = __expf(s[nt][3] - mn1);
            sum0 += s[nt][0] + s[nt][1];
            sum1 += s[nt][2] + s[nt][3];
        }
        sum0 += __shfl_xor_sync(0xFFFFFFFFu, sum0, 1);
        sum0 += __shfl_xor_sync(0xFFFFFFFFu, sum0, 2);
        sum1 += __shfl_xor_sync(0xFFFFFFFFu, sum1, 1);
        sum1 += __shfl_xor_sync(0xFFFFFFFFu, sum1, 2);
        l0 = l0 * al0 + sum0;
        l1 = l1 * al1 + sum1;

#pragma unroll
        for (int nt = 0; nt < 8; nt++) {
            o[nt][0] *= al0; o[nt][1] *= al0;
            o[nt][2] *= al1; o[nt][3] *= al1;
        }

        // ---- O += P @ V, bf16x3 (P from registers, V via ldmatrix.trans) ----
#pragma unroll
        for (int t = 0; t < 4; t++) {
            uint32_t ap[4], apl[4];
#pragma unroll
            for (int u = 0; u < 4; u++) {
                int nt = t * 2 + (u >> 1);
                int base = (u & 1) * 2;
                float p0 = s[nt][base], p1 = s[nt][base + 1];
                __nv_bfloat162 H = __floats2bfloat162_rn(p0, p1);
                __nv_bfloat162 L = __floats2bfloat162_rn(p0 - __bfloat162float(H.x),
                                                         p1 - __bfloat162float(H.y));
                ap[u]  = bf2u(H);
                apl[u] = bf2u(L);
            }
            uint32_t rowoff = (uint32_t)((t * 16 + (lane & 15)) * 128);
#pragma unroll
            for (int g = 0; g < 4; g++) {
                uint32_t cvv = ((uint32_t)(g * 32) + c_lane) ^ xorterm;
                uint32_t vh[4], vl[4];
                LDSM4T(vh[0], vh[1], vh[2], vh[3], Vsh + rowoff + cvv);
                LDSM4T(vl[0], vl[1], vl[2], vl[3], Vsl + rowoff + cvv);
                MMA16816(o[g * 2],     ap,  vh[0], vh[1]);
                MMA16816(o[g * 2 + 1], ap,  vh[2], vh[3]);
                MMA16816(o[g * 2],     apl, vh[0], vh[1]);
                MMA16816(o[g * 2 + 1], apl, vh[2], vh[3]);
                MMA16816(o[g * 2],     ap,  vl[0], vl[1]);
                MMA16816(o[g * 2 + 1], ap,  vl[2], vl[3]);
            }
        }
        __syncthreads();   // reads of this stage done before next prefetch overwrites
    }

    // ---- normalize + write bf16 hi/lo directly into proj-GEMM input ----
    float inv0 = 1.f / l0, inv1 = 1.f / l1;
    int colb = h * 64 + (lane & 3) * 2;
#pragma unroll
    for (int nt = 0; nt < 8; nt++) {
        int col = colb + nt * 8;
        float x0 = o[nt][0] * inv0, x1 = o[nt][1] * inv0;
        float y0 = o[nt][2] * inv1, y1 = o[nt][3] * inv1;
        __nv_bfloat162 H0 = __floats2bfloat162_rn(x0, x1);
        __nv_bfloat162 L0 = __floats2bfloat162_rn(x0 - __bfloat162float(H0.x),
                                                  x1 - __bfloat162float(H0.y));
        __nv_bfloat162 H1 = __floats2bfloat162_rn(y0, y1);
        __nv_bfloat162 L1 = __floats2bfloat162_rn(y0 - __bfloat162float(H1.x),
                                                  y1 - __bfloat162float(H1.y));
        size_t i0 = (size_t)r0g_base * DMODEL + col;
        size_t i1 = (size_t)(r0g_base + 8) * DMODEL + col;
        *(__nv_bfloat162*)&g_ahi[i0] = H0;
        *(__nv_bfloat162*)&g_alo[i0] = L0;
        *(__nv_bfloat162*)&g_ahi[i1] = H1;
        *(__nv_bfloat162*)&g_alo[i1] = L1;
    }
}

// ---------------------------------------------------------------------------
extern "C" void kernel_launch(void* const* d_in, const int* in_sizes, int n_in,
                              void* d_out, int out_size)
{
    const float* X     = (const float*)d_in[0];
    const float* Wqkv  = (const float*)d_in[1];
    const float* bqkv  = (const float*)d_in[2];
    const float* Wproj = (const float*)d_in[3];
    const float* bproj = (const float*)d_in[4];
    float* out = (float*)d_out;

    const int GEMM_SMEM = 2 * 4 * 16384;             // 131072 B
    const int ATTN_SMEM = 32768 + 2 * 32768;         // 98304 B
    cudaFuncSetAttribute(tc_gemm<1>, cudaFuncAttributeMaxDynamicSharedMemorySize, GEMM_SMEM);
    cudaFuncSetAttribute(tc_gemm<0>, cudaFuncAttributeMaxDynamicSharedMemorySize, GEMM_SMEM);
    cudaFuncSetAttribute(attn_mma_kernel, cudaFuncAttributeMaxDynamicSharedMemorySize, ATTN_SMEM);

    // 1) split-convert X; transpose-split weights
    convA_kernel<<<SEQ * DMODEL / 4 / 256, 256>>>(X);
    transW_kernel<1><<<dim3(3 * DMODEL / 32, DMODEL / 32), dim3(32, 8)>>>(Wqkv, DMODEL, 3 * DMODEL);
    transW_kernel<2><<<dim3(DMODEL / 32, DMODEL / 32), dim3(32, 8)>>>(Wproj, DMODEL, DMODEL);

    // 2) QKV GEMM -> bf16 hi/lo q/k/v (q pre-scaled)
    tc_gemm<1><<<dim3(24, 32), 256, GEMM_SMEM>>>(bqkv, nullptr, 3 * DMODEL, DMODEL);

    // 3) fused attention -> g_ahi/g_alo (bf16 split, proj input)
    attn_mma_kernel<<<dim3(32, NH), 256, ATTN_SMEM>>>();

    // 4) proj GEMM -> out
    tc_gemm<0><<<dim3(8, 32), 256, GEMM_SMEM>>>(bproj, out, DMODEL, DMODEL);
}

// round 6
// speedup vs baseline: 3.3493x; 1.2467x over previous
#include <cuda_runtime.h>
#include <cuda_bf16.h>
#include <cuda_fp16.h>
#include <cstdint>

#define SEQ  4096
#define DMODEL 1024
#define NH   16
#define HDIM 64

// bf16 split scratch for the two dense GEMMs (A: X, then attention output)
__device__ __align__(16) __nv_bfloat16 g_ahi[(long)SEQ * DMODEL];
__device__ __align__(16) __nv_bfloat16 g_alo[(long)SEQ * DMODEL];
__device__ __align__(16) __nv_bfloat16 g_bhi1[(long)3 * DMODEL * DMODEL];
__device__ __align__(16) __nv_bfloat16 g_blo1[(long)3 * DMODEL * DMODEL];
__device__ __align__(16) __nv_bfloat16 g_bhi2[(long)DMODEL * DMODEL];
__device__ __align__(16) __nv_bfloat16 g_blo2[(long)DMODEL * DMODEL];
// fp16 q/k/v for attention (q pre-scaled by 0.125), head-major [h][seq][hd]
__device__ __align__(16) __half g_q16[(long)NH * SEQ * HDIM];
__device__ __align__(16) __half g_k16[(long)NH * SEQ * HDIM];
__device__ __align__(16) __half g_v16[(long)NH * SEQ * HDIM];

// ---------------------------------------------------------------------------
// Base-PTX helpers (family-common; no tcgen05)
// ---------------------------------------------------------------------------
__device__ __forceinline__ uint32_t smem_u32(const void* p) {
    uint32_t a;
    asm("{ .reg .u64 t; cvta.to.shared.u64 t, %1; cvt.u32.u64 %0, t; }" : "=r"(a) : "l"(p));
    return a;
}
#define CP16(dst, src) \
    asm volatile("cp.async.cg.shared.global [%0], [%1], 16;" :: "r"(dst), "l"(src))
#define CP_COMMIT() asm volatile("cp.async.commit_group;" ::: "memory")
#define CP_WAIT2()  asm volatile("cp.async.wait_group 2;" ::: "memory")
#define CP_WAIT1()  asm volatile("cp.async.wait_group 1;" ::: "memory")
#define CP_WAIT0()  asm volatile("cp.async.wait_group 0;" ::: "memory")

#define LDSM4(r0, r1, r2, r3, addr) \
    asm volatile("ldmatrix.sync.aligned.m8n8.x4.shared.b16 {%0,%1,%2,%3}, [%4];" \
                 : "=r"(r0), "=r"(r1), "=r"(r2), "=r"(r3) : "r"(addr))
#define LDSM4T(r0, r1, r2, r3, addr) \
    asm volatile("ldmatrix.sync.aligned.m8n8.x4.trans.shared.b16 {%0,%1,%2,%3}, [%4];" \
                 : "=r"(r0), "=r"(r1), "=r"(r2), "=r"(r3) : "r"(addr))

#define MMA16816(c, a, b0, b1) \
    asm volatile("mma.sync.aligned.m16n8k16.row.col.f32.bf16.bf16.f32 " \
                 "{%0,%1,%2,%3}, {%4,%5,%6,%7}, {%8,%9}, {%0,%1,%2,%3};" \
                 : "+f"((c)[0]), "+f"((c)[1]), "+f"((c)[2]), "+f"((c)[3]) \
                 : "r"((a)[0]), "r"((a)[1]), "r"((a)[2]), "r"((a)[3]), \
                   "r"(b0), "r"(b1))
#define MMAH(c, a, b0, b1) \
    asm volatile("mma.sync.aligned.m16n8k16.row.col.f32.f16.f16.f32 " \
                 "{%0,%1,%2,%3}, {%4,%5,%6,%7}, {%8,%9}, {%0,%1,%2,%3};" \
                 : "+f"((c)[0]), "+f"((c)[1]), "+f"((c)[2]), "+f"((c)[3]) \
                 : "r"((a)[0]), "r"((a)[1]), "r"((a)[2]), "r"((a)[3]), \
                   "r"(b0), "r"(b1))

__device__ __forceinline__ uint32_t h2u(__half2 h) { return *(uint32_t*)&h; }

// ---------------------------------------------------------------------------
// Conversion kernels
// ---------------------------------------------------------------------------
__global__ void convA_kernel(const float* __restrict__ A) {
    int i = blockIdx.x * 256 + threadIdx.x;        // float4 index
    float4 v = ((const float4*)A)[i];
    __nv_bfloat162 h01 = __floats2bfloat162_rn(v.x, v.y);
    __nv_bfloat162 h23 = __floats2bfloat162_rn(v.z, v.w);
    __nv_bfloat162 l01 = __floats2bfloat162_rn(v.x - __bfloat162float(h01.x),
                                               v.y - __bfloat162float(h01.y));
    __nv_bfloat162 l23 = __floats2bfloat162_rn(v.z - __bfloat162float(h23.x),
                                               v.w - __bfloat162float(h23.y));
    __nv_bfloat162* H = (__nv_bfloat162*)g_ahi;
    __nv_bfloat162* L = (__nv_bfloat162*)g_alo;
    H[2*i] = h01; H[2*i+1] = h23;
    L[2*i] = l01; L[2*i+1] = l23;
}

template <int WSEL>
__global__ void transW_kernel(const float* __restrict__ W, int K, int N) {
    __nv_bfloat16* Th = (WSEL == 1) ? g_bhi1 : g_bhi2;
    __nv_bfloat16* Tl = (WSEL == 1) ? g_blo1 : g_blo2;
    __shared__ float t[32][33];
    int n0 = blockIdx.x * 32, k0 = blockIdx.y * 32;
    int tx = threadIdx.x, ty = threadIdx.y;   // 32 x 8
#pragma unroll
    for (int r = 0; r < 4; r++)
        t[ty + 8*r][tx] = W[(size_t)(k0 + ty + 8*r) * N + n0 + tx];
    __syncthreads();
#pragma unroll
    for (int r = 0; r < 4; r++) {
        int nl = ty + 8*r, kl = tx;
        float v = t[kl][nl];
        __nv_bfloat16 h = __float2bfloat16(v);
        Th[(size_t)(n0 + nl) * K + k0 + kl] = h;
        Tl[(size_t)(n0 + nl) * K + k0 + kl] = __float2bfloat16(v - __bfloat162float(h));
    }
}

// ---------------------------------------------------------------------------
// mma.sync bf16x3 GEMM, 128x128 tile, 3-stage cp.async pipeline (192KB smem).
// MODE 1: epilogue writes single-fp16 q(scaled)/k/v. MODE 0: fp32 C + bias.
// ---------------------------------------------------------------------------
template <int MODE>
__global__ __launch_bounds__(256, 1) void tc_gemm(
    const float* __restrict__ bias, float* __restrict__ C, int N, int K)
{
    const __nv_bfloat16* __restrict__ Ahi = g_ahi;
    const __nv_bfloat16* __restrict__ Alo = g_alo;
    const __nv_bfloat16* __restrict__ Bhi = (MODE == 1) ? g_bhi1 : g_bhi2;
    const __nv_bfloat16* __restrict__ Blo = (MODE == 1) ? g_blo1 : g_blo2;

    extern __shared__ char smem[];                  // 3 stages x 4 arrays x 16KB
    const uint32_t sb = smem_u32(smem);
    const int tid  = threadIdx.x;
    const int lane = tid & 31;
    const int wid  = tid >> 5;
    const int wm   = wid >> 2;
    const int wn   = wid & 3;
    const int n0 = blockIdx.x * 128, m0 = blockIdx.y * 128;

    float acc[4][4][4];
#pragma unroll
    for (int mt = 0; mt < 4; mt++)
#pragma unroll
        for (int nt = 0; nt < 4; nt++)
#pragma unroll
            for (int r = 0; r < 4; r++) acc[mt][nt][r] = 0.f;

    auto load_stage = [&](int stg, int ck) {
        const uint32_t st = sb + (uint32_t)stg * 65536;
        const int k0 = ck * 64;
#pragma unroll
        for (int arr = 0; arr < 4; arr++) {
            const __nv_bfloat16* src = (arr == 0) ? Ahi : (arr == 1) ? Alo
                                     : (arr == 2) ? Bhi : Blo;
            const int base0 = (arr < 2) ? m0 : n0;
#pragma unroll
            for (int it = 0; it < 4; it++) {
                int id  = it * 256 + tid;
                int row = id >> 3, kc = id & 7;
                const void* g = src + (size_t)(base0 + row) * K + k0 + kc * 8;
                uint32_t soff = (uint32_t)(row * 128 + ((kc * 16) ^ ((row & 7) << 4)));
                CP16(st + arr * 16384 + soff, g);
            }
        }
    };

    const int NC = K / 64;                 // 16
    load_stage(0, 0); CP_COMMIT();
    load_stage(1, 1); CP_COMMIT();

    const int r_lane = lane & 15;
    const int c_lane = (lane >> 4) << 4;
    const uint32_t xorterm = (uint32_t)((r_lane & 7) << 4);

    int buf = 0, nxt = 2;
    for (int c = 0; c < NC; c++) {
        if (c + 2 < NC) { load_stage(nxt, c + 2); CP_COMMIT(); CP_WAIT2();
                          if (++nxt == 3) nxt = 0; }
        else if (c + 1 < NC) { CP_WAIT1(); }
        else                 { CP_WAIT0(); }
        __syncthreads();

        const uint32_t st  = sb + (uint32_t)buf * 65536;
        if (++buf == 3) buf = 0;
        const uint32_t aAh = st +      0 + (uint32_t)((wm * 64 + r_lane) * 128);
        const uint32_t aAl = aAh + 16384;
        const uint32_t aBh = st + 32768 + (uint32_t)((wn * 32 + r_lane) * 128);
        const uint32_t aBl = aBh + 16384;

#pragma unroll
        for (int ks = 0; ks < 4; ks++) {
            const uint32_t cv = ((uint32_t)(ks * 32 + c_lane)) ^ xorterm;
            uint32_t ah[4][4], al[4][4], bh[2][4], bl[2][4];
#pragma unroll
            for (int mt = 0; mt < 4; mt++) {
                LDSM4(ah[mt][0], ah[mt][1], ah[mt][2], ah[mt][3], aAh + mt * 2048 + cv);
                LDSM4(al[mt][0], al[mt][1], al[mt][2], al[mt][3], aAl + mt * 2048 + cv);
            }
#pragma unroll
            for (int bn = 0; bn < 2; bn++) {
                LDSM4(bh[bn][0], bh[bn][1], bh[bn][2], bh[bn][3], aBh + bn * 2048 + cv);
                LDSM4(bl[bn][0], bl[bn][1], bl[bn][2], bl[bn][3], aBl + bn * 2048 + cv);
            }
#pragma unroll
            for (int mt = 0; mt < 4; mt++)
#pragma unroll
                for (int nt = 0; nt < 4; nt++) {
                    int bn = nt >> 1, sub = nt & 1;
                    MMA16816(acc[mt][nt], ah[mt], bh[bn][sub], bh[bn][sub + 2]);
                }
#pragma unroll
            for (int mt = 0; mt < 4; mt++)
#pragma unroll
                for (int nt = 0; nt < 4; nt++) {
                    int bn = nt >> 1, sub = nt & 1;
                    MMA16816(acc[mt][nt], al[mt], bh[bn][sub], bh[bn][sub + 2]);
                }
#pragma unroll
            for (int mt = 0; mt < 4; mt++)
#pragma unroll
                for (int nt = 0; nt < 4; nt++) {
                    int bn = nt >> 1, sub = nt & 1;
                    MMA16816(acc[mt][nt], ah[mt], bl[bn][sub], bl[bn][sub + 2]);
                }
        }
        __syncthreads();
    }

    const int rq = lane >> 2;
    const int cq = (lane & 3) * 2;
#pragma unroll
    for (int mt = 0; mt < 4; mt++) {
#pragma unroll
        for (int nt = 0; nt < 4; nt++) {
            int gcol = n0 + wn * 32 + nt * 8 + cq;
            float b0 = bias[gcol], b1 = bias[gcol + 1];
#pragma unroll
            for (int half = 0; half < 2; half++) {
                int grow = m0 + wm * 64 + mt * 16 + rq + half * 8;
                float vx = acc[mt][nt][half * 2 + 0] + b0;
                float vy = acc[mt][nt][half * 2 + 1] + b1;
                if (MODE == 1) {
                    int sect = gcol >> 10, w = gcol & 1023;
                    int hh = w >> 6, dd = w & 63;
                    if (sect == 0) { vx *= 0.125f; vy *= 0.125f; }
                    __half* dst = (sect == 0) ? g_q16 : (sect == 1) ? g_k16 : g_v16;
                    *(__half2*)&dst[((size_t)hh * SEQ + grow) * HDIM + dd] =
                        __floats2half2_rn(vx, vy);
                } else {
                    float2 v; v.x = vx; v.y = vy;
                    *(float2*)&C[(size_t)grow * N + gcol] = v;
                }
            }
        }
    }
}

// ---------------------------------------------------------------------------
// FlashAttention-2 on mma.sync, fp16 Q/K/V (single) + fp16 hi/lo P split.
// 1 CTA = 1 head x 128 queries, 8 warps x 16 rows. KV tiles of 64, cp.async
// double-buffered. smem = Q 16KB + 2 x (K 8KB + V 8KB) = 48KB -> 2 CTAs/SM.
// ---------------------------------------------------------------------------
__global__ __launch_bounds__(256, 2) void attn_mma_kernel()
{
    extern __shared__ char smem[];
    const uint32_t sb = smem_u32(smem);
    const int tid = threadIdx.x, lane = tid & 31, wid = tid >> 5;
    const int iq = 31 - (int)blockIdx.x;     // heavy blocks first
    const int h  = blockIdx.y;
    const int jmax = 2 * iq + 1;

    const uint32_t Qs = sb;                  // 16KB

    auto load_kv = [&](int stg, int j) {
        const uint32_t st = sb + 16384 + (uint32_t)stg * 16384;
#pragma unroll
        for (int a = 0; a < 2; a++) {
            const __half* src = a ? g_v16 : g_k16;
#pragma unroll
            for (int it = 0; it < 2; it++) {
                int id = it * 256 + tid;
                int row = id >> 3, kc = id & 7;
                uint32_t soff = (uint32_t)(row * 128 + ((kc * 16) ^ ((row & 7) << 4)));
                CP16(st + a * 8192 + soff,
                     src + ((size_t)h * SEQ + j * 64 + row) * HDIM + kc * 8);
            }
        }
    };

    // prologue: Q + first KV stage in one group
    {
#pragma unroll
        for (int it = 0; it < 4; it++) {
            int id = it * 256 + tid;
            int row = id >> 3, kc = id & 7;
            uint32_t soff = (uint32_t)(row * 128 + ((kc * 16) ^ ((row & 7) << 4)));
            CP16(Qs + soff, g_q16 + ((size_t)h * SEQ + iq * 128 + row) * HDIM + kc * 8);
        }
        load_kv(0, 0);
        CP_COMMIT();
    }

    float o[8][4];
#pragma unroll
    for (int nt = 0; nt < 8; nt++)
#pragma unroll
        for (int r = 0; r < 4; r++) o[nt][r] = 0.f;
    float m0 = -1e30f, m1 = -1e30f, l0 = 0.f, l1 = 0.f;
    uint32_t qf[4][4];

    const uint32_t xorterm = (uint32_t)((lane & 7) << 4);
    const uint32_t c_lane  = (uint32_t)((lane >> 4) << 4);
    const int r0g_base = iq * 128 + wid * 16 + (lane >> 2);

    for (int j = 0; j <= jmax; j++) {
        if (j < jmax) { load_kv((j + 1) & 1, j + 1); CP_COMMIT(); CP_WAIT1(); }
        else          { CP_WAIT0(); }
        __syncthreads();

        if (j == 0) {
            const uint32_t qrow = Qs + (uint32_t)((wid * 16 + (lane & 15)) * 128);
#pragma unroll
            for (int ks = 0; ks < 4; ks++) {
                uint32_t cv = ((uint32_t)(ks * 32) + c_lane) ^ xorterm;
                LDSM4(qf[ks][0], qf[ks][1], qf[ks][2], qf[ks][3], qrow + cv);
            }
        }

        const uint32_t st  = sb + 16384 + (uint32_t)(j & 1) * 16384;
        const uint32_t Ks = st, Vs = st + 8192;

        // ---- S = Q @ K^T (scale pre-folded into q), single fp16 ----
        float s[8][4];
#pragma unroll
        for (int nt = 0; nt < 8; nt++)
#pragma unroll
            for (int r = 0; r < 4; r++) s[nt][r] = 0.f;

#pragma unroll
        for (int ks = 0; ks < 4; ks++) {
            uint32_t cv = ((uint32_t)(ks * 32) + c_lane) ^ xorterm;
#pragma unroll
            for (int bn = 0; bn < 4; bn++) {
                uint32_t kh[4];
                LDSM4(kh[0], kh[1], kh[2], kh[3],
                      Ks + (uint32_t)((bn * 16 + (lane & 15)) * 128) + cv);
#pragma unroll
                for (int sub = 0; sub < 2; sub++)
                    MMAH(s[bn * 2 + sub], qf[ks], kh[sub], kh[sub + 2]);
            }
        }

        // ---- causal mask ----
        if (j >= 2 * iq) {
            int cbase = j * 64 + (lane & 3) * 2;
#pragma unroll
            for (int nt = 0; nt < 8; nt++) {
                int c0 = cbase + nt * 8, c1 = c0 + 1;
                if (c0 > r0g_base)     s[nt][0] = -1e30f;
                if (c1 > r0g_base)     s[nt][1] = -1e30f;
                if (c0 > r0g_base + 8) s[nt][2] = -1e30f;
                if (c1 > r0g_base + 8) s[nt][3] = -1e30f;
            }
        }

        // ---- online softmax (quad shfl reductions) ----
        float mx0 = -1e30f, mx1 = -1e30f;
#pragma unroll
        for (int nt = 0; nt < 8; nt++) {
            mx0 = fmaxf(mx0, fmaxf(s[nt][0], s[nt][1]));
            mx1 = fmaxf(mx1, fmaxf(s[nt][2], s[nt][3]));
        }
        mx0 = fmaxf(mx0, __shfl_xor_sync(0xFFFFFFFFu, mx0, 1));
        mx0 = fmaxf(mx0, __shfl_xor_sync(0xFFFFFFFFu, mx0, 2));
        mx1 = fmaxf(mx1, __shfl_xor_sync(0xFFFFFFFFu, mx1, 1));
        mx1 = fmaxf(mx1, __shfl_xor_sync(0xFFFFFFFFu, mx1, 2));
        float mn0 = fmaxf(m0, mx0), mn1 = fmaxf(m1, mx1);
        float al0 = __expf(m0 - mn0), al1 = __expf(m1 - mn1);
        m0 = mn0; m1 = mn1;

        float sum0 = 0.f, sum1 = 0.f;
#pragma unroll
        for (int nt = 0; nt < 8; nt++) {
            s[nt][0] = __expf(s[nt][0] - mn0);
            s[nt][1] = __expf(s[nt][1] - mn0);
            s[nt][2] = __expf(s[nt][2] - mn1);
            s[nt][3] = __expf(s[nt][3] - mn1);
            sum0 += s[nt][0] + s[nt][1];
            sum1 += s[nt][2] + s[nt][3];
        }
        sum0 += __shfl_xor_sync(0xFFFFFFFFu, sum0, 1);
        sum0 += __shfl_xor_sync(0xFFFFFFFFu, sum0, 2);
        sum1 += __shfl_xor_sync(0xFFFFFFFFu, sum1, 1);
        sum1 += __shfl_xor_sync(0xFFFFFFFFu, sum1, 2);
        l0 = l0 * al0 + sum0;
        l1 = l1 * al1 + sum1;

#pragma unroll
        for (int nt = 0; nt < 8; nt++) {
            o[nt][0] *= al0; o[nt][1] *= al0;
            o[nt][2] *= al1; o[nt][3] *= al1;
        }

        // ---- O += P @ V (P split fp16 hi/lo from registers; V single) ----
#pragma unroll
        for (int t = 0; t < 4; t++) {
            uint32_t ap[4], apl[4];
#pragma unroll
            for (int u = 0; u < 4; u++) {
                int nt = t * 2 + (u >> 1);
                int base = (u & 1) * 2;
                float p0 = s[nt][base], p1 = s[nt][base + 1];
                __half h0 = __float2half_rn(p0), h1 = __float2half_rn(p1);
                __half e0 = __float2half_rn(p0 - __half2float(h0));
                __half e1 = __float2half_rn(p1 - __half2float(h1));
                ap[u]  = h2u(__halves2half2(h0, h1));
                apl[u] = h2u(__halves2half2(e0, e1));
            }
            uint32_t rowoff = (uint32_t)((t * 16 + (lane & 15)) * 128);
#pragma unroll
            for (int g = 0; g < 4; g++) {
                uint32_t cvv = ((uint32_t)(g * 32) + c_lane) ^ xorterm;
                uint32_t vh[4];
                LDSM4T(vh[0], vh[1], vh[2], vh[3], Vs + rowoff + cvv);
                MMAH(o[g * 2],     ap,  vh[0], vh[1]);
                MMAH(o[g * 2 + 1], ap,  vh[2], vh[3]);
                MMAH(o[g * 2],     apl, vh[0], vh[1]);
                MMAH(o[g * 2 + 1], apl, vh[2], vh[3]);
            }
        }
        __syncthreads();
    }

    // ---- normalize + write bf16 hi/lo into proj-GEMM input ----
    float inv0 = 1.f / l0, inv1 = 1.f / l1;
    int colb = h * 64 + (lane & 3) * 2;
#pragma unroll
    for (int nt = 0; nt < 8; nt++) {
        int col = colb + nt * 8;
        float x0 = o[nt][0] * inv0, x1 = o[nt][1] * inv0;
        float y0 = o[nt][2] * inv1, y1 = o[nt][3] * inv1;
        __nv_bfloat162 H0 = __floats2bfloat162_rn(x0, x1);
        __nv_bfloat162 L0 = __floats2bfloat162_rn(x0 - __bfloat162float(H0.x),
                                                  x1 - __bfloat162float(H0.y));
        __nv_bfloat162 H1 = __floats2bfloat162_rn(y0, y1);
        __nv_bfloat162 L1 = __floats2bfloat162_rn(y0 - __bfloat162float(H1.x),
                                                  y1 - __bfloat162float(H1.y));
        size_t i0 = (size_t)r0g_base * DMODEL + col;
        size_t i1 = (size_t)(r0g_base + 8) * DMODEL + col;
        *(__nv_bfloat162*)&g_ahi[i0] = H0;
        *(__nv_bfloat162*)&g_alo[i0] = L0;
        *(__nv_bfloat162*)&g_ahi[i1] = H1;
        *(__nv_bfloat162*)&g_alo[i1] = L1;
    }
}

// ---------------------------------------------------------------------------
extern "C" void kernel_launch(void* const* d_in, const int* in_sizes, int n_in,
                              void* d_out, int out_size)
{
    const float* X     = (const float*)d_in[0];
    const float* Wqkv  = (const float*)d_in[1];
    const float* bqkv  = (const float*)d_in[2];
    const float* Wproj = (const float*)d_in[3];
    const float* bproj = (const float*)d_in[4];
    float* out = (float*)d_out;

    const int GEMM_SMEM = 3 * 4 * 16384;             // 196608 B (3-stage)
    const int ATTN_SMEM = 16384 + 2 * 16384;         // 49152 B
    cudaFuncSetAttribute(tc_gemm<1>, cudaFuncAttributeMaxDynamicSharedMemorySize, GEMM_SMEM);
    cudaFuncSetAttribute(tc_gemm<0>, cudaFuncAttributeMaxDynamicSharedMemorySize, GEMM_SMEM);
    cudaFuncSetAttribute(attn_mma_kernel, cudaFuncAttributeMaxDynamicSharedMemorySize, ATTN_SMEM);

    // 1) split-convert X; transpose-split weights
    convA_kernel<<<SEQ * DMODEL / 4 / 256, 256>>>(X);
    transW_kernel<1><<<dim3(3 * DMODEL / 32, DMODEL / 32), dim3(32, 8)>>>(Wqkv, DMODEL, 3 * DMODEL);
    transW_kernel<2><<<dim3(DMODEL / 32, DMODEL / 32), dim3(32, 8)>>>(Wproj, DMODEL, DMODEL);

    // 2) QKV GEMM (bf16x3) -> fp16 q(scaled)/k/v
    tc_gemm<1><<<dim3(24, 32), 256, GEMM_SMEM>>>(bqkv, nullptr, 3 * DMODEL, DMODEL);

    // 3) fused attention (fp16) -> g_ahi/g_alo (bf16 split, proj input)
    attn_mma_kernel<<<dim3(32, NH), 256, ATTN_SMEM>>>();

    // 4) proj GEMM (bf16x3) -> out
    tc_gemm<0><<<dim3(8, 32), 256, GEMM_SMEM>>>(bproj, out, DMODEL, DMODEL);
}

// round 7
// speedup vs baseline: 3.9063x; 1.1663x over previous
#include <cuda_runtime.h>
#include <cuda_bf16.h>
#include <cuda_fp16.h>
#include <cstdint>

#define SEQ  4096
#define DMODEL 1024
#define NH   16
#define HDIM 64

// fp16 split X + single fp16 Wqkv (QKV GEMM operands)
__device__ __align__(16) __half g_xh[(long)SEQ * DMODEL];
__device__ __align__(16) __half g_xl[(long)SEQ * DMODEL];
__device__ __align__(16) __half g_w1[(long)3 * DMODEL * DMODEL];   // [N][K]
// bf16 split operands for proj GEMM (A = attention output, B = Wproj)
__device__ __align__(16) __nv_bfloat16 g_ahi[(long)SEQ * DMODEL];
__device__ __align__(16) __nv_bfloat16 g_alo[(long)SEQ * DMODEL];
__device__ __align__(16) __nv_bfloat16 g_bhi2[(long)DMODEL * DMODEL];
__device__ __align__(16) __nv_bfloat16 g_blo2[(long)DMODEL * DMODEL];
// fp16 q/k/v for attention (q pre-scaled by 0.125), head-major [h][seq][hd]
__device__ __align__(16) __half g_q16[(long)NH * SEQ * HDIM];
__device__ __align__(16) __half g_k16[(long)NH * SEQ * HDIM];
__device__ __align__(16) __half g_v16[(long)NH * SEQ * HDIM];

// ---------------------------------------------------------------------------
// Base-PTX helpers (family-common; no tcgen05)
// ---------------------------------------------------------------------------
__device__ __forceinline__ uint32_t smem_u32(const void* p) {
    uint32_t a;
    asm("{ .reg .u64 t; cvta.to.shared.u64 t, %1; cvt.u32.u64 %0, t; }" : "=r"(a) : "l"(p));
    return a;
}
#define CP16(dst, src) \
    asm volatile("cp.async.cg.shared.global [%0], [%1], 16;" :: "r"(dst), "l"(src))
#define CP_COMMIT() asm volatile("cp.async.commit_group;" ::: "memory")
#define CP_WAIT2()  asm volatile("cp.async.wait_group 2;" ::: "memory")
#define CP_WAIT1()  asm volatile("cp.async.wait_group 1;" ::: "memory")
#define CP_WAIT0()  asm volatile("cp.async.wait_group 0;" ::: "memory")

#define LDSM4(r0, r1, r2, r3, addr) \
    asm volatile("ldmatrix.sync.aligned.m8n8.x4.shared.b16 {%0,%1,%2,%3}, [%4];" \
                 : "=r"(r0), "=r"(r1), "=r"(r2), "=r"(r3) : "r"(addr))
#define LDSM4T(r0, r1, r2, r3, addr) \
    asm volatile("ldmatrix.sync.aligned.m8n8.x4.trans.shared.b16 {%0,%1,%2,%3}, [%4];" \
                 : "=r"(r0), "=r"(r1), "=r"(r2), "=r"(r3) : "r"(addr))

#define MMA16816(c, a, b0, b1) \
    asm volatile("mma.sync.aligned.m16n8k16.row.col.f32.bf16.bf16.f32 " \
                 "{%0,%1,%2,%3}, {%4,%5,%6,%7}, {%8,%9}, {%0,%1,%2,%3};" \
                 : "+f"((c)[0]), "+f"((c)[1]), "+f"((c)[2]), "+f"((c)[3]) \
                 : "r"((a)[0]), "r"((a)[1]), "r"((a)[2]), "r"((a)[3]), \
                   "r"(b0), "r"(b1))
#define MMAH(c, a, b0, b1) \
    asm volatile("mma.sync.aligned.m16n8k16.row.col.f32.f16.f16.f32 " \
                 "{%0,%1,%2,%3}, {%4,%5,%6,%7}, {%8,%9}, {%0,%1,%2,%3};" \
                 : "+f"((c)[0]), "+f"((c)[1]), "+f"((c)[2]), "+f"((c)[3]) \
                 : "r"((a)[0]), "r"((a)[1]), "r"((a)[2]), "r"((a)[3]), \
                   "r"(b0), "r"(b1))

__device__ __forceinline__ uint32_t h2u(__half2 h) { return *(uint32_t*)&h; }

// ---------------------------------------------------------------------------
// Conversion kernels
// ---------------------------------------------------------------------------
__global__ void convX_kernel(const float* __restrict__ A) {
    int i = blockIdx.x * 256 + threadIdx.x;        // float4 index
    float4 v = ((const float4*)A)[i];
    __half2 h01 = __floats2half2_rn(v.x, v.y);
    __half2 h23 = __floats2half2_rn(v.z, v.w);
    __half2 l01 = __floats2half2_rn(v.x - __half2float(h01.x),
                                    v.y - __half2float(h01.y));
    __half2 l23 = __floats2half2_rn(v.z - __half2float(h23.x),
                                    v.w - __half2float(h23.y));
    __half2* H = (__half2*)g_xh;
    __half2* L = (__half2*)g_xl;
    H[2*i] = h01; H[2*i+1] = h23;
    L[2*i] = l01; L[2*i+1] = l23;
}

// Wqkv[K][N] fp32 -> g_w1[N][K] single fp16 (transposed)
__global__ void transW1_kernel(const float* __restrict__ W, int K, int N) {
    __shared__ float t[32][33];
    int n0 = blockIdx.x * 32, k0 = blockIdx.y * 32;
    int tx = threadIdx.x, ty = threadIdx.y;   // 32 x 8
#pragma unroll
    for (int r = 0; r < 4; r++)
        t[ty + 8*r][tx] = W[(size_t)(k0 + ty + 8*r) * N + n0 + tx];
    __syncthreads();
#pragma unroll
    for (int r = 0; r < 4; r++) {
        int nl = ty + 8*r, kl = tx;
        g_w1[(size_t)(n0 + nl) * K + k0 + kl] = __float2half_rn(t[kl][nl]);
    }
}

// Wproj[K][N] fp32 -> g_bhi2/g_blo2[N][K] bf16 split (transposed)
__global__ void transW2_kernel(const float* __restrict__ W, int K, int N) {
    __shared__ float t[32][33];
    int n0 = blockIdx.x * 32, k0 = blockIdx.y * 32;
    int tx = threadIdx.x, ty = threadIdx.y;
#pragma unroll
    for (int r = 0; r < 4; r++)
        t[ty + 8*r][tx] = W[(size_t)(k0 + ty + 8*r) * N + n0 + tx];
    __syncthreads();
#pragma unroll
    for (int r = 0; r < 4; r++) {
        int nl = ty + 8*r, kl = tx;
        float v = t[kl][nl];
        __nv_bfloat16 h = __float2bfloat16(v);
        g_bhi2[(size_t)(n0 + nl) * K + k0 + kl] = h;
        g_blo2[(size_t)(n0 + nl) * K + k0 + kl] =
            __float2bfloat16(v - __bfloat162float(h));
    }
}

// ---------------------------------------------------------------------------
// QKV GEMM, fp16x2: A = Xh+Xl (split fp16), B = Wqkv single fp16 [N][K].
// CTA tile 128x128, K-chunk 64, 2-stage cp.async (48KB/stage, 96KB total)
// -> 2 CTAs/SM. Epilogue writes fp16 q(scaled)/k/v head-major.
// ---------------------------------------------------------------------------
__global__ __launch_bounds__(256, 2) void qkv_gemm(const float* __restrict__ bias)
{
    extern __shared__ char smem[];                  // 2 stages x 3 arrays x 16KB
    const uint32_t sb = smem_u32(smem);
    const int tid  = threadIdx.x;
    const int lane = tid & 31;
    const int wid  = tid >> 5;
    const int wm   = wid >> 2;            // 0..1
    const int wn   = wid & 3;             // 0..3
    const int n0 = blockIdx.x * 128, m0 = blockIdx.y * 128;
    const int K = DMODEL;

    float acc[4][4][4];
#pragma unroll
    for (int mt = 0; mt < 4; mt++)
#pragma unroll
        for (int nt = 0; nt < 4; nt++)
#pragma unroll
            for (int r = 0; r < 4; r++) acc[mt][nt][r] = 0.f;

    auto load_stage = [&](int stg, int ck) {
        const uint32_t st = sb + (uint32_t)stg * 49152;
        const int k0 = ck * 64;
#pragma unroll
        for (int arr = 0; arr < 3; arr++) {
            const __half* src = (arr == 0) ? g_xh : (arr == 1) ? g_xl : g_w1;
            const int base0 = (arr < 2) ? m0 : n0;
#pragma unroll
            for (int it = 0; it < 4; it++) {
                int id  = it * 256 + tid;
                int row = id >> 3, kc = id & 7;
                const void* g = src + (size_t)(base0 + row) * K + k0 + kc * 8;
                uint32_t soff = (uint32_t)(row * 128 + ((kc * 16) ^ ((row & 7) << 4)));
                CP16(st + arr * 16384 + soff, g);
            }
        }
    };

    const int NC = K / 64;                 // 16
    load_stage(0, 0); CP_COMMIT();

    const int r_lane = lane & 15;
    const int c_lane = (lane >> 4) << 4;
    const uint32_t xorterm = (uint32_t)((r_lane & 7) << 4);

    for (int c = 0; c < NC; c++) {
        if (c + 1 < NC) { load_stage((c + 1) & 1, c + 1); CP_COMMIT(); CP_WAIT1(); }
        else            { CP_WAIT0(); }
        __syncthreads();

        const uint32_t st  = sb + (uint32_t)(c & 1) * 49152;
        const uint32_t aAh = st +      0 + (uint32_t)((wm * 64 + r_lane) * 128);
        const uint32_t aAl = aAh + 16384;
        const uint32_t aB  = st + 32768 + (uint32_t)((wn * 32 + r_lane) * 128);

#pragma unroll
        for (int ks = 0; ks < 4; ks++) {
            const uint32_t cv = ((uint32_t)(ks * 32 + c_lane)) ^ xorterm;
            uint32_t ah[4][4], al[4][4], bh[2][4];
#pragma unroll
            for (int mt = 0; mt < 4; mt++) {
                LDSM4(ah[mt][0], ah[mt][1], ah[mt][2], ah[mt][3], aAh + mt * 2048 + cv);
                LDSM4(al[mt][0], al[mt][1], al[mt][2], al[mt][3], aAl + mt * 2048 + cv);
            }
#pragma unroll
            for (int bn = 0; bn < 2; bn++)
                LDSM4(bh[bn][0], bh[bn][1], bh[bn][2], bh[bn][3], aB + bn * 2048 + cv);
#pragma unroll
            for (int mt = 0; mt < 4; mt++)
#pragma unroll
                for (int nt = 0; nt < 4; nt++) {
                    int bn = nt >> 1, sub = nt & 1;
                    MMAH(acc[mt][nt], ah[mt], bh[bn][sub], bh[bn][sub + 2]);
                }
#pragma unroll
            for (int mt = 0; mt < 4; mt++)
#pragma unroll
                for (int nt = 0; nt < 4; nt++) {
                    int bn = nt >> 1, sub = nt & 1;
                    MMAH(acc[mt][nt], al[mt], bh[bn][sub], bh[bn][sub + 2]);
                }
        }
        __syncthreads();
    }

    const int rq = lane >> 2;
    const int cq = (lane & 3) * 2;
#pragma unroll
    for (int mt = 0; mt < 4; mt++) {
#pragma unroll
        for (int nt = 0; nt < 4; nt++) {
            int gcol = n0 + wn * 32 + nt * 8 + cq;
            float b0 = bias[gcol], b1 = bias[gcol + 1];
            int sect = gcol >> 10, w = gcol & 1023;
            int hh = w >> 6, dd = w & 63;
            __half* dst = (sect == 0) ? g_q16 : (sect == 1) ? g_k16 : g_v16;
            float sc = (sect == 0) ? 0.125f : 1.0f;
#pragma unroll
            for (int half = 0; half < 2; half++) {
                int grow = m0 + wm * 64 + mt * 16 + rq + half * 8;
                float vx = (acc[mt][nt][half * 2 + 0] + b0) * sc;
                float vy = (acc[mt][nt][half * 2 + 1] + b1) * sc;
                *(__half2*)&dst[((size_t)hh * SEQ + grow) * HDIM + dd] =
                    __floats2half2_rn(vx, vy);
            }
        }
    }
}

// ---------------------------------------------------------------------------
// Proj GEMM, bf16x3 (proven 1.5e-5): A = g_ahi/g_alo, B = g_bhi2/g_blo2.
// 3-stage pipeline, 192KB smem (round-6 config, passing).
// ---------------------------------------------------------------------------
__global__ __launch_bounds__(256, 1) void proj_gemm(
    const float* __restrict__ bias, float* __restrict__ C)
{
    const int N = DMODEL, K = DMODEL;
    extern __shared__ char smem[];
    const uint32_t sb = smem_u32(smem);
    const int tid  = threadIdx.x;
    const int lane = tid & 31;
    const int wid  = tid >> 5;
    const int wm   = wid >> 2;
    const int wn   = wid & 3;
    const int n0 = blockIdx.x * 128, m0 = blockIdx.y * 128;

    float acc[4][4][4];
#pragma unroll
    for (int mt = 0; mt < 4; mt++)
#pragma unroll
        for (int nt = 0; nt < 4; nt++)
#pragma unroll
            for (int r = 0; r < 4; r++) acc[mt][nt][r] = 0.f;

    auto load_stage = [&](int stg, int ck) {
        const uint32_t st = sb + (uint32_t)stg * 65536;
        const int k0 = ck * 64;
#pragma unroll
        for (int arr = 0; arr < 4; arr++) {
            const __nv_bfloat16* src = (arr == 0) ? g_ahi : (arr == 1) ? g_alo
                                     : (arr == 2) ? g_bhi2 : g_blo2;
            const int base0 = (arr < 2) ? m0 : n0;
#pragma unroll
            for (int it = 0; it < 4; it++) {
                int id  = it * 256 + tid;
                int row = id >> 3, kc = id & 7;
                const void* g = src + (size_t)(base0 + row) * K + k0 + kc * 8;
                uint32_t soff = (uint32_t)(row * 128 + ((kc * 16) ^ ((row & 7) << 4)));
                CP16(st + arr * 16384 + soff, g);
            }
        }
    };

    const int NC = K / 64;
    load_stage(0, 0); CP_COMMIT();
    load_stage(1, 1); CP_COMMIT();

    const int r_lane = lane & 15;
    const int c_lane = (lane >> 4) << 4;
    const uint32_t xorterm = (uint32_t)((r_lane & 7) << 4);

    int buf = 0, nxt = 2;
    for (int c = 0; c < NC; c++) {
        if (c + 2 < NC) { load_stage(nxt, c + 2); CP_COMMIT(); CP_WAIT2();
                          if (++nxt == 3) nxt = 0; }
        else if (c + 1 < NC) { CP_WAIT1(); }
        else                 { CP_WAIT0(); }
        __syncthreads();

        const uint32_t st  = sb + (uint32_t)buf * 65536;
        if (++buf == 3) buf = 0;
        const uint32_t aAh = st +      0 + (uint32_t)((wm * 64 + r_lane) * 128);
        const uint32_t aAl = aAh + 16384;
        const uint32_t aBh = st + 32768 + (uint32_t)((wn * 32 + r_lane) * 128);
        const uint32_t aBl = aBh + 16384;

#pragma unroll
        for (int ks = 0; ks < 4; ks++) {
            const uint32_t cv = ((uint32_t)(ks * 32 + c_lane)) ^ xorterm;
            uint32_t ah[4][4], al[4][4], bh[2][4], bl[2][4];
#pragma unroll
            for (int mt = 0; mt < 4; mt++) {
                LDSM4(ah[mt][0], ah[mt][1], ah[mt][2], ah[mt][3], aAh + mt * 2048 + cv);
                LDSM4(al[mt][0], al[mt][1], al[mt][2], al[mt][3], aAl + mt * 2048 + cv);
            }
#pragma unroll
            for (int bn = 0; bn < 2; bn++) {
                LDSM4(bh[bn][0], bh[bn][1], bh[bn][2], bh[bn][3], aBh + bn * 2048 + cv);
                LDSM4(bl[bn][0], bl[bn][1], bl[bn][2], bl[bn][3], aBl + bn * 2048 + cv);
            }
#pragma unroll
            for (int mt = 0; mt < 4; mt++)
#pragma unroll
                for (int nt = 0; nt < 4; nt++) {
                    int bn = nt >> 1, sub = nt & 1;
                    MMA16816(acc[mt][nt], ah[mt], bh[bn][sub], bh[bn][sub + 2]);
                }
#pragma unroll
            for (int mt = 0; mt < 4; mt++)
#pragma unroll
                for (int nt = 0; nt < 4; nt++) {
                    int bn = nt >> 1, sub = nt & 1;
                    MMA16816(acc[mt][nt], al[mt], bh[bn][sub], bh[bn][sub + 2]);
                }
#pragma unroll
            for (int mt = 0; mt < 4; mt++)
#pragma unroll
                for (int nt = 0; nt < 4; nt++) {
                    int bn = nt >> 1, sub = nt & 1;
                    MMA16816(acc[mt][nt], ah[mt], bl[bn][sub], bl[bn][sub + 2]);
                }
        }
        __syncthreads();
    }

    const int rq = lane >> 2;
    const int cq = (lane & 3) * 2;
#pragma unroll
    for (int mt = 0; mt < 4; mt++) {
#pragma unroll
        for (int nt = 0; nt < 4; nt++) {
            int gcol = n0 + wn * 32 + nt * 8 + cq;
            float b0 = bias[gcol], b1 = bias[gcol + 1];
#pragma unroll
            for (int half = 0; half < 2; half++) {
                int grow = m0 + wm * 64 + mt * 16 + rq + half * 8;
                float2 v;
                v.x = acc[mt][nt][half * 2 + 0] + b0;
                v.y = acc[mt][nt][half * 2 + 1] + b1;
                *(float2*)&C[(size_t)grow * N + gcol] = v;
            }
        }
    }
}

// ---------------------------------------------------------------------------
// FlashAttention-2 on mma.sync, fp16 Q/K/V + fp16 hi/lo P split (round 6,
// passing at rel_err 3.3e-4). smem 48KB -> 2 CTAs/SM.
// ---------------------------------------------------------------------------
__global__ __launch_bounds__(256, 2) void attn_mma_kernel()
{
    extern __shared__ char smem[];
    const uint32_t sb = smem_u32(smem);
    const int tid = threadIdx.x, lane = tid & 31, wid = tid >> 5;
    const int iq = 31 - (int)blockIdx.x;     // heavy blocks first
    const int h  = blockIdx.y;
    const int jmax = 2 * iq + 1;

    const uint32_t Qs = sb;                  // 16KB

    auto load_kv = [&](int stg, int j) {
        const uint32_t st = sb + 16384 + (uint32_t)stg * 16384;
#pragma unroll
        for (int a = 0; a < 2; a++) {
            const __half* src = a ? g_v16 : g_k16;
#pragma unroll
            for (int it = 0; it < 2; it++) {
                int id = it * 256 + tid;
                int row = id >> 3, kc = id & 7;
                uint32_t soff = (uint32_t)(row * 128 + ((kc * 16) ^ ((row & 7) << 4)));
                CP16(st + a * 8192 + soff,
                     src + ((size_t)h * SEQ + j * 64 + row) * HDIM + kc * 8);
            }
        }
    };

    {
#pragma unroll
        for (int it = 0; it < 4; it++) {
            int id = it * 256 + tid;
            int row = id >> 3, kc = id & 7;
            uint32_t soff = (uint32_t)(row * 128 + ((kc * 16) ^ ((row & 7) << 4)));
            CP16(Qs + soff, g_q16 + ((size_t)h * SEQ + iq * 128 + row) * HDIM + kc * 8);
        }
        load_kv(0, 0);
        CP_COMMIT();
    }

    float o[8][4];
#pragma unroll
    for (int nt = 0; nt < 8; nt++)
#pragma unroll
        for (int r = 0; r < 4; r++) o[nt][r] = 0.f;
    float m0 = -1e30f, m1 = -1e30f, l0 = 0.f, l1 = 0.f;
    uint32_t qf[4][4];

    const uint32_t xorterm = (uint32_t)((lane & 7) << 4);
    const uint32_t c_lane  = (uint32_t)((lane >> 4) << 4);
    const int r0g_base = iq * 128 + wid * 16 + (lane >> 2);

    for (int j = 0; j <= jmax; j++) {
        if (j < jmax) { load_kv((j + 1) & 1, j + 1); CP_COMMIT(); CP_WAIT1(); }
        else          { CP_WAIT0(); }
        __syncthreads();

        if (j == 0) {
            const uint32_t qrow = Qs + (uint32_t)((wid * 16 + (lane & 15)) * 128);
#pragma unroll
            for (int ks = 0; ks < 4; ks++) {
                uint32_t cv = ((uint32_t)(ks * 32) + c_lane) ^ xorterm;
                LDSM4(qf[ks][0], qf[ks][1], qf[ks][2], qf[ks][3], qrow + cv);
            }
        }

        const uint32_t st  = sb + 16384 + (uint32_t)(j & 1) * 16384;
        const uint32_t Ks = st, Vs = st + 8192;

        float s[8][4];
#pragma unroll
        for (int nt = 0; nt < 8; nt++)
#pragma unroll
            for (int r = 0; r < 4; r++) s[nt][r] = 0.f;

#pragma unroll
        for (int ks = 0; ks < 4; ks++) {
            uint32_t cv = ((uint32_t)(ks * 32) + c_lane) ^ xorterm;
#pragma unroll
            for (int bn = 0; bn < 4; bn++) {
                uint32_t kh[4];
                LDSM4(kh[0], kh[1], kh[2], kh[3],
                      Ks + (uint32_t)((bn * 16 + (lane & 15)) * 128) + cv);
#pragma unroll
                for (int sub = 0; sub < 2; sub++)
                    MMAH(s[bn * 2 + sub], qf[ks], kh[sub], kh[sub + 2]);
            }
        }

        if (j >= 2 * iq) {
            int cbase = j * 64 + (lane & 3) * 2;
#pragma unroll
            for (int nt = 0; nt < 8; nt++) {
                int c0 = cbase + nt * 8, c1 = c0 + 1;
                if (c0 > r0g_base)     s[nt][0] = -1e30f;
                if (c1 > r0g_base)     s[nt][1] = -1e30f;
                if (c0 > r0g_base + 8) s[nt][2] = -1e30f;
                if (c1 > r0g_base + 8) s[nt][3] = -1e30f;
            }
        }

        float mx0 = -1e30f, mx1 = -1e30f;
#pragma unroll
        for (int nt = 0; nt < 8; nt++) {
            mx0 = fmaxf(mx0, fmaxf(s[nt][0], s[nt][1]));
            mx1 = fmaxf(mx1, fmaxf(s[nt][2], s[nt][3]));
        }
        mx0 = fmaxf(mx0, __shfl_xor_sync(0xFFFFFFFFu, mx0, 1));
        mx0 = fmaxf(mx0, __shfl_xor_sync(0xFFFFFFFFu, mx0, 2));
        mx1 = fmaxf(mx1, __shfl_xor_sync(0xFFFFFFFFu, mx1, 1));
        mx1 = fmaxf(mx1, __shfl_xor_sync(0xFFFFFFFFu, mx1, 2));
        float mn0 = fmaxf(m0, mx0), mn1 = fmaxf(m1, mx1);
        float al0 = __expf(m0 - mn0), al1 = __expf(m1 - mn1);
        m0 = mn0; m1 = mn1;

        float sum0 = 0.f, sum1 = 0.f;
#pragma unroll
        for (int nt = 0; nt < 8; nt++) {
            s[nt][0] = __expf(s[nt][0] - mn0);
            s[nt][1] = __expf(s[nt][1] - mn0);
            s[nt][2] = __expf(s[nt][2] - mn1);
            s[nt][3] = __expf(s[nt][3] - mn1);
            sum0 += s[nt][0] + s[nt][1];
            sum1 += s[nt][2] + s[nt][3];
        }
        sum0 += __shfl_xor_sync(0xFFFFFFFFu, sum0, 1);
        sum0 += __shfl_xor_sync(0xFFFFFFFFu, sum0, 2);
        sum1 += __shfl_xor_sync(0xFFFFFFFFu, sum1, 1);
        sum1 += __shfl_xor_sync(0xFFFFFFFFu, sum1, 2);
        l0 = l0 * al0 + sum0;
        l1 = l1 * al1 + sum1;

#pragma unroll
        for (int nt = 0; nt < 8; nt++) {
            o[nt][0] *= al0; o[nt][1] *= al0;
            o[nt][2] *= al1; o[nt][3] *= al1;
        }

#pragma unroll
        for (int t = 0; t < 4; t++) {
            uint32_t ap[4], apl[4];
#pragma unroll
            for (int u = 0; u < 4; u++) {
                int nt = t * 2 + (u >> 1);
                int base = (u & 1) * 2;
                float p0 = s[nt][base], p1 = s[nt][base + 1];
                __half h0 = __float2half_rn(p0), h1 = __float2half_rn(p1);
                __half e0 = __float2half_rn(p0 - __half2float(h0));
                __half e1 = __float2half_rn(p1 - __half2float(h1));
                ap[u]  = h2u(__halves2half2(h0, h1));
                apl[u] = h2u(__halves2half2(e0, e1));
            }
            uint32_t rowoff = (uint32_t)((t * 16 + (lane & 15)) * 128);
#pragma unroll
            for (int g = 0; g < 4; g++) {
                uint32_t cvv = ((uint32_t)(g * 32) + c_lane) ^ xorterm;
                uint32_t vh[4];
                LDSM4T(vh[0], vh[1], vh[2], vh[3], Vs + rowoff + cvv);
                MMAH(o[g * 2],     ap,  vh[0], vh[1]);
                MMAH(o[g * 2 + 1], ap,  vh[2], vh[3]);
                MMAH(o[g * 2],     apl, vh[0], vh[1]);
                MMAH(o[g * 2 + 1], apl, vh[2], vh[3]);
            }
        }
        __syncthreads();
    }

    // normalize + write bf16 hi/lo into proj-GEMM input
    float inv0 = 1.f / l0, inv1 = 1.f / l1;
    int colb = h * 64 + (lane & 3) * 2;
#pragma unroll
    for (int nt = 0; nt < 8; nt++) {
        int col = colb + nt * 8;
        float x0 = o[nt][0] * inv0, x1 = o[nt][1] * inv0;
        float y0 = o[nt][2] * inv1, y1 = o[nt][3] * inv1;
        __nv_bfloat162 H0 = __floats2bfloat162_rn(x0, x1);
        __nv_bfloat162 L0 = __floats2bfloat162_rn(x0 - __bfloat162float(H0.x),
                                                  x1 - __bfloat162float(H0.y));
        __nv_bfloat162 H1 = __floats2bfloat162_rn(y0, y1);
        __nv_bfloat162 L1 = __floats2bfloat162_rn(y0 - __bfloat162float(H1.x),
                                                  y1 - __bfloat162float(H1.y));
        size_t i0 = (size_t)r0g_base * DMODEL + col;
        size_t i1 = (size_t)(r0g_base + 8) * DMODEL + col;
        *(__nv_bfloat162*)&g_ahi[i0] = H0;
        *(__nv_bfloat162*)&g_alo[i0] = L0;
        *(__nv_bfloat162*)&g_ahi[i1] = H1;
        *(__nv_bfloat162*)&g_alo[i1] = L1;
    }
}

// ---------------------------------------------------------------------------
extern "C" void kernel_launch(void* const* d_in, const int* in_sizes, int n_in,
                              void* d_out, int out_size)
{
    const float* X     = (const float*)d_in[0];
    const float* Wqkv  = (const float*)d_in[1];
    const float* bqkv  = (const float*)d_in[2];
    const float* Wproj = (const float*)d_in[3];
    const float* bproj = (const float*)d_in[4];
    float* out = (float*)d_out;

    const int QKV_SMEM  = 2 * 3 * 16384;             // 98304 B, 2 CTAs/SM
    const int PROJ_SMEM = 3 * 4 * 16384;             // 196608 B
    const int ATTN_SMEM = 16384 + 2 * 16384;         // 49152 B
    cudaFuncSetAttribute(qkv_gemm,  cudaFuncAttributeMaxDynamicSharedMemorySize, QKV_SMEM);
    cudaFuncSetAttribute(proj_gemm, cudaFuncAttributeMaxDynamicSharedMemorySize, PROJ_SMEM);
    cudaFuncSetAttribute(attn_mma_kernel, cudaFuncAttributeMaxDynamicSharedMemorySize, ATTN_SMEM);

    // 1) convert operands
    convX_kernel<<<SEQ * DMODEL / 4 / 256, 256>>>(X);
    transW1_kernel<<<dim3(3 * DMODEL / 32, DMODEL / 32), dim3(32, 8)>>>(Wqkv, DMODEL, 3 * DMODEL);
    transW2_kernel<<<dim3(DMODEL / 32, DMODEL / 32), dim3(32, 8)>>>(Wproj, DMODEL, DMODEL);

    // 2) QKV GEMM (fp16x2, 2 CTAs/SM) -> fp16 q(scaled)/k/v
    qkv_gemm<<<dim3(24, 32), 256, QKV_SMEM>>>(bqkv);

    // 3) fused attention (fp16) -> g_ahi/g_alo (bf16 split, proj input)
    attn_mma_kernel<<<dim3(32, NH), 256, ATTN_SMEM>>>();

    // 4) proj GEMM (bf16x3) -> out
    proj_gemm<<<dim3(8, 32), 256, PROJ_SMEM>>>(bproj, out);
}

// round 8
// speedup vs baseline: 4.3488x; 1.1133x over previous
#include <cuda_runtime.h>
#include <cuda_fp16.h>
#include <cstdint>

#define SEQ  4096
#define DMODEL 1024
#define NH   16
#define HDIM 64

// fp16 split A operand: X for QKV GEMM, then attention output for proj GEMM.
__device__ __align__(16) __half g_xh[(long)SEQ * DMODEL];
__device__ __align__(16) __half g_xl[(long)SEQ * DMODEL];
// single fp16 weights, transposed to [N][K]
__device__ __align__(16) __half g_w1[(long)3 * DMODEL * DMODEL];
__device__ __align__(16) __half g_w2[(long)DMODEL * DMODEL];
// fp16 q/k/v (q pre-scaled by 0.125*log2e), head-major [h][seq][hd]
__device__ __align__(16) __half g_q16[(long)NH * SEQ * HDIM];
__device__ __align__(16) __half g_k16[(long)NH * SEQ * HDIM];
__device__ __align__(16) __half g_v16[(long)NH * SEQ * HDIM];

#define QSCALE 0.18033688f   // 0.125 * log2(e); softmax exp done in exp2 domain

// ---------------------------------------------------------------------------
// Base-PTX helpers (family-common; no tcgen05)
// ---------------------------------------------------------------------------
__device__ __forceinline__ uint32_t smem_u32(const void* p) {
    uint32_t a;
    asm("{ .reg .u64 t; cvta.to.shared.u64 t, %1; cvt.u32.u64 %0, t; }" : "=r"(a) : "l"(p));
    return a;
}
__device__ __forceinline__ float ex2(float x) {
    float y; asm("ex2.approx.f32 %0, %1;" : "=f"(y) : "f"(x)); return y;
}
#define CP16(dst, src) \
    asm volatile("cp.async.cg.shared.global [%0], [%1], 16;" :: "r"(dst), "l"(src))
#define CP_COMMIT() asm volatile("cp.async.commit_group;" ::: "memory")
#define CP_WAIT1()  asm volatile("cp.async.wait_group 1;" ::: "memory")
#define CP_WAIT0()  asm volatile("cp.async.wait_group 0;" ::: "memory")

#define LDSM4(r0, r1, r2, r3, addr) \
    asm volatile("ldmatrix.sync.aligned.m8n8.x4.shared.b16 {%0,%1,%2,%3}, [%4];" \
                 : "=r"(r0), "=r"(r1), "=r"(r2), "=r"(r3) : "r"(addr))
#define LDSM4T(r0, r1, r2, r3, addr) \
    asm volatile("ldmatrix.sync.aligned.m8n8.x4.trans.shared.b16 {%0,%1,%2,%3}, [%4];" \
                 : "=r"(r0), "=r"(r1), "=r"(r2), "=r"(r3) : "r"(addr))

#define MMAH(c, a, b0, b1) \
    asm volatile("mma.sync.aligned.m16n8k16.row.col.f32.f16.f16.f32 " \
                 "{%0,%1,%2,%3}, {%4,%5,%6,%7}, {%8,%9}, {%0,%1,%2,%3};" \
                 : "+f"((c)[0]), "+f"((c)[1]), "+f"((c)[2]), "+f"((c)[3]) \
                 : "r"((a)[0]), "r"((a)[1]), "r"((a)[2]), "r"((a)[3]), \
                   "r"(b0), "r"(b1))

__device__ __forceinline__ uint32_t h2u(__half2 h) { return *(uint32_t*)&h; }

// ---------------------------------------------------------------------------
// Conversion kernels
// ---------------------------------------------------------------------------
__global__ void convX_kernel(const float* __restrict__ A) {
    int i = blockIdx.x * 256 + threadIdx.x;        // float4 index
    float4 v = ((const float4*)A)[i];
    __half2 h01 = __floats2half2_rn(v.x, v.y);
    __half2 h23 = __floats2half2_rn(v.z, v.w);
    float2 f01 = __half22float2(h01);
    float2 f23 = __half22float2(h23);
    __half2 l01 = __floats2half2_rn(v.x - f01.x, v.y - f01.y);
    __half2 l23 = __floats2half2_rn(v.z - f23.x, v.w - f23.y);
    __half2* H = (__half2*)g_xh;
    __half2* L = (__half2*)g_xl;
    H[2*i] = h01; H[2*i+1] = h23;
    L[2*i] = l01; L[2*i+1] = l23;
}

// W[K][N] fp32 -> [N][K] single fp16 (transposed). WSEL: 1=Wqkv, 0=Wproj
template <int WSEL>
__global__ void transW_kernel(const float* __restrict__ W, int K, int N) {
    __half* T = WSEL ? g_w1 : g_w2;
    __shared__ float t[32][33];
    int n0 = blockIdx.x * 32, k0 = blockIdx.y * 32;
    int tx = threadIdx.x, ty = threadIdx.y;   // 32 x 8
#pragma unroll
    for (int r = 0; r < 4; r++)
        t[ty + 8*r][tx] = W[(size_t)(k0 + ty + 8*r) * N + n0 + tx];
    __syncthreads();
#pragma unroll
    for (int r = 0; r < 4; r++) {
        int nl = ty + 8*r, kl = tx;
        T[(size_t)(n0 + nl) * K + k0 + kl] = __float2half_rn(t[kl][nl]);
    }
}

// ---------------------------------------------------------------------------
// fp16x2 GEMM: A = g_xh/g_xl (split fp16 [M][K]), B single fp16 [N][K].
// CTA tile 128x128, K-chunk 64, 2-stage cp.async (96KB) -> 2 CTAs/SM.
// MODE 1: B=g_w1, epilogue -> fp16 q(scaled)/k/v. MODE 0: B=g_w2, fp32 C+bias.
// ---------------------------------------------------------------------------
template <int MODE>
__global__ __launch_bounds__(256, 2) void gemm16(
    const float* __restrict__ bias, float* __restrict__ C, int N)
{
    const __half* __restrict__ B = MODE ? g_w1 : g_w2;
    const int K = DMODEL;

    extern __shared__ char smem[];                  // 2 stages x 3 arrays x 16KB
    const uint32_t sb = smem_u32(smem);
    const int tid  = threadIdx.x;
    const int lane = tid & 31;
    const int wid  = tid >> 5;
    const int wm   = wid >> 2;            // 0..1
    const int wn   = wid & 3;             // 0..3
    const int n0 = blockIdx.x * 128, m0 = blockIdx.y * 128;

    float acc[4][4][4];
#pragma unroll
    for (int mt = 0; mt < 4; mt++)
#pragma unroll
        for (int nt = 0; nt < 4; nt++)
#pragma unroll
            for (int r = 0; r < 4; r++) acc[mt][nt][r] = 0.f;

    auto load_stage = [&](int stg, int ck) {
        const uint32_t st = sb + (uint32_t)stg * 49152;
        const int k0 = ck * 64;
#pragma unroll
        for (int arr = 0; arr < 3; arr++) {
            const __half* src = (arr == 0) ? g_xh : (arr == 1) ? g_xl : B;
            const int base0 = (arr < 2) ? m0 : n0;
#pragma unroll
            for (int it = 0; it < 4; it++) {
                int id  = it * 256 + tid;
                int row = id >> 3, kc = id & 7;
                const void* g = src + (size_t)(base0 + row) * K + k0 + kc * 8;
                uint32_t soff = (uint32_t)(row * 128 + ((kc * 16) ^ ((row & 7) << 4)));
                CP16(st + arr * 16384 + soff, g);
            }
        }
    };

    const int NC = K / 64;                 // 16
    load_stage(0, 0); CP_COMMIT();

    const int r_lane = lane & 15;
    const int c_lane = (lane >> 4) << 4;
    const uint32_t xorterm = (uint32_t)((r_lane & 7) << 4);

    for (int c = 0; c < NC; c++) {
        if (c + 1 < NC) { load_stage((c + 1) & 1, c + 1); CP_COMMIT(); CP_WAIT1(); }
        else            { CP_WAIT0(); }
        __syncthreads();

        const uint32_t st  = sb + (uint32_t)(c & 1) * 49152;
        const uint32_t aAh = st +      0 + (uint32_t)((wm * 64 + r_lane) * 128);
        const uint32_t aAl = aAh + 16384;
        const uint32_t aB  = st + 32768 + (uint32_t)((wn * 32 + r_lane) * 128);

#pragma unroll
        for (int ks = 0; ks < 4; ks++) {
            const uint32_t cv = ((uint32_t)(ks * 32 + c_lane)) ^ xorterm;
            uint32_t ah[4][4], al[4][4], bh[2][4];
#pragma unroll
            for (int mt = 0; mt < 4; mt++) {
                LDSM4(ah[mt][0], ah[mt][1], ah[mt][2], ah[mt][3], aAh + mt * 2048 + cv);
                LDSM4(al[mt][0], al[mt][1], al[mt][2], al[mt][3], aAl + mt * 2048 + cv);
            }
#pragma unroll
            for (int bn = 0; bn < 2; bn++)
                LDSM4(bh[bn][0], bh[bn][1], bh[bn][2], bh[bn][3], aB + bn * 2048 + cv);
#pragma unroll
            for (int mt = 0; mt < 4; mt++)
#pragma unroll
                for (int nt = 0; nt < 4; nt++) {
                    int bn = nt >> 1, sub = nt & 1;
                    MMAH(acc[mt][nt], ah[mt], bh[bn][sub], bh[bn][sub + 2]);
                }
#pragma unroll
            for (int mt = 0; mt < 4; mt++)
#pragma unroll
                for (int nt = 0; nt < 4; nt++) {
                    int bn = nt >> 1, sub = nt & 1;
                    MMAH(acc[mt][nt], al[mt], bh[bn][sub], bh[bn][sub + 2]);
                }
        }
        __syncthreads();
    }

    const int rq = lane >> 2;
    const int cq = (lane & 3) * 2;
#pragma unroll
    for (int mt = 0; mt < 4; mt++) {
#pragma unroll
        for (int nt = 0; nt < 4; nt++) {
            int gcol = n0 + wn * 32 + nt * 8 + cq;
            float b0 = bias[gcol], b1 = bias[gcol + 1];
            if (MODE == 1) {
                int sect = gcol >> 10, w = gcol & 1023;
                int hh = w >> 6, dd = w & 63;
                __half* dst = (sect == 0) ? g_q16 : (sect == 1) ? g_k16 : g_v16;
                float sc = (sect == 0) ? QSCALE : 1.0f;
#pragma unroll
                for (int half = 0; half < 2; half++) {
                    int grow = m0 + wm * 64 + mt * 16 + rq + half * 8;
                    float vx = (acc[mt][nt][half * 2 + 0] + b0) * sc;
                    float vy = (acc[mt][nt][half * 2 + 1] + b1) * sc;
                    *(__half2*)&dst[((size_t)hh * SEQ + grow) * HDIM + dd] =
                        __floats2half2_rn(vx, vy);
                }
            } else {
#pragma unroll
                for (int half = 0; half < 2; half++) {
                    int grow = m0 + wm * 64 + mt * 16 + rq + half * 8;
                    float2 v;
                    v.x = acc[mt][nt][half * 2 + 0] + b0;
                    v.y = acc[mt][nt][half * 2 + 1] + b1;
                    *(float2*)&C[(size_t)grow * N + gcol] = v;
                }
            }
        }
    }
}

// ---------------------------------------------------------------------------
// FlashAttention-2 on mma.sync, fp16 Q/K/V + fp16 hi/lo P split, exp2-domain
// softmax (log2e folded into q). Writes fp16 hi/lo output into g_xh/g_xl.
// smem 48KB -> 2 CTAs/SM.
// ---------------------------------------------------------------------------
__global__ __launch_bounds__(256, 2) void attn_mma_kernel()
{
    extern __shared__ char smem[];
    const uint32_t sb = smem_u32(smem);
    const int tid = threadIdx.x, lane = tid & 31, wid = tid >> 5;
    const int iq = 31 - (int)blockIdx.x;     // heavy blocks first
    const int h  = blockIdx.y;
    const int jmax = 2 * iq + 1;

    const uint32_t Qs = sb;                  // 16KB

    auto load_kv = [&](int stg, int j) {
        const uint32_t st = sb + 16384 + (uint32_t)stg * 16384;
#pragma unroll
        for (int a = 0; a < 2; a++) {
            const __half* src = a ? g_v16 : g_k16;
#pragma unroll
            for (int it = 0; it < 2; it++) {
                int id = it * 256 + tid;
                int row = id >> 3, kc = id & 7;
                uint32_t soff = (uint32_t)(row * 128 + ((kc * 16) ^ ((row & 7) << 4)));
                CP16(st + a * 8192 + soff,
                     src + ((size_t)h * SEQ + j * 64 + row) * HDIM + kc * 8);
            }
        }
    };

    {
#pragma unroll
        for (int it = 0; it < 4; it++) {
            int id = it * 256 + tid;
            int row = id >> 3, kc = id & 7;
            uint32_t soff = (uint32_t)(row * 128 + ((kc * 16) ^ ((row & 7) << 4)));
            CP16(Qs + soff, g_q16 + ((size_t)h * SEQ + iq * 128 + row) * HDIM + kc * 8);
        }
        load_kv(0, 0);
        CP_COMMIT();
    }

    float o[8][4];
#pragma unroll
    for (int nt = 0; nt < 8; nt++)
#pragma unroll
        for (int r = 0; r < 4; r++) o[nt][r] = 0.f;
    float m0 = -1e30f, m1 = -1e30f, l0 = 0.f, l1 = 0.f;
    uint32_t qf[4][4];

    const uint32_t xorterm = (uint32_t)((lane & 7) << 4);
    const uint32_t c_lane  = (uint32_t)((lane >> 4) << 4);
    const int r0g_base = iq * 128 + wid * 16 + (lane >> 2);

    for (int j = 0; j <= jmax; j++) {
        if (j < jmax) { load_kv((j + 1) & 1, j + 1); CP_COMMIT(); CP_WAIT1(); }
        else          { CP_WAIT0(); }
        __syncthreads();

        if (j == 0) {
            const uint32_t qrow = Qs + (uint32_t)((wid * 16 + (lane & 15)) * 128);
#pragma unroll
            for (int ks = 0; ks < 4; ks++) {
                uint32_t cv = ((uint32_t)(ks * 32) + c_lane) ^ xorterm;
                LDSM4(qf[ks][0], qf[ks][1], qf[ks][2], qf[ks][3], qrow + cv);
            }
        }

        const uint32_t st  = sb + 16384 + (uint32_t)(j & 1) * 16384;
        const uint32_t Ks = st, Vs = st + 8192;

        // ---- S = Q @ K^T (exp2-domain scale pre-folded into q) ----
        float s[8][4];
#pragma unroll
        for (int nt = 0; nt < 8; nt++)
#pragma unroll
            for (int r = 0; r < 4; r++) s[nt][r] = 0.f;

#pragma unroll
        for (int ks = 0; ks < 4; ks++) {
            uint32_t cv = ((uint32_t)(ks * 32) + c_lane) ^ xorterm;
#pragma unroll
            for (int bn = 0; bn < 4; bn++) {
                uint32_t kh[4];
                LDSM4(kh[0], kh[1], kh[2], kh[3],
                      Ks + (uint32_t)((bn * 16 + (lane & 15)) * 128) + cv);
#pragma unroll
                for (int sub = 0; sub < 2; sub++)
                    MMAH(s[bn * 2 + sub], qf[ks], kh[sub], kh[sub + 2]);
            }
        }

        // ---- causal mask ----
        if (j >= 2 * iq) {
            int cbase = j * 64 + (lane & 3) * 2;
#pragma unroll
            for (int nt = 0; nt < 8; nt++) {
                int c0 = cbase + nt * 8, c1 = c0 + 1;
                if (c0 > r0g_base)     s[nt][0] = -1e30f;
                if (c1 > r0g_base)     s[nt][1] = -1e30f;
                if (c0 > r0g_base + 8) s[nt][2] = -1e30f;
                if (c1 > r0g_base + 8) s[nt][3] = -1e30f;
            }
        }

        // ---- online softmax in exp2 domain ----
        float mx0 = -1e30f, mx1 = -1e30f;
#pragma unroll
        for (int nt = 0; nt < 8; nt++) {
            mx0 = fmaxf(mx0, fmaxf(s[nt][0], s[nt][1]));
            mx1 = fmaxf(mx1, fmaxf(s[nt][2], s[nt][3]));
        }
        mx0 = fmaxf(mx0, __shfl_xor_sync(0xFFFFFFFFu, mx0, 1));
        mx0 = fmaxf(mx0, __shfl_xor_sync(0xFFFFFFFFu, mx0, 2));
        mx1 = fmaxf(mx1, __shfl_xor_sync(0xFFFFFFFFu, mx1, 1));
        mx1 = fmaxf(mx1, __shfl_xor_sync(0xFFFFFFFFu, mx1, 2));
        float mn0 = fmaxf(m0, mx0), mn1 = fmaxf(m1, mx1);
        float al0 = ex2(m0 - mn0), al1 = ex2(m1 - mn1);
        m0 = mn0; m1 = mn1;

        float sum0 = 0.f, sum1 = 0.f;
#pragma unroll
        for (int nt = 0; nt < 8; nt++) {
            s[nt][0] = ex2(s[nt][0] - mn0);
            s[nt][1] = ex2(s[nt][1] - mn0);
            s[nt][2] = ex2(s[nt][2] - mn1);
            s[nt][3] = ex2(s[nt][3] - mn1);
            sum0 += s[nt][0] + s[nt][1];
            sum1 += s[nt][2] + s[nt][3];
        }
        sum0 += __shfl_xor_sync(0xFFFFFFFFu, sum0, 1);
        sum0 += __shfl_xor_sync(0xFFFFFFFFu, sum0, 2);
        sum1 += __shfl_xor_sync(0xFFFFFFFFu, sum1, 1);
        sum1 += __shfl_xor_sync(0xFFFFFFFFu, sum1, 2);
        l0 = l0 * al0 + sum0;
        l1 = l1 * al1 + sum1;

#pragma unroll
        for (int nt = 0; nt < 8; nt++) {
            o[nt][0] *= al0; o[nt][1] *= al0;
            o[nt][2] *= al1; o[nt][3] *= al1;
        }

        // ---- O += P @ V (P split fp16 hi/lo, packed converts) ----
#pragma unroll
        for (int t = 0; t < 4; t++) {
            uint32_t ap[4], apl[4];
#pragma unroll
            for (int u = 0; u < 4; u++) {
                int nt = t * 2 + (u >> 1);
                int base = (u & 1) * 2;
                float p0 = s[nt][base], p1 = s[nt][base + 1];
                __half2 H = __floats2half2_rn(p0, p1);
                float2 f = __half22float2(H);
                __half2 L = __floats2half2_rn(p0 - f.x, p1 - f.y);
                ap[u]  = h2u(H);
                apl[u] = h2u(L);
            }
            uint32_t rowoff = (uint32_t)((t * 16 + (lane & 15)) * 128);
#pragma unroll
            for (int g = 0; g < 4; g++) {
                uint32_t cvv = ((uint32_t)(g * 32) + c_lane) ^ xorterm;
                uint32_t vh[4];
                LDSM4T(vh[0], vh[1], vh[2], vh[3], Vs + rowoff + cvv);
                MMAH(o[g * 2],     ap,  vh[0], vh[1]);
                MMAH(o[g * 2 + 1], ap,  vh[2], vh[3]);
                MMAH(o[g * 2],     apl, vh[0], vh[1]);
                MMAH(o[g * 2 + 1], apl, vh[2], vh[3]);
            }
        }
        __syncthreads();
    }

    // ---- normalize + write fp16 hi/lo into proj-GEMM input (g_xh/g_xl) ----
    float inv0 = 1.f / l0, inv1 = 1.f / l1;
    int colb = h * 64 + (lane & 3) * 2;
#pragma unroll
    for (int nt = 0; nt < 8; nt++) {
        int col = colb + nt * 8;
        float x0 = o[nt][0] * inv0, x1 = o[nt][1] * inv0;
        float y0 = o[nt][2] * inv1, y1 = o[nt][3] * inv1;
        __half2 H0 = __floats2half2_rn(x0, x1);
        float2 f0 = __half22float2(H0);
        __half2 L0 = __floats2half2_rn(x0 - f0.x, x1 - f0.y);
        __half2 H1 = __floats2half2_rn(y0, y1);
        float2 f1 = __half22float2(H1);
        __half2 L1 = __floats2half2_rn(y0 - f1.x, y1 - f1.y);
        size_t i0 = (size_t)r0g_base * DMODEL + col;
        size_t i1 = (size_t)(r0g_base + 8) * DMODEL + col;
        *(__half2*)&g_xh[i0] = H0;
        *(__half2*)&g_xl[i0] = L0;
        *(__half2*)&g_xh[i1] = H1;
        *(__half2*)&g_xl[i1] = L1;
    }
}

// ---------------------------------------------------------------------------
extern "C" void kernel_launch(void* const* d_in, const int* in_sizes, int n_in,
                              void* d_out, int out_size)
{
    const float* X     = (const float*)d_in[0];
    const float* Wqkv  = (const float*)d_in[1];
    const float* bqkv  = (const float*)d_in[2];
    const float* Wproj = (const float*)d_in[3];
    const float* bproj = (const float*)d_in[4];
    float* out = (float*)d_out;

    const int GEMM_SMEM = 2 * 3 * 16384;             // 98304 B, 2 CTAs/SM
    const int ATTN_SMEM = 16384 + 2 * 16384;         // 49152 B
    cudaFuncSetAttribute(gemm16<1>, cudaFuncAttributeMaxDynamicSharedMemorySize, GEMM_SMEM);
    cudaFuncSetAttribute(gemm16<0>, cudaFuncAttributeMaxDynamicSharedMemorySize, GEMM_SMEM);
    cudaFuncSetAttribute(attn_mma_kernel, cudaFuncAttributeMaxDynamicSharedMemorySize, ATTN_SMEM);

    // 1) convert operands
    convX_kernel<<<SEQ * DMODEL / 4 / 256, 256>>>(X);
    transW_kernel<1><<<dim3(3 * DMODEL / 32, DMODEL / 32), dim3(32, 8)>>>(Wqkv, DMODEL, 3 * DMODEL);
    transW_kernel<0><<<dim3(DMODEL / 32, DMODEL / 32), dim3(32, 8)>>>(Wproj, DMODEL, DMODEL);

    // 2) QKV GEMM (fp16x2) -> fp16 q(scaled)/k/v
    gemm16<1><<<dim3(24, 32), 256, GEMM_SMEM>>>(bqkv, nullptr, 3 * DMODEL);

    // 3) fused attention (fp16, exp2 softmax) -> g_xh/g_xl
    attn_mma_kernel<<<dim3(32, NH), 256, ATTN_SMEM>>>();

    // 4) proj GEMM (fp16x2) -> out
    gemm16<0><<<dim3(8, 32), 256, GEMM_SMEM>>>(bproj, out, DMODEL);
}

// round 9
// speedup vs baseline: 5.5997x; 1.2876x over previous
#include <cuda_runtime.h>
#include <cuda_fp16.h>
#include <cstdint>

#define SEQ  4096
#define DMODEL 1024
#define NH   16
#define HDIM 64
#define KSPLIT 2

// single fp16 X (qkv GEMM A), fp16 hi/lo proj input (written by combine)
__device__ __align__(16) __half g_x16[(long)SEQ * DMODEL];
__device__ __align__(16) __half g_xh[(long)SEQ * DMODEL];
__device__ __align__(16) __half g_xl[(long)SEQ * DMODEL];
// single fp16 weights, transposed to [N][K]
__device__ __align__(16) __half g_w1[(long)3 * DMODEL * DMODEL];
__device__ __align__(16) __half g_w2[(long)DMODEL * DMODEL];
// fp16 q/k/v (q pre-scaled by 0.125*log2e), head-major [h][seq][hd]
__device__ __align__(16) __half g_q16[(long)NH * SEQ * HDIM];
__device__ __align__(16) __half g_k16[(long)NH * SEQ * HDIM];
__device__ __align__(16) __half g_v16[(long)NH * SEQ * HDIM];
// split-KV partials: unnormalized O + per-row m,l (exp2 domain)
__device__ __align__(16) float g_opart[(long)KSPLIT * SEQ * DMODEL];
__device__ float g_pm[(long)KSPLIT * NH * SEQ];
__device__ float g_pl[(long)KSPLIT * NH * SEQ];

#define QSCALE 0.18033688f   // 0.125 * log2(e)

// ---------------------------------------------------------------------------
__device__ __forceinline__ uint32_t smem_u32(const void* p) {
    uint32_t a;
    asm("{ .reg .u64 t; cvta.to.shared.u64 t, %1; cvt.u32.u64 %0, t; }" : "=r"(a) : "l"(p));
    return a;
}
__device__ __forceinline__ float ex2(float x) {
    float y; asm("ex2.approx.f32 %0, %1;" : "=f"(y) : "f"(x)); return y;
}
#define CP16(dst, src) \
    asm volatile("cp.async.cg.shared.global [%0], [%1], 16;" :: "r"(dst), "l"(src))
#define CP_COMMIT() asm volatile("cp.async.commit_group;" ::: "memory")
#define CP_WAIT1()  asm volatile("cp.async.wait_group 1;" ::: "memory")
#define CP_WAIT0()  asm volatile("cp.async.wait_group 0;" ::: "memory")

#define LDSM4(r0, r1, r2, r3, addr) \
    asm volatile("ldmatrix.sync.aligned.m8n8.x4.shared.b16 {%0,%1,%2,%3}, [%4];" \
                 : "=r"(r0), "=r"(r1), "=r"(r2), "=r"(r3) : "r"(addr))
#define LDSM4T(r0, r1, r2, r3, addr) \
    asm volatile("ldmatrix.sync.aligned.m8n8.x4.trans.shared.b16 {%0,%1,%2,%3}, [%4];" \
                 : "=r"(r0), "=r"(r1), "=r"(r2), "=r"(r3) : "r"(addr))

#define MMAH(c, a, b0, b1) \
    asm volatile("mma.sync.aligned.m16n8k16.row.col.f32.f16.f16.f32 " \
                 "{%0,%1,%2,%3}, {%4,%5,%6,%7}, {%8,%9}, {%0,%1,%2,%3};" \
                 : "+f"((c)[0]), "+f"((c)[1]), "+f"((c)[2]), "+f"((c)[3]) \
                 : "r"((a)[0]), "r"((a)[1]), "r"((a)[2]), "r"((a)[3]), \
                   "r"(b0), "r"(b1))

__device__ __forceinline__ uint32_t h2u(__half2 h) { return *(uint32_t*)&h; }

// ---------------------------------------------------------------------------
// Conversion kernels
// ---------------------------------------------------------------------------
__global__ void convX_kernel(const float* __restrict__ A) {
    int i = blockIdx.x * 256 + threadIdx.x;        // float4 index
    float4 v = ((const float4*)A)[i];
    __half2* H = (__half2*)g_x16;
    H[2*i]   = __floats2half2_rn(v.x, v.y);
    H[2*i+1] = __floats2half2_rn(v.z, v.w);
}

// W[K][N] fp32 -> [N][K] single fp16 (transposed). WSEL: 1=Wqkv, 0=Wproj
template <int WSEL>
__global__ void transW_kernel(const float* __restrict__ W, int K, int N) {
    __half* T = WSEL ? g_w1 : g_w2;
    __shared__ float t[32][33];
    int n0 = blockIdx.x * 32, k0 = blockIdx.y * 32;
    int tx = threadIdx.x, ty = threadIdx.y;   // 32 x 8
#pragma unroll
    for (int r = 0; r < 4; r++)
        t[ty + 8*r][tx] = W[(size_t)(k0 + ty + 8*r) * N + n0 + tx];
    __syncthreads();
#pragma unroll
    for (int r = 0; r < 4; r++) {
        int nl = ty + 8*r, kl = tx;
        T[(size_t)(n0 + nl) * K + k0 + kl] = __float2half_rn(t[kl][nl]);
    }
}

// ---------------------------------------------------------------------------
// QKV GEMM, pure single fp16: A = g_x16 [M][K], B = g_w1 [N][K].
// CTA 128x128, K-chunk 64, 2-stage cp.async (64KB) -> 2 CTAs/SM.
// Epilogue -> fp16 q(scaled)/k/v head-major.
// ---------------------------------------------------------------------------
__global__ __launch_bounds__(256, 2) void qkv_gemm(const float* __restrict__ bias)
{
    const int K = DMODEL, N = 3 * DMODEL;
    extern __shared__ char smem[];                  // 2 stages x 2 arrays x 16KB
    const uint32_t sb = smem_u32(smem);
    const int tid  = threadIdx.x;
    const int lane = tid & 31;
    const int wid  = tid >> 5;
    const int wm   = wid >> 2;            // 0..1
    const int wn   = wid & 3;             // 0..3
    const int n0 = blockIdx.x * 128, m0 = blockIdx.y * 128;

    float acc[4][4][4];
#pragma unroll
    for (int mt = 0; mt < 4; mt++)
#pragma unroll
        for (int nt = 0; nt < 4; nt++)
#pragma unroll
            for (int r = 0; r < 4; r++) acc[mt][nt][r] = 0.f;

    auto load_stage = [&](int stg, int ck) {
        const uint32_t st = sb + (uint32_t)stg * 32768;
        const int k0 = ck * 64;
#pragma unroll
        for (int arr = 0; arr < 2; arr++) {
            const __half* src = arr ? g_w1 : g_x16;
            const int base0 = arr ? n0 : m0;
#pragma unroll
            for (int it = 0; it < 4; it++) {
                int id  = it * 256 + tid;
                int row = id >> 3, kc = id & 7;
                const void* g = src + (size_t)(base0 + row) * K + k0 + kc * 8;
                uint32_t soff = (uint32_t)(row * 128 + ((kc * 16) ^ ((row & 7) << 4)));
                CP16(st + arr * 16384 + soff, g);
            }
        }
    };

    const int NC = K / 64;                 // 16
    load_stage(0, 0); CP_COMMIT();

    const int r_lane = lane & 15;
    const int c_lane = (lane >> 4) << 4;
    const uint32_t xorterm = (uint32_t)((r_lane & 7) << 4);

    for (int c = 0; c < NC; c++) {
        if (c + 1 < NC) { load_stage((c + 1) & 1, c + 1); CP_COMMIT(); CP_WAIT1(); }
        else            { CP_WAIT0(); }
        __syncthreads();

        const uint32_t st = sb + (uint32_t)(c & 1) * 32768;
        const uint32_t aA = st +         (uint32_t)((wm * 64 + r_lane) * 128);
        const uint32_t aB = st + 16384 + (uint32_t)((wn * 32 + r_lane) * 128);

#pragma unroll
        for (int ks = 0; ks < 4; ks++) {
            const uint32_t cv = ((uint32_t)(ks * 32 + c_lane)) ^ xorterm;
            uint32_t ah[4][4], bh[2][4];
#pragma unroll
            for (int mt = 0; mt < 4; mt++)
                LDSM4(ah[mt][0], ah[mt][1], ah[mt][2], ah[mt][3], aA + mt * 2048 + cv);
#pragma unroll
            for (int bn = 0; bn < 2; bn++)
                LDSM4(bh[bn][0], bh[bn][1], bh[bn][2], bh[bn][3], aB + bn * 2048 + cv);
#pragma unroll
            for (int mt = 0; mt < 4; mt++)
#pragma unroll
                for (int nt = 0; nt < 4; nt++) {
                    int bn = nt >> 1, sub = nt & 1;
                    MMAH(acc[mt][nt], ah[mt], bh[bn][sub], bh[bn][sub + 2]);
                }
        }
        __syncthreads();
    }

    const int rq = lane >> 2;
    const int cq = (lane & 3) * 2;
#pragma unroll
    for (int mt = 0; mt < 4; mt++) {
#pragma unroll
        for (int nt = 0; nt < 4; nt++) {
            int gcol = n0 + wn * 32 + nt * 8 + cq;
            float b0 = bias[gcol], b1 = bias[gcol + 1];
            int sect = gcol >> 10, w = gcol & 1023;
            int hh = w >> 6, dd = w & 63;
            __half* dst = (sect == 0) ? g_q16 : (sect == 1) ? g_k16 : g_v16;
            float sc = (sect == 0) ? QSCALE : 1.0f;
#pragma unroll
            for (int half = 0; half < 2; half++) {
                int grow = m0 + wm * 64 + mt * 16 + rq + half * 8;
                float vx = (acc[mt][nt][half * 2 + 0] + b0) * sc;
                float vy = (acc[mt][nt][half * 2 + 1] + b1) * sc;
                *(__half2*)&dst[((size_t)hh * SEQ + grow) * HDIM + dd] =
                    __floats2half2_rn(vx, vy);
            }
        }
    }
}

// ---------------------------------------------------------------------------
// Proj GEMM, fp16x2 (A split): A = g_xh/g_xl, B = g_w2. Round-8 config.
// ---------------------------------------------------------------------------
__global__ __launch_bounds__(256, 2) void proj_gemm(
    const float* __restrict__ bias, float* __restrict__ C)
{
    const int K = DMODEL, N = DMODEL;
    extern __shared__ char smem[];                  // 2 stages x 3 arrays x 16KB
    const uint32_t sb = smem_u32(smem);
    const int tid  = threadIdx.x;
    const int lane = tid & 31;
    const int wid  = tid >> 5;
    const int wm   = wid >> 2;
    const int wn   = wid & 3;
    const int n0 = blockIdx.x * 128, m0 = blockIdx.y * 128;

    float acc[4][4][4];
#pragma unroll
    for (int mt = 0; mt < 4; mt++)
#pragma unroll
        for (int nt = 0; nt < 4; nt++)
#pragma unroll
            for (int r = 0; r < 4; r++) acc[mt][nt][r] = 0.f;

    auto load_stage = [&](int stg, int ck) {
        const uint32_t st = sb + (uint32_t)stg * 49152;
        const int k0 = ck * 64;
#pragma unroll
        for (int arr = 0; arr < 3; arr++) {
            const __half* src = (arr == 0) ? g_xh : (arr == 1) ? g_xl : g_w2;
            const int base0 = (arr < 2) ? m0 : n0;
#pragma unroll
            for (int it = 0; it < 4; it++) {
                int id  = it * 256 + tid;
                int row = id >> 3, kc = id & 7;
                const void* g = src + (size_t)(base0 + row) * K + k0 + kc * 8;
                uint32_t soff = (uint32_t)(row * 128 + ((kc * 16) ^ ((row & 7) << 4)));
                CP16(st + arr * 16384 + soff, g);
            }
        }
    };

    const int NC = K / 64;
    load_stage(0, 0); CP_COMMIT();

    const int r_lane = lane & 15;
    const int c_lane = (lane >> 4) << 4;
    const uint32_t xorterm = (uint32_t)((r_lane & 7) << 4);

    for (int c = 0; c < NC; c++) {
        if (c + 1 < NC) { load_stage((c + 1) & 1, c + 1); CP_COMMIT(); CP_WAIT1(); }
        else            { CP_WAIT0(); }
        __syncthreads();

        const uint32_t st  = sb + (uint32_t)(c & 1) * 49152;
        const uint32_t aAh = st +         (uint32_t)((wm * 64 + r_lane) * 128);
        const uint32_t aAl = aAh + 16384;
        const uint32_t aB  = st + 32768 + (uint32_t)((wn * 32 + r_lane) * 128);

#pragma unroll
        for (int ks = 0; ks < 4; ks++) {
            const uint32_t cv = ((uint32_t)(ks * 32 + c_lane)) ^ xorterm;
            uint32_t ah[4][4], al[4][4], bh[2][4];
#pragma unroll
            for (int mt = 0; mt < 4; mt++) {
                LDSM4(ah[mt][0], ah[mt][1], ah[mt][2], ah[mt][3], aAh + mt * 2048 + cv);
                LDSM4(al[mt][0], al[mt][1], al[mt][2], al[mt][3], aAl + mt * 2048 + cv);
            }
#pragma unroll
            for (int bn = 0; bn < 2; bn++)
                LDSM4(bh[bn][0], bh[bn][1], bh[bn][2], bh[bn][3], aB + bn * 2048 + cv);
#pragma unroll
            for (int mt = 0; mt < 4; mt++)
#pragma unroll
                for (int nt = 0; nt < 4; nt++) {
                    int bn = nt >> 1, sub = nt & 1;
                    MMAH(acc[mt][nt], ah[mt], bh[bn][sub], bh[bn][sub + 2]);
                }
#pragma unroll
            for (int mt = 0; mt < 4; mt++)
#pragma unroll
                for (int nt = 0; nt < 4; nt++) {
                    int bn = nt >> 1, sub = nt & 1;
                    MMAH(acc[mt][nt], al[mt], bh[bn][sub], bh[bn][sub + 2]);
                }
        }
        __syncthreads();
    }

    const int rq = lane >> 2;
    const int cq = (lane & 3) * 2;
#pragma unroll
    for (int mt = 0; mt < 4; mt++) {
#pragma unroll
        for (int nt = 0; nt < 4; nt++) {
            int gcol = n0 + wn * 32 + nt * 8 + cq;
            float b0 = bias[gcol], b1 = bias[gcol + 1];
#pragma unroll
            for (int half = 0; half < 2; half++) {
                int grow = m0 + wm * 64 + mt * 16 + rq + half * 8;
                float2 v;
                v.x = acc[mt][nt][half * 2 + 0] + b0;
                v.y = acc[mt][nt][half * 2 + 1] + b1;
                *(float2*)&C[(size_t)grow * N + gcol] = v;
            }
        }
    }
}

// ---------------------------------------------------------------------------
// FlashAttention-2, split-KV x2. Grid (KSPLIT, 32, NH). Each split handles
// iq+1 of the 2iq+2 KV tiles and writes unnormalized O + (m,l) partials.
// ---------------------------------------------------------------------------
__global__ __launch_bounds__(256, 2) void attn_mma_kernel()
{
    extern __shared__ char smem[];
    const uint32_t sb = smem_u32(smem);
    const int tid = threadIdx.x, lane = tid & 31, wid = tid >> 5;
    const int sp = blockIdx.x;
    const int iq = 31 - (int)blockIdx.y;     // heavy blocks first
    const int h  = blockIdx.z;
    const int jbeg = sp * (iq + 1);
    const int jend = jbeg + iq + 1;

    const uint32_t Qs = sb;                  // 16KB

    auto load_kv = [&](int stg, int j) {
        const uint32_t st = sb + 16384 + (uint32_t)stg * 16384;
#pragma unroll
        for (int a = 0; a < 2; a++) {
            const __half* src = a ? g_v16 : g_k16;
#pragma unroll
            for (int it = 0; it < 2; it++) {
                int id = it * 256 + tid;
                int row = id >> 3, kc = id & 7;
                uint32_t soff = (uint32_t)(row * 128 + ((kc * 16) ^ ((row & 7) << 4)));
                CP16(st + a * 8192 + soff,
                     src + ((size_t)h * SEQ + j * 64 + row) * HDIM + kc * 8);
            }
        }
    };

    {
#pragma unroll
        for (int it = 0; it < 4; it++) {
            int id = it * 256 + tid;
            int row = id >> 3, kc = id & 7;
            uint32_t soff = (uint32_t)(row * 128 + ((kc * 16) ^ ((row & 7) << 4)));
            CP16(Qs + soff, g_q16 + ((size_t)h * SEQ + iq * 128 + row) * HDIM + kc * 8);
        }
        load_kv(0, jbeg);
        CP_COMMIT();
    }

    float o[8][4];
#pragma unroll
    for (int nt = 0; nt < 8; nt++)
#pragma unroll
        for (int r = 0; r < 4; r++) o[nt][r] = 0.f;
    float m0 = -1e30f, m1 = -1e30f, l0 = 0.f, l1 = 0.f;
    uint32_t qf[4][4];

    const uint32_t xorterm = (uint32_t)((lane & 7) << 4);
    const uint32_t c_lane  = (uint32_t)((lane >> 4) << 4);
    const int r0g_base = iq * 128 + wid * 16 + (lane >> 2);

    for (int j = jbeg; j < jend; j++) {
        const int jj = j - jbeg;
        if (j + 1 < jend) { load_kv((jj + 1) & 1, j + 1); CP_COMMIT(); CP_WAIT1(); }
        else              { CP_WAIT0(); }
        __syncthreads();

        if (jj == 0) {
            const uint32_t qrow = Qs + (uint32_t)((wid * 16 + (lane & 15)) * 128);
#pragma unroll
            for (int ks = 0; ks < 4; ks++) {
                uint32_t cv = ((uint32_t)(ks * 32) + c_lane) ^ xorterm;
                LDSM4(qf[ks][0], qf[ks][1], qf[ks][2], qf[ks][3], qrow + cv);
            }
        }

        const uint32_t st  = sb + 16384 + (uint32_t)(jj & 1) * 16384;
        const uint32_t Ks = st, Vs = st + 8192;

        float s[8][4];
#pragma unroll
        for (int nt = 0; nt < 8; nt++)
#pragma unroll
            for (int r = 0; r < 4; r++) s[nt][r] = 0.f;

#pragma unroll
        for (int ks = 0; ks < 4; ks++) {
            uint32_t cv = ((uint32_t)(ks * 32) + c_lane) ^ xorterm;
#pragma unroll
            for (int bn = 0; bn < 4; bn++) {
                uint32_t kh[4];
                LDSM4(kh[0], kh[1], kh[2], kh[3],
                      Ks + (uint32_t)((bn * 16 + (lane & 15)) * 128) + cv);
#pragma unroll
                for (int sub = 0; sub < 2; sub++)
                    MMAH(s[bn * 2 + sub], qf[ks], kh[sub], kh[sub + 2]);
            }
        }

        if (j >= 2 * iq) {
            int cbase = j * 64 + (lane & 3) * 2;
#pragma unroll
            for (int nt = 0; nt < 8; nt++) {
                int c0 = cbase + nt * 8, c1 = c0 + 1;
                if (c0 > r0g_base)     s[nt][0] = -1e30f;
                if (c1 > r0g_base)     s[nt][1] = -1e30f;
                if (c0 > r0g_base + 8) s[nt][2] = -1e30f;
                if (c1 > r0g_base + 8) s[nt][3] = -1e30f;
            }
        }

        float mx0 = -1e30f, mx1 = -1e30f;
#pragma unroll
        for (int nt = 0; nt < 8; nt++) {
            mx0 = fmaxf(mx0, fmaxf(s[nt][0], s[nt][1]));
            mx1 = fmaxf(mx1, fmaxf(s[nt][2], s[nt][3]));
        }
        mx0 = fmaxf(mx0, __shfl_xor_sync(0xFFFFFFFFu, mx0, 1));
        mx0 = fmaxf(mx0, __shfl_xor_sync(0xFFFFFFFFu, mx0, 2));
        mx1 = fmaxf(mx1, __shfl_xor_sync(0xFFFFFFFFu, mx1, 1));
        mx1 = fmaxf(mx1, __shfl_xor_sync(0xFFFFFFFFu, mx1, 2));
        float mn0 = fmaxf(m0, mx0), mn1 = fmaxf(m1, mx1);
        float al0 = ex2(m0 - mn0), al1 = ex2(m1 - mn1);
        m0 = mn0; m1 = mn1;

        float sum0 = 0.f, sum1 = 0.f;
#pragma unroll
        for (int nt = 0; nt < 8; nt++) {
            s[nt][0] = ex2(s[nt][0] - mn0);
            s[nt][1] = ex2(s[nt][1] - mn0);
            s[nt][2] = ex2(s[nt][2] - mn1);
            s[nt][3] = ex2(s[nt][3] - mn1);
            sum0 += s[nt][0] + s[nt][1];
            sum1 += s[nt][2] + s[nt][3];
        }
        sum0 += __shfl_xor_sync(0xFFFFFFFFu, sum0, 1);
        sum0 += __shfl_xor_sync(0xFFFFFFFFu, sum0, 2);
        sum1 += __shfl_xor_sync(0xFFFFFFFFu, sum1, 1);
        sum1 += __shfl_xor_sync(0xFFFFFFFFu, sum1, 2);
        l0 = l0 * al0 + sum0;
        l1 = l1 * al1 + sum1;

#pragma unroll
        for (int nt = 0; nt < 8; nt++) {
            o[nt][0] *= al0; o[nt][1] *= al0;
            o[nt][2] *= al1; o[nt][3] *= al1;
        }

#pragma unroll
        for (int t = 0; t < 4; t++) {
            uint32_t ap[4], apl[4];
#pragma unroll
            for (int u = 0; u < 4; u++) {
                int nt = t * 2 + (u >> 1);
                int base = (u & 1) * 2;
                float p0 = s[nt][base], p1 = s[nt][base + 1];
                __half2 H = __floats2half2_rn(p0, p1);
                float2 f = __half22float2(H);
                __half2 L = __floats2half2_rn(p0 - f.x, p1 - f.y);
                ap[u]  = h2u(H);
                apl[u] = h2u(L);
            }
            uint32_t rowoff = (uint32_t)((t * 16 + (lane & 15)) * 128);
#pragma unroll
            for (int g = 0; g < 4; g++) {
                uint32_t cvv = ((uint32_t)(g * 32) + c_lane) ^ xorterm;
                uint32_t vh[4];
                LDSM4T(vh[0], vh[1], vh[2], vh[3], Vs + rowoff + cvv);
                MMAH(o[g * 2],     ap,  vh[0], vh[1]);
                MMAH(o[g * 2 + 1], ap,  vh[2], vh[3]);
                MMAH(o[g * 2],     apl, vh[0], vh[1]);
                MMAH(o[g * 2 + 1], apl, vh[2], vh[3]);
            }
        }
        __syncthreads();
    }

    // ---- write unnormalized partials ----
    float* Op = g_opart + (size_t)sp * SEQ * DMODEL;
    int colb = h * 64 + (lane & 3) * 2;
#pragma unroll
    for (int nt = 0; nt < 8; nt++) {
        int col = colb + nt * 8;
        size_t i0 = (size_t)r0g_base * DMODEL + col;
        size_t i1 = (size_t)(r0g_base + 8) * DMODEL + col;
        float2 v0; v0.x = o[nt][0]; v0.y = o[nt][1];
        float2 v1; v1.x = o[nt][2]; v1.y = o[nt][3];
        *(float2*)&Op[i0] = v0;
        *(float2*)&Op[i1] = v1;
    }
    if ((lane & 3) == 0) {
        size_t base = (size_t)sp * NH * SEQ + (size_t)h * SEQ;
        g_pm[base + r0g_base]     = m0;
        g_pm[base + r0g_base + 8] = m1;
        g_pl[base + r0g_base]     = l0;
        g_pl[base + r0g_base + 8] = l1;
    }
}

// ---------------------------------------------------------------------------
// Combine split-KV partials (exp2 domain) -> fp16 hi/lo proj input.
// ---------------------------------------------------------------------------
__global__ void combine_kernel()
{
    int idx = blockIdx.x * 256 + threadIdx.x;   // float4 index over SEQ*DMODEL/4
    int row = idx >> 8;                          // 256 float4 per row
    int h   = (idx & 255) >> 4;                  // 16 float4 per head
    size_t mlb = (size_t)h * SEQ + row;
    float m0 = g_pm[mlb], m1 = g_pm[(size_t)NH * SEQ + mlb];
    float l0 = g_pl[mlb], l1 = g_pl[(size_t)NH * SEQ + mlb];
    float ms = fmaxf(m0, m1);
    float w0 = ex2(m0 - ms), w1 = ex2(m1 - ms);
    float inv = 1.0f / (w0 * l0 + w1 * l1);
    w0 *= inv; w1 *= inv;
    float4 a = ((const float4*)g_opart)[idx];
    float4 b = ((const float4*)(g_opart + (size_t)SEQ * DMODEL))[idx];
    float x0 = a.x * w0 + b.x * w1;
    float x1 = a.y * w0 + b.y * w1;
    float x2 = a.z * w0 + b.z * w1;
    float x3 = a.w * w0 + b.w * w1;
    __half2 H0 = __floats2half2_rn(x0, x1);
    __half2 H1 = __floats2half2_rn(x2, x3);
    float2 f0 = __half22float2(H0);
    float2 f1 = __half22float2(H1);
    __half2 L0 = __floats2half2_rn(x0 - f0.x, x1 - f0.y);
    __half2 L1 = __floats2half2_rn(x2 - f1.x, x3 - f1.y);
    ((__half2*)g_xh)[2*idx]   = H0;
    ((__half2*)g_xh)[2*idx+1] = H1;
    ((__half2*)g_xl)[2*idx]   = L0;
    ((__half2*)g_xl)[2*idx+1] = L1;
}

// ---------------------------------------------------------------------------
extern "C" void kernel_launch(void* const* d_in, const int* in_sizes, int n_in,
                              void* d_out, int out_size)
{
    const float* X     = (const float*)d_in[0];
    const float* Wqkv  = (const float*)d_in[1];
    const float* bqkv  = (const float*)d_in[2];
    const float* Wproj = (const float*)d_in[3];
    const float* bproj = (const float*)d_in[4];
    float* out = (float*)d_out;

    const int QKV_SMEM  = 2 * 2 * 16384;             // 65536 B
    const int PROJ_SMEM = 2 * 3 * 16384;             // 98304 B
    const int ATTN_SMEM = 16384 + 2 * 16384;         // 49152 B
    cudaFuncSetAttribute(qkv_gemm,  cudaFuncAttributeMaxDynamicSharedMemorySize, QKV_SMEM);
    cudaFuncSetAttribute(proj_gemm, cudaFuncAttributeMaxDynamicSharedMemorySize, PROJ_SMEM);
    cudaFuncSetAttribute(attn_mma_kernel, cudaFuncAttributeMaxDynamicSharedMemorySize, ATTN_SMEM);

    // 1) convert operands
    convX_kernel<<<SEQ * DMODEL / 4 / 256, 256>>>(X);
    transW_kernel<1><<<dim3(3 * DMODEL / 32, DMODEL / 32), dim3(32, 8)>>>(Wqkv, DMODEL, 3 * DMODEL);
    transW_kernel<0><<<dim3(DMODEL / 32, DMODEL / 32), dim3(32, 8)>>>(Wproj, DMODEL, DMODEL);

    // 2) QKV GEMM (single fp16) -> fp16 q(scaled)/k/v
    qkv_gemm<<<dim3(24, 32), 256, QKV_SMEM>>>(bqkv);

    // 3) split-KV attention + combine -> g_xh/g_xl
    attn_mma_kernel<<<dim3(KSPLIT, 32, NH), 256, ATTN_SMEM>>>();
    combine_kernel<<<SEQ * DMODEL / 4 / 256, 256>>>();

    // 4) proj GEMM (fp16x2) -> out
    proj_gemm<<<dim3(8, 32), 256, PROJ_SMEM>>>(bproj, out);
}

// round 10
// speedup vs baseline: 7.0890x; 1.2660x over previous
#include <cuda_runtime.h>
#include <cuda_fp16.h>
#include <cstdint>

#define SEQ  4096
#define DMODEL 1024
#define NH   16
#define HDIM 64
#define KSPLIT 2

// single fp16 A operand: X for QKV GEMM, then combined attention output for proj
__device__ __align__(16) __half g_x16[(long)SEQ * DMODEL];
// single fp16 weights, transposed to [N][K]
__device__ __align__(16) __half g_w1[(long)3 * DMODEL * DMODEL];
__device__ __align__(16) __half g_w2[(long)DMODEL * DMODEL];
// fp16 q/k/v (q pre-scaled by 0.125*log2e), head-major [h][seq][hd]
__device__ __align__(16) __half g_q16[(long)NH * SEQ * HDIM];
__device__ __align__(16) __half g_k16[(long)NH * SEQ * HDIM];
__device__ __align__(16) __half g_v16[(long)NH * SEQ * HDIM];
// split-KV partials: unnormalized O + per-row m,l (exp2 domain)
__device__ __align__(16) float g_opart[(long)KSPLIT * SEQ * DMODEL];
__device__ float g_pm[(long)KSPLIT * NH * SEQ];
__device__ float g_pl[(long)KSPLIT * NH * SEQ];

#define QSCALE 0.18033688f   // 0.125 * log2(e)

// ---------------------------------------------------------------------------
__device__ __forceinline__ uint32_t smem_u32(const void* p) {
    uint32_t a;
    asm("{ .reg .u64 t; cvta.to.shared.u64 t, %1; cvt.u32.u64 %0, t; }" : "=r"(a) : "l"(p));
    return a;
}
__device__ __forceinline__ float ex2(float x) {
    float y; asm("ex2.approx.f32 %0, %1;" : "=f"(y) : "f"(x)); return y;
}
#define CP16(dst, src) \
    asm volatile("cp.async.cg.shared.global [%0], [%1], 16;" :: "r"(dst), "l"(src))
#define CP_COMMIT() asm volatile("cp.async.commit_group;" ::: "memory")
#define CP_WAIT1()  asm volatile("cp.async.wait_group 1;" ::: "memory")
#define CP_WAIT0()  asm volatile("cp.async.wait_group 0;" ::: "memory")

#define LDSM4(r0, r1, r2, r3, addr) \
    asm volatile("ldmatrix.sync.aligned.m8n8.x4.shared.b16 {%0,%1,%2,%3}, [%4];" \
                 : "=r"(r0), "=r"(r1), "=r"(r2), "=r"(r3) : "r"(addr))
#define LDSM4T(r0, r1, r2, r3, addr) \
    asm volatile("ldmatrix.sync.aligned.m8n8.x4.trans.shared.b16 {%0,%1,%2,%3}, [%4];" \
                 : "=r"(r0), "=r"(r1), "=r"(r2), "=r"(r3) : "r"(addr))

#define MMAH(c, a, b0, b1) \
    asm volatile("mma.sync.aligned.m16n8k16.row.col.f32.f16.f16.f32 " \
                 "{%0,%1,%2,%3}, {%4,%5,%6,%7}, {%8,%9}, {%0,%1,%2,%3};" \
                 : "+f"((c)[0]), "+f"((c)[1]), "+f"((c)[2]), "+f"((c)[3]) \
                 : "r"((a)[0]), "r"((a)[1]), "r"((a)[2]), "r"((a)[3]), \
                   "r"(b0), "r"(b1))

__device__ __forceinline__ uint32_t h2u(__half2 h) { return *(uint32_t*)&h; }

// ---------------------------------------------------------------------------
// Conversion kernels
// ---------------------------------------------------------------------------
__global__ void convX_kernel(const float* __restrict__ A) {
    int i = blockIdx.x * 256 + threadIdx.x;        // float4 index
    float4 v = ((const float4*)A)[i];
    __half2* H = (__half2*)g_x16;
    H[2*i]   = __floats2half2_rn(v.x, v.y);
    H[2*i+1] = __floats2half2_rn(v.z, v.w);
}

// W[K][N] fp32 -> [N][K] single fp16 (transposed). WSEL: 1=Wqkv, 0=Wproj
template <int WSEL>
__global__ void transW_kernel(const float* __restrict__ W, int K, int N) {
    __half* T = WSEL ? g_w1 : g_w2;
    __shared__ float t[32][33];
    int n0 = blockIdx.x * 32, k0 = blockIdx.y * 32;
    int tx = threadIdx.x, ty = threadIdx.y;   // 32 x 8
#pragma unroll
    for (int r = 0; r < 4; r++)
        t[ty + 8*r][tx] = W[(size_t)(k0 + ty + 8*r) * N + n0 + tx];
    __syncthreads();
#pragma unroll
    for (int r = 0; r < 4; r++) {
        int nl = ty + 8*r, kl = tx;
        T[(size_t)(n0 + nl) * K + k0 + kl] = __float2half_rn(t[kl][nl]);
    }
}

// ---------------------------------------------------------------------------
// Single-fp16 GEMM: A = g_x16 [M][K], B = g_w1/g_w2 [N][K].
// CTA 128x128, K-chunk 64, 2-stage cp.async (64KB) -> 2 CTAs/SM.
// MODE 1: epilogue -> fp16 q(scaled)/k/v. MODE 0: fp32 C + bias.
// ---------------------------------------------------------------------------
template <int MODE>
__global__ __launch_bounds__(256, 2) void gemm16(
    const float* __restrict__ bias, float* __restrict__ C, int N)
{
    const __half* __restrict__ B = MODE ? g_w1 : g_w2;
    const int K = DMODEL;
    extern __shared__ char smem[];                  // 2 stages x 2 arrays x 16KB
    const uint32_t sb = smem_u32(smem);
    const int tid  = threadIdx.x;
    const int lane = tid & 31;
    const int wid  = tid >> 5;
    const int wm   = wid >> 2;            // 0..1
    const int wn   = wid & 3;             // 0..3
    const int n0 = blockIdx.x * 128, m0 = blockIdx.y * 128;

    float acc[4][4][4];
#pragma unroll
    for (int mt = 0; mt < 4; mt++)
#pragma unroll
        for (int nt = 0; nt < 4; nt++)
#pragma unroll
            for (int r = 0; r < 4; r++) acc[mt][nt][r] = 0.f;

    auto load_stage = [&](int stg, int ck) {
        const uint32_t st = sb + (uint32_t)stg * 32768;
        const int k0 = ck * 64;
#pragma unroll
        for (int arr = 0; arr < 2; arr++) {
            const __half* src = arr ? B : g_x16;
            const int base0 = arr ? n0 : m0;
#pragma unroll
            for (int it = 0; it < 4; it++) {
                int id  = it * 256 + tid;
                int row = id >> 3, kc = id & 7;
                const void* g = src + (size_t)(base0 + row) * K + k0 + kc * 8;
                uint32_t soff = (uint32_t)(row * 128 + ((kc * 16) ^ ((row & 7) << 4)));
                CP16(st + arr * 16384 + soff, g);
            }
        }
    };

    const int NC = K / 64;                 // 16
    load_stage(0, 0); CP_COMMIT();

    const int r_lane = lane & 15;
    const int c_lane = (lane >> 4) << 4;
    const uint32_t xorterm = (uint32_t)((r_lane & 7) << 4);

    for (int c = 0; c < NC; c++) {
        if (c + 1 < NC) { load_stage((c + 1) & 1, c + 1); CP_COMMIT(); CP_WAIT1(); }
        else            { CP_WAIT0(); }
        __syncthreads();

        const uint32_t st = sb + (uint32_t)(c & 1) * 32768;
        const uint32_t aA = st +         (uint32_t)((wm * 64 + r_lane) * 128);
        const uint32_t aB = st + 16384 + (uint32_t)((wn * 32 + r_lane) * 128);

#pragma unroll
        for (int ks = 0; ks < 4; ks++) {
            const uint32_t cv = ((uint32_t)(ks * 32 + c_lane)) ^ xorterm;
            uint32_t ah[4][4], bh[2][4];
#pragma unroll
            for (int mt = 0; mt < 4; mt++)
                LDSM4(ah[mt][0], ah[mt][1], ah[mt][2], ah[mt][3], aA + mt * 2048 + cv);
#pragma unroll
            for (int bn = 0; bn < 2; bn++)
                LDSM4(bh[bn][0], bh[bn][1], bh[bn][2], bh[bn][3], aB + bn * 2048 + cv);
#pragma unroll
            for (int mt = 0; mt < 4; mt++)
#pragma unroll
                for (int nt = 0; nt < 4; nt++) {
                    int bn = nt >> 1, sub = nt & 1;
                    MMAH(acc[mt][nt], ah[mt], bh[bn][sub], bh[bn][sub + 2]);
                }
        }
        __syncthreads();
    }

    const int rq = lane >> 2;
    const int cq = (lane & 3) * 2;
#pragma unroll
    for (int mt = 0; mt < 4; mt++) {
#pragma unroll
        for (int nt = 0; nt < 4; nt++) {
            int gcol = n0 + wn * 32 + nt * 8 + cq;
            float b0 = bias[gcol], b1 = bias[gcol + 1];
            if (MODE == 1) {
                int sect = gcol >> 10, w = gcol & 1023;
                int hh = w >> 6, dd = w & 63;
                __half* dst = (sect == 0) ? g_q16 : (sect == 1) ? g_k16 : g_v16;
                float sc = (sect == 0) ? QSCALE : 1.0f;
#pragma unroll
                for (int half = 0; half < 2; half++) {
                    int grow = m0 + wm * 64 + mt * 16 + rq + half * 8;
                    float vx = (acc[mt][nt][half * 2 + 0] + b0) * sc;
                    float vy = (acc[mt][nt][half * 2 + 1] + b1) * sc;
                    *(__half2*)&dst[((size_t)hh * SEQ + grow) * HDIM + dd] =
                        __floats2half2_rn(vx, vy);
                }
            } else {
#pragma unroll
                for (int half = 0; half < 2; half++) {
                    int grow = m0 + wm * 64 + mt * 16 + rq + half * 8;
                    float2 v;
                    v.x = acc[mt][nt][half * 2 + 0] + b0;
                    v.y = acc[mt][nt][half * 2 + 1] + b1;
                    *(float2*)&C[(size_t)grow * N + gcol] = v;
                }
            }
        }
    }
}

// ---------------------------------------------------------------------------
// FlashAttention-2, split-KV x2, fp16 Q/K/V and single-fp16 P (relative
// rounding of P contributes ~2.8e-4, within budget). Unnormalized partials.
// ---------------------------------------------------------------------------
__global__ __launch_bounds__(256, 2) void attn_mma_kernel()
{
    extern __shared__ char smem[];
    const uint32_t sb = smem_u32(smem);
    const int tid = threadIdx.x, lane = tid & 31, wid = tid >> 5;
    const int sp = blockIdx.x;
    const int iq = 31 - (int)blockIdx.y;     // heavy blocks first
    const int h  = blockIdx.z;
    const int jbeg = sp * (iq + 1);
    const int jend = jbeg + iq + 1;

    const uint32_t Qs = sb;                  // 16KB

    auto load_kv = [&](int stg, int j) {
        const uint32_t st = sb + 16384 + (uint32_t)stg * 16384;
#pragma unroll
        for (int a = 0; a < 2; a++) {
            const __half* src = a ? g_v16 : g_k16;
#pragma unroll
            for (int it = 0; it < 2; it++) {
                int id = it * 256 + tid;
                int row = id >> 3, kc = id & 7;
                uint32_t soff = (uint32_t)(row * 128 + ((kc * 16) ^ ((row & 7) << 4)));
                CP16(st + a * 8192 + soff,
                     src + ((size_t)h * SEQ + j * 64 + row) * HDIM + kc * 8);
            }
        }
    };

    {
#pragma unroll
        for (int it = 0; it < 4; it++) {
            int id = it * 256 + tid;
            int row = id >> 3, kc = id & 7;
            uint32_t soff = (uint32_t)(row * 128 + ((kc * 16) ^ ((row & 7) << 4)));
            CP16(Qs + soff, g_q16 + ((size_t)h * SEQ + iq * 128 + row) * HDIM + kc * 8);
        }
        load_kv(0, jbeg);
        CP_COMMIT();
    }

    float o[8][4];
#pragma unroll
    for (int nt = 0; nt < 8; nt++)
#pragma unroll
        for (int r = 0; r < 4; r++) o[nt][r] = 0.f;
    float m0 = -1e30f, m1 = -1e30f, l0 = 0.f, l1 = 0.f;
    uint32_t qf[4][4];

    const uint32_t xorterm = (uint32_t)((lane & 7) << 4);
    const uint32_t c_lane  = (uint32_t)((lane >> 4) << 4);
    const int r0g_base = iq * 128 + wid * 16 + (lane >> 2);

    for (int j = jbeg; j < jend; j++) {
        const int jj = j - jbeg;
        if (j + 1 < jend) { load_kv((jj + 1) & 1, j + 1); CP_COMMIT(); CP_WAIT1(); }
        else              { CP_WAIT0(); }
        __syncthreads();

        if (jj == 0) {
            const uint32_t qrow = Qs + (uint32_t)((wid * 16 + (lane & 15)) * 128);
#pragma unroll
            for (int ks = 0; ks < 4; ks++) {
                uint32_t cv = ((uint32_t)(ks * 32) + c_lane) ^ xorterm;
                LDSM4(qf[ks][0], qf[ks][1], qf[ks][2], qf[ks][3], qrow + cv);
            }
        }

        const uint32_t st  = sb + 16384 + (uint32_t)(jj & 1) * 16384;
        const uint32_t Ks = st, Vs = st + 8192;

        float s[8][4];
#pragma unroll
        for (int nt = 0; nt < 8; nt++)
#pragma unroll
            for (int r = 0; r < 4; r++) s[nt][r] = 0.f;

#pragma unroll
        for (int ks = 0; ks < 4; ks++) {
            uint32_t cv = ((uint32_t)(ks * 32) + c_lane) ^ xorterm;
#pragma unroll
            for (int bn = 0; bn < 4; bn++) {
                uint32_t kh[4];
                LDSM4(kh[0], kh[1], kh[2], kh[3],
                      Ks + (uint32_t)((bn * 16 + (lane & 15)) * 128) + cv);
#pragma unroll
                for (int sub = 0; sub < 2; sub++)
                    MMAH(s[bn * 2 + sub], qf[ks], kh[sub], kh[sub + 2]);
            }
        }

        if (j >= 2 * iq) {
            int cbase = j * 64 + (lane & 3) * 2;
#pragma unroll
            for (int nt = 0; nt < 8; nt++) {
                int c0 = cbase + nt * 8, c1 = c0 + 1;
                if (c0 > r0g_base)     s[nt][0] = -1e30f;
                if (c1 > r0g_base)     s[nt][1] = -1e30f;
                if (c0 > r0g_base + 8) s[nt][2] = -1e30f;
                if (c1 > r0g_base + 8) s[nt][3] = -1e30f;
            }
        }

        float mx0 = -1e30f, mx1 = -1e30f;
#pragma unroll
        for (int nt = 0; nt < 8; nt++) {
            mx0 = fmaxf(mx0, fmaxf(s[nt][0], s[nt][1]));
            mx1 = fmaxf(mx1, fmaxf(s[nt][2], s[nt][3]));
        }
        mx0 = fmaxf(mx0, __shfl_xor_sync(0xFFFFFFFFu, mx0, 1));
        mx0 = fmaxf(mx0, __shfl_xor_sync(0xFFFFFFFFu, mx0, 2));
        mx1 = fmaxf(mx1, __shfl_xor_sync(0xFFFFFFFFu, mx1, 1));
        mx1 = fmaxf(mx1, __shfl_xor_sync(0xFFFFFFFFu, mx1, 2));
        float mn0 = fmaxf(m0, mx0), mn1 = fmaxf(m1, mx1);
        float al0 = ex2(m0 - mn0), al1 = ex2(m1 - mn1);
        m0 = mn0; m1 = mn1;

        float sum0 = 0.f, sum1 = 0.f;
#pragma unroll
        for (int nt = 0; nt < 8; nt++) {
            s[nt][0] = ex2(s[nt][0] - mn0);
            s[nt][1] = ex2(s[nt][1] - mn0);
            s[nt][2] = ex2(s[nt][2] - mn1);
            s[nt][3] = ex2(s[nt][3] - mn1);
            sum0 += s[nt][0] + s[nt][1];
            sum1 += s[nt][2] + s[nt][3];
        }
        sum0 += __shfl_xor_sync(0xFFFFFFFFu, sum0, 1);
        sum0 += __shfl_xor_sync(0xFFFFFFFFu, sum0, 2);
        sum1 += __shfl_xor_sync(0xFFFFFFFFu, sum1, 1);
        sum1 += __shfl_xor_sync(0xFFFFFFFFu, sum1, 2);
        l0 = l0 * al0 + sum0;
        l1 = l1 * al1 + sum1;

#pragma unroll
        for (int nt = 0; nt < 8; nt++) {
            o[nt][0] *= al0; o[nt][1] *= al0;
            o[nt][2] *= al1; o[nt][3] *= al1;
        }

        // ---- O += P @ V, single fp16 P ----
#pragma unroll
        for (int t = 0; t < 4; t++) {
            uint32_t ap[4];
#pragma unroll
            for (int u = 0; u < 4; u++) {
                int nt = t * 2 + (u >> 1);
                int base = (u & 1) * 2;
                ap[u] = h2u(__floats2half2_rn(s[nt][base], s[nt][base + 1]));
            }
            uint32_t rowoff = (uint32_t)((t * 16 + (lane & 15)) * 128);
#pragma unroll
            for (int g = 0; g < 4; g++) {
                uint32_t cvv = ((uint32_t)(g * 32) + c_lane) ^ xorterm;
                uint32_t vh[4];
                LDSM4T(vh[0], vh[1], vh[2], vh[3], Vs + rowoff + cvv);
                MMAH(o[g * 2],     ap, vh[0], vh[1]);
                MMAH(o[g * 2 + 1], ap, vh[2], vh[3]);
            }
        }
        __syncthreads();
    }

    // ---- write unnormalized partials ----
    float* Op = g_opart + (size_t)sp * SEQ * DMODEL;
    int colb = h * 64 + (lane & 3) * 2;
#pragma unroll
    for (int nt = 0; nt < 8; nt++) {
        int col = colb + nt * 8;
        size_t i0 = (size_t)r0g_base * DMODEL + col;
        size_t i1 = (size_t)(r0g_base + 8) * DMODEL + col;
        float2 v0; v0.x = o[nt][0]; v0.y = o[nt][1];
        float2 v1; v1.x = o[nt][2]; v1.y = o[nt][3];
        *(float2*)&Op[i0] = v0;
        *(float2*)&Op[i1] = v1;
    }
    if ((lane & 3) == 0) {
        size_t base = (size_t)sp * NH * SEQ + (size_t)h * SEQ;
        g_pm[base + r0g_base]     = m0;
        g_pm[base + r0g_base + 8] = m1;
        g_pl[base + r0g_base]     = l0;
        g_pl[base + r0g_base + 8] = l1;
    }
}

// ---------------------------------------------------------------------------
// Combine split-KV partials (exp2 domain) -> single fp16 proj input (g_x16).
// ---------------------------------------------------------------------------
__global__ void combine_kernel()
{
    int idx = blockIdx.x * 256 + threadIdx.x;   // float4 index over SEQ*DMODEL/4
    int row = idx >> 8;                          // 256 float4 per row
    int h   = (idx & 255) >> 4;                  // 16 float4 per head
    size_t mlb = (size_t)h * SEQ + row;
    float m0 = g_pm[mlb], m1 = g_pm[(size_t)NH * SEQ + mlb];
    float l0 = g_pl[mlb], l1 = g_pl[(size_t)NH * SEQ + mlb];
    float ms = fmaxf(m0, m1);
    float w0 = ex2(m0 - ms), w1 = ex2(m1 - ms);
    float inv = 1.0f / (w0 * l0 + w1 * l1);
    w0 *= inv; w1 *= inv;
    float4 a = ((const float4*)g_opart)[idx];
    float4 b = ((const float4*)(g_opart + (size_t)SEQ * DMODEL))[idx];
    __half2* H = (__half2*)g_x16;
    H[2*idx]   = __floats2half2_rn(a.x * w0 + b.x * w1, a.y * w0 + b.y * w1);
    H[2*idx+1] = __floats2half2_rn(a.z * w0 + b.z * w1, a.w * w0 + b.w * w1);
}

// ---------------------------------------------------------------------------
extern "C" void kernel_launch(void* const* d_in, const int* in_sizes, int n_in,
                              void* d_out, int out_size)
{
    const float* X     = (const float*)d_in[0];
    const float* Wqkv  = (const float*)d_in[1];
    const float* bqkv  = (const float*)d_in[2];
    const float* Wproj = (const float*)d_in[3];
    const float* bproj = (const float*)d_in[4];
    float* out = (float*)d_out;

    const int GEMM_SMEM = 2 * 2 * 16384;             // 65536 B, 2 CTAs/SM
    const int ATTN_SMEM = 16384 + 2 * 16384;         // 49152 B
    cudaFuncSetAttribute(gemm16<1>, cudaFuncAttributeMaxDynamicSharedMemorySize, GEMM_SMEM);
    cudaFuncSetAttribute(gemm16<0>, cudaFuncAttributeMaxDynamicSharedMemorySize, GEMM_SMEM);
    cudaFuncSetAttribute(attn_mma_kernel, cudaFuncAttributeMaxDynamicSharedMemorySize, ATTN_SMEM);

    // 1) convert operands
    convX_kernel<<<SEQ * DMODEL / 4 / 256, 256>>>(X);
    transW_kernel<1><<<dim3(3 * DMODEL / 32, DMODEL / 32), dim3(32, 8)>>>(Wqkv, DMODEL, 3 * DMODEL);
    transW_kernel<0><<<dim3(DMODEL / 32, DMODEL / 32), dim3(32, 8)>>>(Wproj, DMODEL, DMODEL);

    // 2) QKV GEMM (single fp16) -> fp16 q(scaled)/k/v
    gemm16<1><<<dim3(24, 32), 256, GEMM_SMEM>>>(bqkv, nullptr, 3 * DMODEL);

    // 3) split-KV attention + combine -> g_x16 (proj input; X is dead by now)
    attn_mma_kernel<<<dim3(KSPLIT, 32, NH), 256, ATTN_SMEM>>>();
    combine_kernel<<<SEQ * DMODEL / 4 / 256, 256>>>();

    // 4) proj GEMM (single fp16) -> out
    gemm16<0><<<dim3(8, 32), 256, GEMM_SMEM>>>(bproj, out, DMODEL);
}

// round 11
// speedup vs baseline: 7.3286x; 1.0338x over previous
#include <cuda_runtime.h>
#include <cuda_fp16.h>
#include <cstdint>

#define SEQ  4096
#define DMODEL 1024
#define NH   16
#define HDIM 64
#define KSPLIT 2

// single fp16 A operand: X for QKV GEMM, then combined attention output for proj
__device__ __align__(16) __half g_x16[(long)SEQ * DMODEL];
// single fp16 weights, SAME layout as input: [K][N] (loaded k-major via ldsm.trans)
__device__ __align__(16) __half g_w1[(long)DMODEL * 3 * DMODEL];
__device__ __align__(16) __half g_w2[(long)DMODEL * DMODEL];
// fp16 q/k/v (q pre-scaled by 0.125*log2e), head-major [h][seq][hd]
__device__ __align__(16) __half g_q16[(long)NH * SEQ * HDIM];
__device__ __align__(16) __half g_k16[(long)NH * SEQ * HDIM];
__device__ __align__(16) __half g_v16[(long)NH * SEQ * HDIM];
// split-KV partials: unnormalized O + per-row m,l (exp2 domain)
__device__ __align__(16) float g_opart[(long)KSPLIT * SEQ * DMODEL];
__device__ float g_pm[(long)KSPLIT * NH * SEQ];
__device__ float g_pl[(long)KSPLIT * NH * SEQ];

#define QSCALE 0.18033688f   // 0.125 * log2(e)

// ---------------------------------------------------------------------------
__device__ __forceinline__ uint32_t smem_u32(const void* p) {
    uint32_t a;
    asm("{ .reg .u64 t; cvta.to.shared.u64 t, %1; cvt.u32.u64 %0, t; }" : "=r"(a) : "l"(p));
    return a;
}
__device__ __forceinline__ float ex2(float x) {
    float y; asm("ex2.approx.f32 %0, %1;" : "=f"(y) : "f"(x)); return y;
}
#define CP16(dst, src) \
    asm volatile("cp.async.cg.shared.global [%0], [%1], 16;" :: "r"(dst), "l"(src))
#define CP_COMMIT() asm volatile("cp.async.commit_group;" ::: "memory")
#define CP_WAIT1()  asm volatile("cp.async.wait_group 1;" ::: "memory")
#define CP_WAIT0()  asm volatile("cp.async.wait_group 0;" ::: "memory")

#define LDSM4(r0, r1, r2, r3, addr) \
    asm volatile("ldmatrix.sync.aligned.m8n8.x4.shared.b16 {%0,%1,%2,%3}, [%4];" \
                 : "=r"(r0), "=r"(r1), "=r"(r2), "=r"(r3) : "r"(addr))
#define LDSM4T(r0, r1, r2, r3, addr) \
    asm volatile("ldmatrix.sync.aligned.m8n8.x4.trans.shared.b16 {%0,%1,%2,%3}, [%4];" \
                 : "=r"(r0), "=r"(r1), "=r"(r2), "=r"(r3) : "r"(addr))

#define MMAH(c, a, b0, b1) \
    asm volatile("mma.sync.aligned.m16n8k16.row.col.f32.f16.f16.f32 " \
                 "{%0,%1,%2,%3}, {%4,%5,%6,%7}, {%8,%9}, {%0,%1,%2,%3};" \
                 : "+f"((c)[0]), "+f"((c)[1]), "+f"((c)[2]), "+f"((c)[3]) \
                 : "r"((a)[0]), "r"((a)[1]), "r"((a)[2]), "r"((a)[3]), \
                   "r"(b0), "r"(b1))

__device__ __forceinline__ uint32_t h2u(__half2 h) { return *(uint32_t*)&h; }

// ---------------------------------------------------------------------------
// Conversion kernels (all coalesced, no transpose)
// ---------------------------------------------------------------------------
__global__ void convX_kernel(const float* __restrict__ A) {
    int i = blockIdx.x * 256 + threadIdx.x;        // float4 index
    float4 v = ((const float4*)A)[i];
    __half2* H = (__half2*)g_x16;
    H[2*i]   = __floats2half2_rn(v.x, v.y);
    H[2*i+1] = __floats2half2_rn(v.z, v.w);
}

// W fp32 -> fp16, same [K][N] layout. WSEL: 1=Wqkv, 0=Wproj
template <int WSEL>
__global__ void convW_kernel(const float* __restrict__ W) {
    __half* T = WSEL ? g_w1 : g_w2;
    int i = blockIdx.x * 256 + threadIdx.x;
    float4 v = ((const float4*)W)[i];
    __half2* H = (__half2*)T;
    H[2*i]   = __floats2half2_rn(v.x, v.y);
    H[2*i+1] = __floats2half2_rn(v.z, v.w);
}

// ---------------------------------------------------------------------------
// Single-fp16 GEMM: A = g_x16 [M][K]; B = W16 [K][N] loaded k-major and
// consumed via ldmatrix.trans (no weight transpose needed).
// CTA 128x128, K-chunk 64, 3-stage cp.async (96KB) -> 2 CTAs/SM, ONE
// __syncthreads per chunk (prefetch issued after the barrier).
// MODE 1: epilogue -> fp16 q(scaled)/k/v. MODE 0: fp32 C + bias.
// ---------------------------------------------------------------------------
template <int MODE>
__global__ __launch_bounds__(256, 2) void gemm16(
    const float* __restrict__ bias, float* __restrict__ C, int N)
{
    const __half* __restrict__ B = MODE ? g_w1 : g_w2;
    const int K = DMODEL;
    extern __shared__ char smem[];                  // 3 stages x (A 16KB + B 16KB)
    const uint32_t sb = smem_u32(smem);
    const int tid  = threadIdx.x;
    const int lane = tid & 31;
    const int wid  = tid >> 5;
    const int wm   = wid >> 2;            // 0..1
    const int wn   = wid & 3;             // 0..3
    const int n0 = blockIdx.x * 128, m0 = blockIdx.y * 128;

    float acc[4][4][4];
#pragma unroll
    for (int mt = 0; mt < 4; mt++)
#pragma unroll
        for (int nt = 0; nt < 4; nt++)
#pragma unroll
            for (int r = 0; r < 4; r++) acc[mt][nt][r] = 0.f;

    auto load_stage = [&](int stg, int ck) {
        const uint32_t st = sb + (uint32_t)stg * 32768;
        const int k0 = ck * 64;
        // A: 128 rows x 64 k (128B rows, SW swizzle on 8-row period)
#pragma unroll
        for (int it = 0; it < 4; it++) {
            int id  = it * 256 + tid;
            int row = id >> 3, kc = id & 7;
            const void* g = g_x16 + (size_t)(m0 + row) * K + k0 + kc * 8;
            uint32_t soff = (uint32_t)(row * 128 + ((kc * 16) ^ ((row & 7) << 4)));
            CP16(st + soff, g);
        }
        // B: 64 k-rows x 128 n (256B rows, swizzle on 16-row period)
#pragma unroll
        for (int it = 0; it < 4; it++) {
            int id  = it * 256 + tid;
            int row = id >> 4, c16 = id & 15;
            const void* g = B + (size_t)(k0 + row) * N + n0 + c16 * 8;
            uint32_t soff = (uint32_t)(row * 256 + ((c16 * 16) ^ ((row & 15) << 4)));
            CP16(st + 16384 + soff, g);
        }
    };

    const int NC = K / 64;                 // 16
    load_stage(0, 0); CP_COMMIT();
    load_stage(1, 1); CP_COMMIT();

    const int r_lane = lane & 15;
    const int c_lane = (lane >> 4) << 4;
    const uint32_t xorA = (uint32_t)((r_lane & 7) << 4);
    const uint32_t xorB = (uint32_t)(r_lane << 4);
    const uint32_t colB = (uint32_t)(wn * 64 + c_lane);

    for (int c = 0; c < NC; c++) {
        if (c + 1 < NC) { CP_WAIT1(); } else { CP_WAIT0(); }
        __syncthreads();
        if (c + 2 < NC) { load_stage((c + 2) % 3, c + 2); CP_COMMIT(); }

        const uint32_t st = sb + (uint32_t)(c % 3) * 32768;
        const uint32_t aA = st +         (uint32_t)((wm * 64 + r_lane) * 128);
        const uint32_t rB = st + 16384 + (uint32_t)(r_lane * 256);

#pragma unroll
        for (int ks = 0; ks < 4; ks++) {
            const uint32_t cvA = ((uint32_t)(ks * 32 + c_lane)) ^ xorA;
            uint32_t ah[4][4], bh[2][4];
#pragma unroll
            for (int mt = 0; mt < 4; mt++)
                LDSM4(ah[mt][0], ah[mt][1], ah[mt][2], ah[mt][3], aA + mt * 2048 + cvA);
#pragma unroll
            for (int bn = 0; bn < 2; bn++)
                LDSM4T(bh[bn][0], bh[bn][1], bh[bn][2], bh[bn][3],
                       rB + ks * 4096 + (((colB + bn * 32)) ^ xorB));
#pragma unroll
            for (int mt = 0; mt < 4; mt++)
#pragma unroll
                for (int nt = 0; nt < 4; nt++) {
                    int bn = nt >> 1, sub = nt & 1;
                    MMAH(acc[mt][nt], ah[mt], bh[bn][sub * 2], bh[bn][sub * 2 + 1]);
                }
        }
    }

    const int rq = lane >> 2;
    const int cq = (lane & 3) * 2;
#pragma unroll
    for (int mt = 0; mt < 4; mt++) {
#pragma unroll
        for (int nt = 0; nt < 4; nt++) {
            int gcol = n0 + wn * 32 + nt * 8 + cq;
            float b0 = bias[gcol], b1 = bias[gcol + 1];
            if (MODE == 1) {
                int sect = gcol >> 10, w = gcol & 1023;
                int hh = w >> 6, dd = w & 63;
                __half* dst = (sect == 0) ? g_q16 : (sect == 1) ? g_k16 : g_v16;
                float sc = (sect == 0) ? QSCALE : 1.0f;
#pragma unroll
                for (int half = 0; half < 2; half++) {
                    int grow = m0 + wm * 64 + mt * 16 + rq + half * 8;
                    float vx = (acc[mt][nt][half * 2 + 0] + b0) * sc;
                    float vy = (acc[mt][nt][half * 2 + 1] + b1) * sc;
                    *(__half2*)&dst[((size_t)hh * SEQ + grow) * HDIM + dd] =
                        __floats2half2_rn(vx, vy);
                }
            } else {
#pragma unroll
                for (int half = 0; half < 2; half++) {
                    int grow = m0 + wm * 64 + mt * 16 + rq + half * 8;
                    float2 v;
                    v.x = acc[mt][nt][half * 2 + 0] + b0;
                    v.y = acc[mt][nt][half * 2 + 1] + b1;
                    *(float2*)&C[(size_t)grow * N + gcol] = v;
                }
            }
        }
    }
}

// ---------------------------------------------------------------------------
// FlashAttention-2, split-KV x2, fp16 Q/K/V, single-fp16 P. 3-stage KV
// pipeline, one __syncthreads per tile. smem 64KB -> 2 CTAs/SM.
// ---------------------------------------------------------------------------
__global__ __launch_bounds__(256, 2) void attn_mma_kernel()
{
    extern __shared__ char smem[];
    const uint32_t sb = smem_u32(smem);
    const int tid = threadIdx.x, lane = tid & 31, wid = tid >> 5;
    const int sp = blockIdx.x;
    const int iq = 31 - (int)blockIdx.y;     // heavy blocks first
    const int h  = blockIdx.z;
    const int jbeg = sp * (iq + 1);
    const int jend = jbeg + iq + 1;

    const uint32_t Qs = sb;                  // 16KB

    auto load_kv = [&](int stg, int j) {
        const uint32_t st = sb + 16384 + (uint32_t)stg * 16384;
#pragma unroll
        for (int a = 0; a < 2; a++) {
            const __half* src = a ? g_v16 : g_k16;
#pragma unroll
            for (int it = 0; it < 2; it++) {
                int id = it * 256 + tid;
                int row = id >> 3, kc = id & 7;
                uint32_t soff = (uint32_t)(row * 128 + ((kc * 16) ^ ((row & 7) << 4)));
                CP16(st + a * 8192 + soff,
                     src + ((size_t)h * SEQ + j * 64 + row) * HDIM + kc * 8);
            }
        }
    };

    {   // group 0: Q + first KV tile; group 1: second KV tile (if any)
#pragma unroll
        for (int it = 0; it < 4; it++) {
            int id = it * 256 + tid;
            int row = id >> 3, kc = id & 7;
            uint32_t soff = (uint32_t)(row * 128 + ((kc * 16) ^ ((row & 7) << 4)));
            CP16(Qs + soff, g_q16 + ((size_t)h * SEQ + iq * 128 + row) * HDIM + kc * 8);
        }
        load_kv(0, jbeg);
        CP_COMMIT();
        if (jbeg + 1 < jend) { load_kv(1, jbeg + 1); CP_COMMIT(); }
    }

    float o[8][4];
#pragma unroll
    for (int nt = 0; nt < 8; nt++)
#pragma unroll
        for (int r = 0; r < 4; r++) o[nt][r] = 0.f;
    float m0 = -1e30f, m1 = -1e30f, l0 = 0.f, l1 = 0.f;
    uint32_t qf[4][4];

    const uint32_t xorterm = (uint32_t)((lane & 7) << 4);
    const uint32_t c_lane  = (uint32_t)((lane >> 4) << 4);
    const int r0g_base = iq * 128 + wid * 16 + (lane >> 2);

    for (int j = jbeg; j < jend; j++) {
        const int jj = j - jbeg;
        if (j + 1 < jend) { CP_WAIT1(); } else { CP_WAIT0(); }
        __syncthreads();
        if (j + 2 < jend) { load_kv((jj + 2) % 3, j + 2); CP_COMMIT(); }

        if (jj == 0) {
            const uint32_t qrow = Qs + (uint32_t)((wid * 16 + (lane & 15)) * 128);
#pragma unroll
            for (int ks = 0; ks < 4; ks++) {
                uint32_t cv = ((uint32_t)(ks * 32) + c_lane) ^ xorterm;
                LDSM4(qf[ks][0], qf[ks][1], qf[ks][2], qf[ks][3], qrow + cv);
            }
        }

        const uint32_t st = sb + 16384 + (uint32_t)(jj % 3) * 16384;
        const uint32_t Ks = st, Vs = st + 8192;

        float s[8][4];
#pragma unroll
        for (int nt = 0; nt < 8; nt++)
#pragma unroll
            for (int r = 0; r < 4; r++) s[nt][r] = 0.f;

#pragma unroll
        for (int ks = 0; ks < 4; ks++) {
            uint32_t cv = ((uint32_t)(ks * 32) + c_lane) ^ xorterm;
#pragma unroll
            for (int bn = 0; bn < 4; bn++) {
                uint32_t kh[4];
                LDSM4(kh[0], kh[1], kh[2], kh[3],
                      Ks + (uint32_t)((bn * 16 + (lane & 15)) * 128) + cv);
#pragma unroll
                for (int sub = 0; sub < 2; sub++)
                    MMAH(s[bn * 2 + sub], qf[ks], kh[sub], kh[sub + 2]);
            }
        }

        if (j >= 2 * iq) {
            int cbase = j * 64 + (lane & 3) * 2;
#pragma unroll
            for (int nt = 0; nt < 8; nt++) {
                int c0 = cbase + nt * 8, c1 = c0 + 1;
                if (c0 > r0g_base)     s[nt][0] = -1e30f;
                if (c1 > r0g_base)     s[nt][1] = -1e30f;
                if (c0 > r0g_base + 8) s[nt][2] = -1e30f;
                if (c1 > r0g_base + 8) s[nt][3] = -1e30f;
            }
        }

        float mx0 = -1e30f, mx1 = -1e30f;
#pragma unroll
        for (int nt = 0; nt < 8; nt++) {
            mx0 = fmaxf(mx0, fmaxf(s[nt][0], s[nt][1]));
            mx1 = fmaxf(mx1, fmaxf(s[nt][2], s[nt][3]));
        }
        mx0 = fmaxf(mx0, __shfl_xor_sync(0xFFFFFFFFu, mx0, 1));
        mx0 = fmaxf(mx0, __shfl_xor_sync(0xFFFFFFFFu, mx0, 2));
        mx1 = fmaxf(mx1, __shfl_xor_sync(0xFFFFFFFFu, mx1, 1));
        mx1 = fmaxf(mx1, __shfl_xor_sync(0xFFFFFFFFu, mx1, 2));
        float mn0 = fmaxf(m0, mx0), mn1 = fmaxf(m1, mx1);
        float al0 = ex2(m0 - mn0), al1 = ex2(m1 - mn1);
        m0 = mn0; m1 = mn1;

        float sum0 = 0.f, sum1 = 0.f;
#pragma unroll
        for (int nt = 0; nt < 8; nt++) {
            s[nt][0] = ex2(s[nt][0] - mn0);
            s[nt][1] = ex2(s[nt][1] - mn0);
            s[nt][2] = ex2(s[nt][2] - mn1);
            s[nt][3] = ex2(s[nt][3] - mn1);
            sum0 += s[nt][0] + s[nt][1];
            sum1 += s[nt][2] + s[nt][3];
        }
        sum0 += __shfl_xor_sync(0xFFFFFFFFu, sum0, 1);
        sum0 += __shfl_xor_sync(0xFFFFFFFFu, sum0, 2);
        sum1 += __shfl_xor_sync(0xFFFFFFFFu, sum1, 1);
        sum1 += __shfl_xor_sync(0xFFFFFFFFu, sum1, 2);
        l0 = l0 * al0 + sum0;
        l1 = l1 * al1 + sum1;

#pragma unroll
        for (int nt = 0; nt < 8; nt++) {
            o[nt][0] *= al0; o[nt][1] *= al0;
            o[nt][2] *= al1; o[nt][3] *= al1;
        }

        // ---- O += P @ V, single fp16 P ----
#pragma unroll
        for (int t = 0; t < 4; t++) {
            uint32_t ap[4];
#pragma unroll
            for (int u = 0; u < 4; u++) {
                int nt = t * 2 + (u >> 1);
                int base = (u & 1) * 2;
                ap[u] = h2u(__floats2half2_rn(s[nt][base], s[nt][base + 1]));
            }
            uint32_t rowoff = (uint32_t)((t * 16 + (lane & 15)) * 128);
#pragma unroll
            for (int g = 0; g < 4; g++) {
                uint32_t cvv = ((uint32_t)(g * 32) + c_lane) ^ xorterm;
                uint32_t vh[4];
                LDSM4T(vh[0], vh[1], vh[2], vh[3], Vs + rowoff + cvv);
                MMAH(o[g * 2],     ap, vh[0], vh[1]);
                MMAH(o[g * 2 + 1], ap, vh[2], vh[3]);
            }
        }
    }

    // ---- write unnormalized partials ----
    float* Op = g_opart + (size_t)sp * SEQ * DMODEL;
    int colb = h * 64 + (lane & 3) * 2;
#pragma unroll
    for (int nt = 0; nt < 8; nt++) {
        int col = colb + nt * 8;
        size_t i0 = (size_t)r0g_base * DMODEL + col;
        size_t i1 = (size_t)(r0g_base + 8) * DMODEL + col;
        float2 v0; v0.x = o[nt][0]; v0.y = o[nt][1];
        float2 v1; v1.x = o[nt][2]; v1.y = o[nt][3];
        *(float2*)&Op[i0] = v0;
        *(float2*)&Op[i1] = v1;
    }
    if ((lane & 3) == 0) {
        size_t base = (size_t)sp * NH * SEQ + (size_t)h * SEQ;
        g_pm[base + r0g_base]     = m0;
        g_pm[base + r0g_base + 8] = m1;
        g_pl[base + r0g_base]     = l0;
        g_pl[base + r0g_base + 8] = l1;
    }
}

// ---------------------------------------------------------------------------
// Combine split-KV partials (exp2 domain) -> single fp16 proj input (g_x16).
// ---------------------------------------------------------------------------
__global__ void combine_kernel()
{
    int idx = blockIdx.x * 256 + threadIdx.x;   // float4 index over SEQ*DMODEL/4
    int row = idx >> 8;                          // 256 float4 per row
    int h   = (idx & 255) >> 4;                  // 16 float4 per head
    size_t mlb = (size_t)h * SEQ + row;
    float m0 = g_pm[mlb], m1 = g_pm[(size_t)NH * SEQ + mlb];
    float l0 = g_pl[mlb], l1 = g_pl[(size_t)NH * SEQ + mlb];
    float ms = fmaxf(m0, m1);
    float w0 = ex2(m0 - ms), w1 = ex2(m1 - ms);
    float inv = 1.0f / (w0 * l0 + w1 * l1);
    w0 *= inv; w1 *= inv;
    float4 a = ((const float4*)g_opart)[idx];
    float4 b = ((const float4*)(g_opart + (size_t)SEQ * DMODEL))[idx];
    __half2* H = (__half2*)g_x16;
    H[2*idx]   = __floats2half2_rn(a.x * w0 + b.x * w1, a.y * w0 + b.y * w1);
    H[2*idx+1] = __floats2half2_rn(a.z * w0 + b.z * w1, a.w * w0 + b.w * w1);
}

// ---------------------------------------------------------------------------
extern "C" void kernel_launch(void* const* d_in, const int* in_sizes, int n_in,
                              void* d_out, int out_size)
{
    const float* X     = (const float*)d_in[0];
    const float* Wqkv  = (const float*)d_in[1];
    const float* bqkv  = (const float*)d_in[2];
    const float* Wproj = (const float*)d_in[3];
    const float* bproj = (const float*)d_in[4];
    float* out = (float*)d_out;

    const int GEMM_SMEM = 3 * 2 * 16384;             // 98304 B, 2 CTAs/SM
    const int ATTN_SMEM = 16384 + 3 * 16384;         // 65536 B, 2 CTAs/SM
    cudaFuncSetAttribute(gemm16<1>, cudaFuncAttributeMaxDynamicSharedMemorySize, GEMM_SMEM);
    cudaFuncSetAttribute(gemm16<0>, cudaFuncAttributeMaxDynamicSharedMemorySize, GEMM_SMEM);
    cudaFuncSetAttribute(attn_mma_kernel, cudaFuncAttributeMaxDynamicSharedMemorySize, ATTN_SMEM);

    // 1) convert operands (all coalesced; no transposes)
    convX_kernel<<<SEQ * DMODEL / 4 / 256, 256>>>(X);
    convW_kernel<1><<<3 * DMODEL * DMODEL / 4 / 256, 256>>>(Wqkv);
    convW_kernel<0><<<DMODEL * DMODEL / 4 / 256, 256>>>(Wproj);

    // 2) QKV GEMM (single fp16, trans-B) -> fp16 q(scaled)/k/v
    gemm16<1><<<dim3(24, 32), 256, GEMM_SMEM>>>(bqkv, nullptr, 3 * DMODEL);

    // 3) split-KV attention + combine -> g_x16 (proj input)
    attn_mma_kernel<<<dim3(KSPLIT, 32, NH), 256, ATTN_SMEM>>>();
    combine_kernel<<<SEQ * DMODEL / 4 / 256, 256>>>();

    // 4) proj GEMM (single fp16, trans-B) -> out
    gemm16<0><<<dim3(8, 32), 256, GEMM_SMEM>>>(bproj, out, DMODEL);
}

// round 12
// speedup vs baseline: 7.6647x; 1.0459x over previous
#include <cuda_runtime.h>
#include <cuda_fp16.h>
#include <cstdint>

#define SEQ  4096
#define DMODEL 1024
#define NH   16
#define HDIM 64
#define KSPLIT 2

// single fp16 A operand: X for QKV GEMM, then combined attention output for proj
__device__ __align__(16) __half g_x16[(long)SEQ * DMODEL];
// single fp16 weights, SAME layout as input: [K][N] (consumed k-major via ldsm.trans)
__device__ __align__(16) __half g_w1[(long)DMODEL * 3 * DMODEL];
__device__ __align__(16) __half g_w2[(long)DMODEL * DMODEL];
// fp16 q/k/v (q pre-scaled by 0.125*log2e), head-major [h][seq][hd]
__device__ __align__(16) __half g_q16[(long)NH * SEQ * HDIM];
__device__ __align__(16) __half g_k16[(long)NH * SEQ * HDIM];
__device__ __align__(16) __half g_v16[(long)NH * SEQ * HDIM];
// split-KV partials: unnormalized O + per-row m,l (exp2 domain)
__device__ __align__(16) float g_opart[(long)KSPLIT * SEQ * DMODEL];
__device__ float g_pm[(long)KSPLIT * NH * SEQ];
__device__ float g_pl[(long)KSPLIT * NH * SEQ];

#define QSCALE 0.18033688f   // 0.125 * log2(e)

// ---------------------------------------------------------------------------
__device__ __forceinline__ uint32_t smem_u32(const void* p) {
    uint32_t a;
    asm("{ .reg .u64 t; cvta.to.shared.u64 t, %1; cvt.u32.u64 %0, t; }" : "=r"(a) : "l"(p));
    return a;
}
__device__ __forceinline__ float ex2(float x) {
    float y; asm("ex2.approx.f32 %0, %1;" : "=f"(y) : "f"(x)); return y;
}
#define CP16(dst, src) \
    asm volatile("cp.async.cg.shared.global [%0], [%1], 16;" :: "r"(dst), "l"(src))
#define CP_COMMIT() asm volatile("cp.async.commit_group;" ::: "memory")
#define CP_WAIT1()  asm volatile("cp.async.wait_group 1;" ::: "memory")
#define CP_WAIT0()  asm volatile("cp.async.wait_group 0;" ::: "memory")

#define LDSM4(r0, r1, r2, r3, addr) \
    asm volatile("ldmatrix.sync.aligned.m8n8.x4.shared.b16 {%0,%1,%2,%3}, [%4];" \
                 : "=r"(r0), "=r"(r1), "=r"(r2), "=r"(r3) : "r"(addr))
#define LDSM4T(r0, r1, r2, r3, addr) \
    asm volatile("ldmatrix.sync.aligned.m8n8.x4.trans.shared.b16 {%0,%1,%2,%3}, [%4];" \
                 : "=r"(r0), "=r"(r1), "=r"(r2), "=r"(r3) : "r"(addr))

#define MMAH(c, a, b0, b1) \
    asm volatile("mma.sync.aligned.m16n8k16.row.col.f32.f16.f16.f32 " \
                 "{%0,%1,%2,%3}, {%4,%5,%6,%7}, {%8,%9}, {%0,%1,%2,%3};" \
                 : "+f"((c)[0]), "+f"((c)[1]), "+f"((c)[2]), "+f"((c)[3]) \
                 : "r"((a)[0]), "r"((a)[1]), "r"((a)[2]), "r"((a)[3]), \
                   "r"(b0), "r"(b1))

__device__ __forceinline__ uint32_t h2u(__half2 h) { return *(uint32_t*)&h; }

// ---------------------------------------------------------------------------
// Conversion kernels (coalesced, no transposes)
// ---------------------------------------------------------------------------
__global__ void convX_kernel(const float* __restrict__ A) {
    int i = blockIdx.x * 256 + threadIdx.x;        // float4 index
    float4 v = ((const float4*)A)[i];
    __half2* H = (__half2*)g_x16;
    H[2*i]   = __floats2half2_rn(v.x, v.y);
    H[2*i+1] = __floats2half2_rn(v.z, v.w);
}

template <int WSEL>
__global__ void convW_kernel(const float* __restrict__ W) {
    __half* T = WSEL ? g_w1 : g_w2;
    int i = blockIdx.x * 256 + threadIdx.x;
    float4 v = ((const float4*)W)[i];
    __half2* H = (__half2*)T;
    H[2*i]   = __floats2half2_rn(v.x, v.y);
    H[2*i+1] = __floats2half2_rn(v.z, v.w);
}

// ---------------------------------------------------------------------------
// Single-fp16 GEMM, 128 threads / 4 warps, warp tile 64x64 (2x2 warps).
// A [M][K] row-major; B [K][N] k-major via ldmatrix.trans.
// CTA 128x128, K-chunk 64, 3-stage cp.async (96KB) -> 2 CTAs/SM.
// MODE 1: epilogue -> fp16 q(scaled)/k/v. MODE 0: fp32 C + bias.
// ---------------------------------------------------------------------------
template <int MODE>
__global__ __launch_bounds__(128, 2) void gemm16(
    const float* __restrict__ bias, float* __restrict__ C, int N)
{
    const __half* __restrict__ B = MODE ? g_w1 : g_w2;
    const int K = DMODEL;
    extern __shared__ char smem[];                  // 3 stages x (A 16KB + B 16KB)
    const uint32_t sb = smem_u32(smem);
    const int tid  = threadIdx.x;
    const int lane = tid & 31;
    const int wid  = tid >> 5;            // 0..3
    const int wm   = wid >> 1;            // 0..1
    const int wn   = wid & 1;             // 0..1
    const int n0 = blockIdx.x * 128, m0 = blockIdx.y * 128;

    float acc[4][8][4];
#pragma unroll
    for (int mt = 0; mt < 4; mt++)
#pragma unroll
        for (int nt = 0; nt < 8; nt++)
#pragma unroll
            for (int r = 0; r < 4; r++) acc[mt][nt][r] = 0.f;

    auto load_stage = [&](int stg, int ck) {
        const uint32_t st = sb + (uint32_t)stg * 32768;
        const int k0 = ck * 64;
        // A: 128 rows x 64 k (128B rows, swizzle on 8-row period)
#pragma unroll
        for (int it = 0; it < 8; it++) {
            int id  = it * 128 + tid;
            int row = id >> 3, kc = id & 7;
            const void* g = g_x16 + (size_t)(m0 + row) * K + k0 + kc * 8;
            uint32_t soff = (uint32_t)(row * 128 + ((kc * 16) ^ ((row & 7) << 4)));
            CP16(st + soff, g);
        }
        // B: 64 k-rows x 128 n (256B rows, swizzle on 16-row period)
#pragma unroll
        for (int it = 0; it < 8; it++) {
            int id  = it * 128 + tid;
            int row = id >> 4, c16 = id & 15;
            const void* g = B + (size_t)(k0 + row) * N + n0 + c16 * 8;
            uint32_t soff = (uint32_t)(row * 256 + ((c16 * 16) ^ ((row & 15) << 4)));
            CP16(st + 16384 + soff, g);
        }
    };

    const int NC = K / 64;                 // 16
    load_stage(0, 0); CP_COMMIT();
    load_stage(1, 1); CP_COMMIT();

    const int r_lane = lane & 15;
    const int c_lane = (lane >> 4) << 4;   // bytes
    const uint32_t xorA = (uint32_t)((r_lane & 7) << 4);
    const uint32_t xorB = (uint32_t)(r_lane << 4);
    const uint32_t colB = (uint32_t)(wn * 128 + c_lane);   // byte offset of warp's 64 cols

    for (int c = 0; c < NC; c++) {
        if (c + 1 < NC) { CP_WAIT1(); } else { CP_WAIT0(); }
        __syncthreads();
        if (c + 2 < NC) { load_stage((c + 2) % 3, c + 2); CP_COMMIT(); }

        const uint32_t st = sb + (uint32_t)(c % 3) * 32768;
        const uint32_t aA = st +         (uint32_t)((wm * 64 + r_lane) * 128);
        const uint32_t rB = st + 16384 + (uint32_t)(r_lane * 256);

#pragma unroll
        for (int ks = 0; ks < 4; ks++) {
            const uint32_t cvA = ((uint32_t)(ks * 32 + c_lane)) ^ xorA;
            uint32_t ah[4][4], bh[4][4];
#pragma unroll
            for (int mt = 0; mt < 4; mt++)
                LDSM4(ah[mt][0], ah[mt][1], ah[mt][2], ah[mt][3], aA + mt * 2048 + cvA);
#pragma unroll
            for (int bn = 0; bn < 4; bn++)
                LDSM4T(bh[bn][0], bh[bn][1], bh[bn][2], bh[bn][3],
                       rB + ks * 4096 + ((colB + bn * 32) ^ xorB));
#pragma unroll
            for (int mt = 0; mt < 4; mt++)
#pragma unroll
                for (int nt = 0; nt < 8; nt++) {
                    int bn = nt >> 1, sub = nt & 1;
                    MMAH(acc[mt][nt], ah[mt], bh[bn][sub * 2], bh[bn][sub * 2 + 1]);
                }
        }
    }

    const int rq = lane >> 2;
    const int cq = (lane & 3) * 2;
#pragma unroll
    for (int mt = 0; mt < 4; mt++) {
#pragma unroll
        for (int nt = 0; nt < 8; nt++) {
            int gcol = n0 + wn * 64 + nt * 8 + cq;
            float b0 = bias[gcol], b1 = bias[gcol + 1];
            if (MODE == 1) {
                int sect = gcol >> 10, w = gcol & 1023;
                int hh = w >> 6, dd = w & 63;
                __half* dst = (sect == 0) ? g_q16 : (sect == 1) ? g_k16 : g_v16;
                float sc = (sect == 0) ? QSCALE : 1.0f;
#pragma unroll
                for (int half = 0; half < 2; half++) {
                    int grow = m0 + wm * 64 + mt * 16 + rq + half * 8;
                    float vx = (acc[mt][nt][half * 2 + 0] + b0) * sc;
                    float vy = (acc[mt][nt][half * 2 + 1] + b1) * sc;
                    *(__half2*)&dst[((size_t)hh * SEQ + grow) * HDIM + dd] =
                        __floats2half2_rn(vx, vy);
                }
            } else {
#pragma unroll
                for (int half = 0; half < 2; half++) {
                    int grow = m0 + wm * 64 + mt * 16 + rq + half * 8;
                    float2 v;
                    v.x = acc[mt][nt][half * 2 + 0] + b0;
                    v.y = acc[mt][nt][half * 2 + 1] + b1;
                    *(float2*)&C[(size_t)grow * N + gcol] = v;
                }
            }
        }
    }
}

// ---------------------------------------------------------------------------
// FlashAttention-2, split-KV x2, 128 threads / 4 warps x 32 query rows
// (2 m-subtiles per warp; K/V fragments reused across both). 3-stage KV
// pipeline, one __syncthreads per tile. smem 64KB -> 2 CTAs/SM.
// ---------------------------------------------------------------------------
__global__ __launch_bounds__(128, 2) void attn_mma_kernel()
{
    extern __shared__ char smem[];
    const uint32_t sb = smem_u32(smem);
    const int tid = threadIdx.x, lane = tid & 31, wid = tid >> 5;   // wid 0..3
    const int sp = blockIdx.x;
    const int iq = 31 - (int)blockIdx.y;     // heavy blocks first
    const int h  = blockIdx.z;
    const int jbeg = sp * (iq + 1);
    const int jend = jbeg + iq + 1;

    const uint32_t Qs = sb;                  // 16KB

    auto load_kv = [&](int stg, int j) {
        const uint32_t st = sb + 16384 + (uint32_t)stg * 16384;
#pragma unroll
        for (int a = 0; a < 2; a++) {
            const __half* src = a ? g_v16 : g_k16;
#pragma unroll
            for (int it = 0; it < 4; it++) {
                int id = it * 128 + tid;
                int row = id >> 3, kc = id & 7;
                uint32_t soff = (uint32_t)(row * 128 + ((kc * 16) ^ ((row & 7) << 4)));
                CP16(st + a * 8192 + soff,
                     src + ((size_t)h * SEQ + j * 64 + row) * HDIM + kc * 8);
            }
        }
    };

    {
#pragma unroll
        for (int it = 0; it < 8; it++) {
            int id = it * 128 + tid;
            int row = id >> 3, kc = id & 7;
            uint32_t soff = (uint32_t)(row * 128 + ((kc * 16) ^ ((row & 7) << 4)));
            CP16(Qs + soff, g_q16 + ((size_t)h * SEQ + iq * 128 + row) * HDIM + kc * 8);
        }
        load_kv(0, jbeg);
        CP_COMMIT();
        if (jbeg + 1 < jend) { load_kv(1, jbeg + 1); CP_COMMIT(); }
    }

    float o[2][8][4];
#pragma unroll
    for (int mt = 0; mt < 2; mt++)
#pragma unroll
        for (int nt = 0; nt < 8; nt++)
#pragma unroll
            for (int r = 0; r < 4; r++) o[mt][nt][r] = 0.f;
    float mst[2][2], lst[2][2];
#pragma unroll
    for (int mt = 0; mt < 2; mt++) { mst[mt][0] = mst[mt][1] = -1e30f;
                                     lst[mt][0] = lst[mt][1] = 0.f; }
    uint32_t qf[2][4][4];

    const uint32_t xorterm = (uint32_t)((lane & 7) << 4);
    const uint32_t c_lane  = (uint32_t)((lane >> 4) << 4);
    int r0g[2];
#pragma unroll
    for (int mt = 0; mt < 2; mt++)
        r0g[mt] = iq * 128 + wid * 32 + mt * 16 + (lane >> 2);

    for (int j = jbeg; j < jend; j++) {
        const int jj = j - jbeg;
        if (j + 1 < jend) { CP_WAIT1(); } else { CP_WAIT0(); }
        __syncthreads();
        if (j + 2 < jend) { load_kv((jj + 2) % 3, j + 2); CP_COMMIT(); }

        if (jj == 0) {
#pragma unroll
            for (int mt = 0; mt < 2; mt++) {
                const uint32_t qrow = Qs +
                    (uint32_t)((wid * 32 + mt * 16 + (lane & 15)) * 128);
#pragma unroll
                for (int ks = 0; ks < 4; ks++) {
                    uint32_t cv = ((uint32_t)(ks * 32) + c_lane) ^ xorterm;
                    LDSM4(qf[mt][ks][0], qf[mt][ks][1], qf[mt][ks][2], qf[mt][ks][3],
                          qrow + cv);
                }
            }
        }

        const uint32_t st = sb + 16384 + (uint32_t)(jj % 3) * 16384;
        const uint32_t Ks = st, Vs = st + 8192;

        // ---- S = Q @ K^T for both m-subtiles (K fragments loaded once) ----
        float s[2][8][4];
#pragma unroll
        for (int mt = 0; mt < 2; mt++)
#pragma unroll
            for (int nt = 0; nt < 8; nt++)
#pragma unroll
                for (int r = 0; r < 4; r++) s[mt][nt][r] = 0.f;

#pragma unroll
        for (int ks = 0; ks < 4; ks++) {
            uint32_t cv = ((uint32_t)(ks * 32) + c_lane) ^ xorterm;
#pragma unroll
            for (int bn = 0; bn < 4; bn++) {
                uint32_t kh[4];
                LDSM4(kh[0], kh[1], kh[2], kh[3],
                      Ks + (uint32_t)((bn * 16 + (lane & 15)) * 128) + cv);
#pragma unroll
                for (int mt = 0; mt < 2; mt++)
#pragma unroll
                    for (int sub = 0; sub < 2; sub++)
                        MMAH(s[mt][bn * 2 + sub], qf[mt][ks], kh[sub], kh[sub + 2]);
            }
        }

        // ---- causal mask ----
        if (j >= 2 * iq) {
            int cbase = j * 64 + (lane & 3) * 2;
#pragma unroll
            for (int mt = 0; mt < 2; mt++)
#pragma unroll
                for (int nt = 0; nt < 8; nt++) {
                    int c0 = cbase + nt * 8, c1 = c0 + 1;
                    if (c0 > r0g[mt])     s[mt][nt][0] = -1e30f;
                    if (c1 > r0g[mt])     s[mt][nt][1] = -1e30f;
                    if (c0 > r0g[mt] + 8) s[mt][nt][2] = -1e30f;
                    if (c1 > r0g[mt] + 8) s[mt][nt][3] = -1e30f;
                }
        }

        // ---- online softmax per m-subtile (exp2 domain) ----
#pragma unroll
        for (int mt = 0; mt < 2; mt++) {
            float mx0 = -1e30f, mx1 = -1e30f;
#pragma unroll
            for (int nt = 0; nt < 8; nt++) {
                mx0 = fmaxf(mx0, fmaxf(s[mt][nt][0], s[mt][nt][1]));
                mx1 = fmaxf(mx1, fmaxf(s[mt][nt][2], s[mt][nt][3]));
            }
            mx0 = fmaxf(mx0, __shfl_xor_sync(0xFFFFFFFFu, mx0, 1));
            mx0 = fmaxf(mx0, __shfl_xor_sync(0xFFFFFFFFu, mx0, 2));
            mx1 = fmaxf(mx1, __shfl_xor_sync(0xFFFFFFFFu, mx1, 1));
            mx1 = fmaxf(mx1, __shfl_xor_sync(0xFFFFFFFFu, mx1, 2));
            float mn0 = fmaxf(mst[mt][0], mx0), mn1 = fmaxf(mst[mt][1], mx1);
            float al0 = ex2(mst[mt][0] - mn0), al1 = ex2(mst[mt][1] - mn1);
            mst[mt][0] = mn0; mst[mt][1] = mn1;

            float sum0 = 0.f, sum1 = 0.f;
#pragma unroll
            for (int nt = 0; nt < 8; nt++) {
                s[mt][nt][0] = ex2(s[mt][nt][0] - mn0);
                s[mt][nt][1] = ex2(s[mt][nt][1] - mn0);
                s[mt][nt][2] = ex2(s[mt][nt][2] - mn1);
                s[mt][nt][3] = ex2(s[mt][nt][3] - mn1);
                sum0 += s[mt][nt][0] + s[mt][nt][1];
                sum1 += s[mt][nt][2] + s[mt][nt][3];
            }
            sum0 += __shfl_xor_sync(0xFFFFFFFFu, sum0, 1);
            sum0 += __shfl_xor_sync(0xFFFFFFFFu, sum0, 2);
            sum1 += __shfl_xor_sync(0xFFFFFFFFu, sum1, 1);
            sum1 += __shfl_xor_sync(0xFFFFFFFFu, sum1, 2);
            lst[mt][0] = lst[mt][0] * al0 + sum0;
            lst[mt][1] = lst[mt][1] * al1 + sum1;

#pragma unroll
            for (int nt = 0; nt < 8; nt++) {
                o[mt][nt][0] *= al0; o[mt][nt][1] *= al0;
                o[mt][nt][2] *= al1; o[mt][nt][3] *= al1;
            }
        }

        // ---- O += P @ V (V fragments loaded once, used by both subtiles) ----
#pragma unroll
        for (int t = 0; t < 4; t++) {
            uint32_t ap[2][4];
#pragma unroll
            for (int mt = 0; mt < 2; mt++)
#pragma unroll
                for (int u = 0; u < 4; u++) {
                    int nt = t * 2 + (u >> 1);
                    int base = (u & 1) * 2;
                    ap[mt][u] = h2u(__floats2half2_rn(s[mt][nt][base],
                                                      s[mt][nt][base + 1]));
                }
            uint32_t rowoff = (uint32_t)((t * 16 + (lane & 15)) * 128);
#pragma unroll
            for (int g = 0; g < 4; g++) {
                uint32_t cvv = ((uint32_t)(g * 32) + c_lane) ^ xorterm;
                uint32_t vh[4];
                LDSM4T(vh[0], vh[1], vh[2], vh[3], Vs + rowoff + cvv);
#pragma unroll
                for (int mt = 0; mt < 2; mt++) {
                    MMAH(o[mt][g * 2],     ap[mt], vh[0], vh[1]);
                    MMAH(o[mt][g * 2 + 1], ap[mt], vh[2], vh[3]);
                }
            }
        }
    }

    // ---- write unnormalized partials ----
    float* Op = g_opart + (size_t)sp * SEQ * DMODEL;
    int colb = h * 64 + (lane & 3) * 2;
#pragma unroll
    for (int mt = 0; mt < 2; mt++) {
#pragma unroll
        for (int nt = 0; nt < 8; nt++) {
            int col = colb + nt * 8;
            size_t i0 = (size_t)r0g[mt] * DMODEL + col;
            size_t i1 = (size_t)(r0g[mt] + 8) * DMODEL + col;
            float2 v0; v0.x = o[mt][nt][0]; v0.y = o[mt][nt][1];
            float2 v1; v1.x = o[mt][nt][2]; v1.y = o[mt][nt][3];
            *(float2*)&Op[i0] = v0;
            *(float2*)&Op[i1] = v1;
        }
        if ((lane & 3) == 0) {
            size_t base = (size_t)sp * NH * SEQ + (size_t)h * SEQ;
            g_pm[base + r0g[mt]]     = mst[mt][0];
            g_pm[base + r0g[mt] + 8] = mst[mt][1];
            g_pl[base + r0g[mt]]     = lst[mt][0];
            g_pl[base + r0g[mt] + 8] = lst[mt][1];
        }
    }
}

// ---------------------------------------------------------------------------
// Combine split-KV partials (exp2 domain) -> single fp16 proj input (g_x16).
// ---------------------------------------------------------------------------
__global__ void combine_kernel()
{
    int idx = blockIdx.x * 256 + threadIdx.x;   // float4 index over SEQ*DMODEL/4
    int row = idx >> 8;                          // 256 float4 per row
    int h   = (idx & 255) >> 4;                  // 16 float4 per head
    size_t mlb = (size_t)h * SEQ + row;
    float m0 = g_pm[mlb], m1 = g_pm[(size_t)NH * SEQ + mlb];
    float l0 = g_pl[mlb], l1 = g_pl[(size_t)NH * SEQ + mlb];
    float ms = fmaxf(m0, m1);
    float w0 = ex2(m0 - ms), w1 = ex2(m1 - ms);
    float inv = 1.0f / (w0 * l0 + w1 * l1);
    w0 *= inv; w1 *= inv;
    float4 a = ((const float4*)g_opart)[idx];
    float4 b = ((const float4*)(g_opart + (size_t)SEQ * DMODEL))[idx];
    __half2* H = (__half2*)g_x16;
    H[2*idx]   = __floats2half2_rn(a.x * w0 + b.x * w1, a.y * w0 + b.y * w1);
    H[2*idx+1] = __floats2half2_rn(a.z * w0 + b.z * w1, a.w * w0 + b.w * w1);
}

// ---------------------------------------------------------------------------
extern "C" void kernel_launch(void* const* d_in, const int* in_sizes, int n_in,
                              void* d_out, int out_size)
{
    const float* X     = (const float*)d_in[0];
    const float* Wqkv  = (const float*)d_in[1];
    const float* bqkv  = (const float*)d_in[2];
    const float* Wproj = (const float*)d_in[3];
    const float* bproj = (const float*)d_in[4];
    float* out = (float*)d_out;

    const int GEMM_SMEM = 3 * 2 * 16384;             // 98304 B, 2 CTAs/SM
    const int ATTN_SMEM = 16384 + 3 * 16384;         // 65536 B, 2 CTAs/SM
    cudaFuncSetAttribute(gemm16<1>, cudaFuncAttributeMaxDynamicSharedMemorySize, GEMM_SMEM);
    cudaFuncSetAttribute(gemm16<0>, cudaFuncAttributeMaxDynamicSharedMemorySize, GEMM_SMEM);
    cudaFuncSetAttribute(attn_mma_kernel, cudaFuncAttributeMaxDynamicSharedMemorySize, ATTN_SMEM);

    // 1) convert operands
    convX_kernel<<<SEQ * DMODEL / 4 / 256, 256>>>(X);
    convW_kernel<1><<<3 * DMODEL * DMODEL / 4 / 256, 256>>>(Wqkv);
    convW_kernel<0><<<DMODEL * DMODEL / 4 / 256, 256>>>(Wproj);

    // 2) QKV GEMM (single fp16, 64x64 warp tiles) -> fp16 q(scaled)/k/v
    gemm16<1><<<dim3(24, 32), 128, GEMM_SMEM>>>(bqkv, nullptr, 3 * DMODEL);

    // 3) split-KV attention (32-row warps) + combine -> g_x16
    attn_mma_kernel<<<dim3(KSPLIT, 32, NH), 128, ATTN_SMEM>>>();
    combine_kernel<<<SEQ * DMODEL / 4 / 256, 256>>>();

    // 4) proj GEMM (single fp16) -> out
    gemm16<0><<<dim3(8, 32), 128, GEMM_SMEM>>>(bproj, out, DMODEL);
}

// round 13
// speedup vs baseline: 7.8619x; 1.0257x over previous
#include <cuda_runtime.h>
#include <cuda_fp16.h>
#include <cstdint>

#define SEQ  4096
#define DMODEL 1024
#define NH   16
#define HDIM 64
#define KSPLIT 2

// single fp16 A operand: X for QKV GEMM, then combined attention output for proj
__device__ __align__(16) __half g_x16[(long)SEQ * DMODEL];
// single fp16 weights, SAME layout as input: [K][N] (consumed k-major via ldsm.trans)
__device__ __align__(16) __half g_w1[(long)DMODEL * 3 * DMODEL];
__device__ __align__(16) __half g_w2[(long)DMODEL * DMODEL];
// fp16 q/k/v (q pre-scaled by 0.125*log2e), head-major [h][seq][hd]
__device__ __align__(16) __half g_q16[(long)NH * SEQ * HDIM];
__device__ __align__(16) __half g_k16[(long)NH * SEQ * HDIM];
__device__ __align__(16) __half g_v16[(long)NH * SEQ * HDIM];
// split-KV partials: unnormalized O (fp16) + per-row m,l (fp32, exp2 domain)
__device__ __align__(16) __half g_opart[(long)KSPLIT * SEQ * DMODEL];
__device__ float g_pm[(long)KSPLIT * NH * SEQ];
__device__ float g_pl[(long)KSPLIT * NH * SEQ];

#define QSCALE 0.18033688f   // 0.125 * log2(e)

// ---------------------------------------------------------------------------
__device__ __forceinline__ uint32_t smem_u32(const void* p) {
    uint32_t a;
    asm("{ .reg .u64 t; cvta.to.shared.u64 t, %1; cvt.u32.u64 %0, t; }" : "=r"(a) : "l"(p));
    return a;
}
__device__ __forceinline__ float ex2(float x) {
    float y; asm("ex2.approx.f32 %0, %1;" : "=f"(y) : "f"(x)); return y;
}
#define CP16(dst, src) \
    asm volatile("cp.async.cg.shared.global [%0], [%1], 16;" :: "r"(dst), "l"(src))
#define CP_COMMIT() asm volatile("cp.async.commit_group;" ::: "memory")
#define CP_WAIT1()  asm volatile("cp.async.wait_group 1;" ::: "memory")
#define CP_WAIT0()  asm volatile("cp.async.wait_group 0;" ::: "memory")

#define LDSM4(r0, r1, r2, r3, addr) \
    asm volatile("ldmatrix.sync.aligned.m8n8.x4.shared.b16 {%0,%1,%2,%3}, [%4];" \
                 : "=r"(r0), "=r"(r1), "=r"(r2), "=r"(r3) : "r"(addr))
#define LDSM4T(r0, r1, r2, r3, addr) \
    asm volatile("ldmatrix.sync.aligned.m8n8.x4.trans.shared.b16 {%0,%1,%2,%3}, [%4];" \
                 : "=r"(r0), "=r"(r1), "=r"(r2), "=r"(r3) : "r"(addr))

#define MMAH(c, a, b0, b1) \
    asm volatile("mma.sync.aligned.m16n8k16.row.col.f32.f16.f16.f32 " \
                 "{%0,%1,%2,%3}, {%4,%5,%6,%7}, {%8,%9}, {%0,%1,%2,%3};" \
                 : "+f"((c)[0]), "+f"((c)[1]), "+f"((c)[2]), "+f"((c)[3]) \
                 : "r"((a)[0]), "r"((a)[1]), "r"((a)[2]), "r"((a)[3]), \
                   "r"(b0), "r"(b1))

__device__ __forceinline__ uint32_t h2u(__half2 h) { return *(uint32_t*)&h; }

// ---------------------------------------------------------------------------
// Fused conversion kernel: X -> g_x16, Wqkv -> g_w1, Wproj -> g_w2.
// One grid; block index selects source. All coalesced float4 -> half2 pairs.
// Block ranges (float4 units, 256/block): X 4096, W1 3072, W2 1024 blocks.
// ---------------------------------------------------------------------------
__global__ void conv_all_kernel(const float* __restrict__ X,
                                const float* __restrict__ W1,
                                const float* __restrict__ W2) {
    int b = blockIdx.x;
    const float* src;
    __half* dst;
    int j;   // float4 index within the selected array
    if (b < 4096)      { src = X;  dst = g_x16; j = b * 256 + threadIdx.x; }
    else if (b < 7168) { src = W1; dst = g_w1;  j = (b - 4096) * 256 + threadIdx.x; }
    else               { src = W2; dst = g_w2;  j = (b - 7168) * 256 + threadIdx.x; }
    float4 v = ((const float4*)src)[j];
    __half2* H = (__half2*)dst;
    H[2*j]   = __floats2half2_rn(v.x, v.y);
    H[2*j+1] = __floats2half2_rn(v.z, v.w);
}

// ---------------------------------------------------------------------------
// Single-fp16 GEMM, 128 threads / 4 warps, warp tile 64x64 (2x2 warps).
// A [M][K] row-major; B [K][N] k-major via ldmatrix.trans.
// CTA 128x128, K-chunk 64, 3-stage cp.async (96KB) -> 2 CTAs/SM.
// MODE 1: epilogue -> fp16 q(scaled)/k/v. MODE 0: fp32 C + bias.
// ---------------------------------------------------------------------------
template <int MODE>
__global__ __launch_bounds__(128, 2) void gemm16(
    const float* __restrict__ bias, float* __restrict__ C, int N)
{
    const __half* __restrict__ B = MODE ? g_w1 : g_w2;
    const int K = DMODEL;
    extern __shared__ char smem[];                  // 3 stages x (A 16KB + B 16KB)
    const uint32_t sb = smem_u32(smem);
    const int tid  = threadIdx.x;
    const int lane = tid & 31;
    const int wid  = tid >> 5;            // 0..3
    const int wm   = wid >> 1;            // 0..1
    const int wn   = wid & 1;             // 0..1
    const int n0 = blockIdx.x * 128, m0 = blockIdx.y * 128;

    float acc[4][8][4];
#pragma unroll
    for (int mt = 0; mt < 4; mt++)
#pragma unroll
        for (int nt = 0; nt < 8; nt++)
#pragma unroll
            for (int r = 0; r < 4; r++) acc[mt][nt][r] = 0.f;

    auto load_stage = [&](int stg, int ck) {
        const uint32_t st = sb + (uint32_t)stg * 32768;
        const int k0 = ck * 64;
#pragma unroll
        for (int it = 0; it < 8; it++) {
            int id  = it * 128 + tid;
            int row = id >> 3, kc = id & 7;
            const void* g = g_x16 + (size_t)(m0 + row) * K + k0 + kc * 8;
            uint32_t soff = (uint32_t)(row * 128 + ((kc * 16) ^ ((row & 7) << 4)));
            CP16(st + soff, g);
        }
#pragma unroll
        for (int it = 0; it < 8; it++) {
            int id  = it * 128 + tid;
            int row = id >> 4, c16 = id & 15;
            const void* g = B + (size_t)(k0 + row) * N + n0 + c16 * 8;
            uint32_t soff = (uint32_t)(row * 256 + ((c16 * 16) ^ ((row & 15) << 4)));
            CP16(st + 16384 + soff, g);
        }
    };

    const int NC = K / 64;                 // 16
    load_stage(0, 0); CP_COMMIT();
    load_stage(1, 1); CP_COMMIT();

    const int r_lane = lane & 15;
    const int c_lane = (lane >> 4) << 4;   // bytes
    const uint32_t xorA = (uint32_t)((r_lane & 7) << 4);
    const uint32_t xorB = (uint32_t)(r_lane << 4);
    const uint32_t colB = (uint32_t)(wn * 128 + c_lane);

    for (int c = 0; c < NC; c++) {
        if (c + 1 < NC) { CP_WAIT1(); } else { CP_WAIT0(); }
        __syncthreads();
        if (c + 2 < NC) { load_stage((c + 2) % 3, c + 2); CP_COMMIT(); }

        const uint32_t st = sb + (uint32_t)(c % 3) * 32768;
        const uint32_t aA = st +         (uint32_t)((wm * 64 + r_lane) * 128);
        const uint32_t rB = st + 16384 + (uint32_t)(r_lane * 256);

#pragma unroll
        for (int ks = 0; ks < 4; ks++) {
            const uint32_t cvA = ((uint32_t)(ks * 32 + c_lane)) ^ xorA;
            uint32_t ah[4][4], bh[4][4];
#pragma unroll
            for (int mt = 0; mt < 4; mt++)
                LDSM4(ah[mt][0], ah[mt][1], ah[mt][2], ah[mt][3], aA + mt * 2048 + cvA);
#pragma unroll
            for (int bn = 0; bn < 4; bn++)
                LDSM4T(bh[bn][0], bh[bn][1], bh[bn][2], bh[bn][3],
                       rB + ks * 4096 + ((colB + bn * 32) ^ xorB));
#pragma unroll
            for (int mt = 0; mt < 4; mt++)
#pragma unroll
                for (int nt = 0; nt < 8; nt++) {
                    int bn = nt >> 1, sub = nt & 1;
                    MMAH(acc[mt][nt], ah[mt], bh[bn][sub * 2], bh[bn][sub * 2 + 1]);
                }
        }
    }

    const int rq = lane >> 2;
    const int cq = (lane & 3) * 2;
#pragma unroll
    for (int mt = 0; mt < 4; mt++) {
#pragma unroll
        for (int nt = 0; nt < 8; nt++) {
            int gcol = n0 + wn * 64 + nt * 8 + cq;
            float b0 = bias[gcol], b1 = bias[gcol + 1];
            if (MODE == 1) {
                int sect = gcol >> 10, w = gcol & 1023;
                int hh = w >> 6, dd = w & 63;
                __half* dst = (sect == 0) ? g_q16 : (sect == 1) ? g_k16 : g_v16;
                float sc = (sect == 0) ? QSCALE : 1.0f;
#pragma unroll
                for (int half = 0; half < 2; half++) {
                    int grow = m0 + wm * 64 + mt * 16 + rq + half * 8;
                    float vx = (acc[mt][nt][half * 2 + 0] + b0) * sc;
                    float vy = (acc[mt][nt][half * 2 + 1] + b1) * sc;
                    *(__half2*)&dst[((size_t)hh * SEQ + grow) * HDIM + dd] =
                        __floats2half2_rn(vx, vy);
                }
            } else {
#pragma unroll
                for (int half = 0; half < 2; half++) {
                    int grow = m0 + wm * 64 + mt * 16 + rq + half * 8;
                    float2 v;
                    v.x = acc[mt][nt][half * 2 + 0] + b0;
                    v.y = acc[mt][nt][half * 2 + 1] + b1;
                    *(float2*)&C[(size_t)grow * N + gcol] = v;
                }
            }
        }
    }
}

// ---------------------------------------------------------------------------
// FlashAttention-2, split-KV x2, 128 threads / 4 warps x 32 query rows.
// fp16 partial O writes. 3-stage KV pipeline, one __syncthreads per tile.
// ---------------------------------------------------------------------------
__global__ __launch_bounds__(128, 2) void attn_mma_kernel()
{
    extern __shared__ char smem[];
    const uint32_t sb = smem_u32(smem);
    const int tid = threadIdx.x, lane = tid & 31, wid = tid >> 5;   // wid 0..3
    const int sp = blockIdx.x;
    const int iq = 31 - (int)blockIdx.y;     // heavy blocks first
    const int h  = blockIdx.z;
    const int jbeg = sp * (iq + 1);
    const int jend = jbeg + iq + 1;

    const uint32_t Qs = sb;                  // 16KB

    auto load_kv = [&](int stg, int j) {
        const uint32_t st = sb + 16384 + (uint32_t)stg * 16384;
#pragma unroll
        for (int a = 0; a < 2; a++) {
            const __half* src = a ? g_v16 : g_k16;
#pragma unroll
            for (int it = 0; it < 4; it++) {
                int id = it * 128 + tid;
                int row = id >> 3, kc = id & 7;
                uint32_t soff = (uint32_t)(row * 128 + ((kc * 16) ^ ((row & 7) << 4)));
                CP16(st + a * 8192 + soff,
                     src + ((size_t)h * SEQ + j * 64 + row) * HDIM + kc * 8);
            }
        }
    };

    {
#pragma unroll
        for (int it = 0; it < 8; it++) {
            int id = it * 128 + tid;
            int row = id >> 3, kc = id & 7;
            uint32_t soff = (uint32_t)(row * 128 + ((kc * 16) ^ ((row & 7) << 4)));
            CP16(Qs + soff, g_q16 + ((size_t)h * SEQ + iq * 128 + row) * HDIM + kc * 8);
        }
        load_kv(0, jbeg);
        CP_COMMIT();
        if (jbeg + 1 < jend) { load_kv(1, jbeg + 1); CP_COMMIT(); }
    }

    float o[2][8][4];
#pragma unroll
    for (int mt = 0; mt < 2; mt++)
#pragma unroll
        for (int nt = 0; nt < 8; nt++)
#pragma unroll
            for (int r = 0; r < 4; r++) o[mt][nt][r] = 0.f;
    float mst[2][2], lst[2][2];
#pragma unroll
    for (int mt = 0; mt < 2; mt++) { mst[mt][0] = mst[mt][1] = -1e30f;
                                     lst[mt][0] = lst[mt][1] = 0.f; }
    uint32_t qf[2][4][4];

    const uint32_t xorterm = (uint32_t)((lane & 7) << 4);
    const uint32_t c_lane  = (uint32_t)((lane >> 4) << 4);
    int r0g[2];
#pragma unroll
    for (int mt = 0; mt < 2; mt++)
        r0g[mt] = iq * 128 + wid * 32 + mt * 16 + (lane >> 2);

    for (int j = jbeg; j < jend; j++) {
        const int jj = j - jbeg;
        if (j + 1 < jend) { CP_WAIT1(); } else { CP_WAIT0(); }
        __syncthreads();
        if (j + 2 < jend) { load_kv((jj + 2) % 3, j + 2); CP_COMMIT(); }

        if (jj == 0) {
#pragma unroll
            for (int mt = 0; mt < 2; mt++) {
                const uint32_t qrow = Qs +
                    (uint32_t)((wid * 32 + mt * 16 + (lane & 15)) * 128);
#pragma unroll
                for (int ks = 0; ks < 4; ks++) {
                    uint32_t cv = ((uint32_t)(ks * 32) + c_lane) ^ xorterm;
                    LDSM4(qf[mt][ks][0], qf[mt][ks][1], qf[mt][ks][2], qf[mt][ks][3],
                          qrow + cv);
                }
            }
        }

        const uint32_t st = sb + 16384 + (uint32_t)(jj % 3) * 16384;
        const uint32_t Ks = st, Vs = st + 8192;

        float s[2][8][4];
#pragma unroll
        for (int mt = 0; mt < 2; mt++)
#pragma unroll
            for (int nt = 0; nt < 8; nt++)
#pragma unroll
                for (int r = 0; r < 4; r++) s[mt][nt][r] = 0.f;

#pragma unroll
        for (int ks = 0; ks < 4; ks++) {
            uint32_t cv = ((uint32_t)(ks * 32) + c_lane) ^ xorterm;
#pragma unroll
            for (int bn = 0; bn < 4; bn++) {
                uint32_t kh[4];
                LDSM4(kh[0], kh[1], kh[2], kh[3],
                      Ks + (uint32_t)((bn * 16 + (lane & 15)) * 128) + cv);
#pragma unroll
                for (int mt = 0; mt < 2; mt++)
#pragma unroll
                    for (int sub = 0; sub < 2; sub++)
                        MMAH(s[mt][bn * 2 + sub], qf[mt][ks], kh[sub], kh[sub + 2]);
            }
        }

        if (j >= 2 * iq) {
            int cbase = j * 64 + (lane & 3) * 2;
#pragma unroll
            for (int mt = 0; mt < 2; mt++)
#pragma unroll
                for (int nt = 0; nt < 8; nt++) {
                    int c0 = cbase + nt * 8, c1 = c0 + 1;
                    if (c0 > r0g[mt])     s[mt][nt][0] = -1e30f;
                    if (c1 > r0g[mt])     s[mt][nt][1] = -1e30f;
                    if (c0 > r0g[mt] + 8) s[mt][nt][2] = -1e30f;
                    if (c1 > r0g[mt] + 8) s[mt][nt][3] = -1e30f;
                }
        }

#pragma unroll
        for (int mt = 0; mt < 2; mt++) {
            float mx0 = -1e30f, mx1 = -1e30f;
#pragma unroll
            for (int nt = 0; nt < 8; nt++) {
                mx0 = fmaxf(mx0, fmaxf(s[mt][nt][0], s[mt][nt][1]));
                mx1 = fmaxf(mx1, fmaxf(s[mt][nt][2], s[mt][nt][3]));
            }
            mx0 = fmaxf(mx0, __shfl_xor_sync(0xFFFFFFFFu, mx0, 1));
            mx0 = fmaxf(mx0, __shfl_xor_sync(0xFFFFFFFFu, mx0, 2));
            mx1 = fmaxf(mx1, __shfl_xor_sync(0xFFFFFFFFu, mx1, 1));
            mx1 = fmaxf(mx1, __shfl_xor_sync(0xFFFFFFFFu, mx1, 2));
            float mn0 = fmaxf(mst[mt][0], mx0), mn1 = fmaxf(mst[mt][1], mx1);
            float al0 = ex2(mst[mt][0] - mn0), al1 = ex2(mst[mt][1] - mn1);
            mst[mt][0] = mn0; mst[mt][1] = mn1;

            float sum0 = 0.f, sum1 = 0.f;
#pragma unroll
            for (int nt = 0; nt < 8; nt++) {
                s[mt][nt][0] = ex2(s[mt][nt][0] - mn0);
                s[mt][nt][1] = ex2(s[mt][nt][1] - mn0);
                s[mt][nt][2] = ex2(s[mt][nt][2] - mn1);
                s[mt][nt][3] = ex2(s[mt][nt][3] - mn1);
                sum0 += s[mt][nt][0] + s[mt][nt][1];
                sum1 += s[mt][nt][2] + s[mt][nt][3];
            }
            sum0 += __shfl_xor_sync(0xFFFFFFFFu, sum0, 1);
            sum0 += __shfl_xor_sync(0xFFFFFFFFu, sum0, 2);
            sum1 += __shfl_xor_sync(0xFFFFFFFFu, sum1, 1);
            sum1 += __shfl_xor_sync(0xFFFFFFFFu, sum1, 2);
            lst[mt][0] = lst[mt][0] * al0 + sum0;
            lst[mt][1] = lst[mt][1] * al1 + sum1;

#pragma unroll
            for (int nt = 0; nt < 8; nt++) {
                o[mt][nt][0] *= al0; o[mt][nt][1] *= al0;
                o[mt][nt][2] *= al1; o[mt][nt][3] *= al1;
            }
        }

#pragma unroll
        for (int t = 0; t < 4; t++) {
            uint32_t ap[2][4];
#pragma unroll
            for (int mt = 0; mt < 2; mt++)
#pragma unroll
                for (int u = 0; u < 4; u++) {
                    int nt = t * 2 + (u >> 1);
                    int base = (u & 1) * 2;
                    ap[mt][u] = h2u(__floats2half2_rn(s[mt][nt][base],
                                                      s[mt][nt][base + 1]));
                }
            uint32_t rowoff = (uint32_t)((t * 16 + (lane & 15)) * 128);
#pragma unroll
            for (int g = 0; g < 4; g++) {
                uint32_t cvv = ((uint32_t)(g * 32) + c_lane) ^ xorterm;
                uint32_t vh[4];
                LDSM4T(vh[0], vh[1], vh[2], vh[3], Vs + rowoff + cvv);
#pragma unroll
                for (int mt = 0; mt < 2; mt++) {
                    MMAH(o[mt][g * 2],     ap[mt], vh[0], vh[1]);
                    MMAH(o[mt][g * 2 + 1], ap[mt], vh[2], vh[3]);
                }
            }
        }
    }

    // ---- write unnormalized partials (fp16) ----
    __half* Op = g_opart + (size_t)sp * SEQ * DMODEL;
    int colb = h * 64 + (lane & 3) * 2;
#pragma unroll
    for (int mt = 0; mt < 2; mt++) {
#pragma unroll
        for (int nt = 0; nt < 8; nt++) {
            int col = colb + nt * 8;
            size_t i0 = (size_t)r0g[mt] * DMODEL + col;
            size_t i1 = (size_t)(r0g[mt] + 8) * DMODEL + col;
            *(__half2*)&Op[i0] = __floats2half2_rn(o[mt][nt][0], o[mt][nt][1]);
            *(__half2*)&Op[i1] = __floats2half2_rn(o[mt][nt][2], o[mt][nt][3]);
        }
        if ((lane & 3) == 0) {
            size_t base = (size_t)sp * NH * SEQ + (size_t)h * SEQ;
            g_pm[base + r0g[mt]]     = mst[mt][0];
            g_pm[base + r0g[mt] + 8] = mst[mt][1];
            g_pl[base + r0g[mt]]     = lst[mt][0];
            g_pl[base + r0g[mt] + 8] = lst[mt][1];
        }
    }
}

// ---------------------------------------------------------------------------
// Combine split-KV partials (exp2 domain) -> single fp16 proj input (g_x16).
// ---------------------------------------------------------------------------
__global__ void combine_kernel()
{
    int idx = blockIdx.x * 256 + threadIdx.x;   // group of 4 halves over SEQ*DMODEL/4
    int row = idx >> 8;                          // 256 groups per row
    int h   = (idx & 255) >> 4;                  // 16 groups per head
    size_t mlb = (size_t)h * SEQ + row;
    float m0 = g_pm[mlb], m1 = g_pm[(size_t)NH * SEQ + mlb];
    float l0 = g_pl[mlb], l1 = g_pl[(size_t)NH * SEQ + mlb];
    float ms = fmaxf(m0, m1);
    float w0 = ex2(m0 - ms), w1 = ex2(m1 - ms);
    float inv = 1.0f / (w0 * l0 + w1 * l1);
    w0 *= inv; w1 *= inv;
    const __half2* A0 = (const __half2*)g_opart;
    const __half2* B0 = (const __half2*)(g_opart + (size_t)SEQ * DMODEL);
    float2 a0 = __half22float2(A0[2*idx]);
    float2 a1 = __half22float2(A0[2*idx+1]);
    float2 b0 = __half22float2(B0[2*idx]);
    float2 b1 = __half22float2(B0[2*idx+1]);
    __half2* H = (__half2*)g_x16;
    H[2*idx]   = __floats2half2_rn(a0.x * w0 + b0.x * w1, a0.y * w0 + b0.y * w1);
    H[2*idx+1] = __floats2half2_rn(a1.x * w0 + b1.x * w1, a1.y * w0 + b1.y * w1);
}

// ---------------------------------------------------------------------------
extern "C" void kernel_launch(void* const* d_in, const int* in_sizes, int n_in,
                              void* d_out, int out_size)
{
    const float* X     = (const float*)d_in[0];
    const float* Wqkv  = (const float*)d_in[1];
    const float* bqkv  = (const float*)d_in[2];
    const float* Wproj = (const float*)d_in[3];
    const float* bproj = (const float*)d_in[4];
    float* out = (float*)d_out;

    const int GEMM_SMEM = 3 * 2 * 16384;             // 98304 B, 2 CTAs/SM
    const int ATTN_SMEM = 16384 + 3 * 16384;         // 65536 B, 2 CTAs/SM
    cudaFuncSetAttribute(gemm16<1>, cudaFuncAttributeMaxDynamicSharedMemorySize, GEMM_SMEM);
    cudaFuncSetAttribute(gemm16<0>, cudaFuncAttributeMaxDynamicSharedMemorySize, GEMM_SMEM);
    cudaFuncSetAttribute(attn_mma_kernel, cudaFuncAttributeMaxDynamicSharedMemorySize, ATTN_SMEM);

    // 1) fused operand conversion (one kernel: X, Wqkv, Wproj)
    conv_all_kernel<<<8192, 256>>>(X, Wqkv, Wproj);

    // 2) QKV GEMM (single fp16, 64x64 warp tiles) -> fp16 q(scaled)/k/v
    gemm16<1><<<dim3(24, 32), 128, GEMM_SMEM>>>(bqkv, nullptr, 3 * DMODEL);

    // 3) split-KV attention (fp16 partials) + combine -> g_x16
    attn_mma_kernel<<<dim3(KSPLIT, 32, NH), 128, ATTN_SMEM>>>();
    combine_kernel<<<SEQ * DMODEL / 4 / 256, 256>>>();

    // 4) proj GEMM (single fp16) -> out
    gemm16<0><<<dim3(8, 32), 128, GEMM_SMEM>>>(bproj, out, DMODEL);
}